// round 4
// baseline (speedup 1.0000x reference)
#include <cuda_runtime.h>
#include <math.h>

#define SQ 4096
#define HIDN 2048
#define NHEAD 16
#define DH 128
#define CB 1024
#define NEGV -1e30f
#define NEGH -5e29f
#define ATT_SCALE 0.08838834764831845f

// ------------- scratch (static __device__ globals; allocation-free) -------------
__device__ float g_q[(size_t)SQ * HIDN];        // q after norm+rope, [s][h*128+d]
__device__ float g_lk[(size_t)SQ * HIDN];
__device__ float g_lv[(size_t)SQ * HIDN];
__device__ float g_wlog[SQ];
__device__ float g_entries[(size_t)CB * HIDN];
__device__ float g_ck[CB * DH];
__device__ float g_cv[CB * DH];
__device__ float g_merged[(size_t)SQ * HIDN];   // sparse, then (sparse+local)*0.5
__device__ float g_sc[(size_t)NHEAD * SQ * CB]; // 268 MB compressed scores
__device__ float g_scl[(size_t)NHEAD * 32 * 128 * 256]; // 67 MB local scores/probs

__device__ __forceinline__ float warp_sum(float v) {
#pragma unroll
    for (int o = 16; o; o >>= 1) v += __shfl_xor_sync(0xffffffffu, v, o);
    return v;
}
__device__ __forceinline__ float warp_max(float v) {
#pragma unroll
    for (int o = 16; o; o >>= 1) v = fmaxf(v, __shfl_xor_sync(0xffffffffu, v, o));
    return v;
}

// ------------------------------------------------------------------
// Generic NN SGEMM with bias, K = HIDN = 2048 always.
// KH=true: Kahan-compensated accumulation (near-exact dot products) for
// GEMMs that feed the discrete top-k selection (Wq, Wk).
// ------------------------------------------------------------------
template <bool KH>
__global__ __launch_bounds__(256)
void sgemm_bias(int mode, const float* __restrict__ X,
                const float* __restrict__ W, const float* __restrict__ bias,
                float* __restrict__ outp)
{
    const float* A;
    float* C;
    int lda, ldb, ldc;
    if (mode <= 2) { A = X; C = (mode == 0) ? g_q : (mode == 1 ? g_lk : g_lv);
                     lda = HIDN; ldb = HIDN; ldc = HIDN; }
    else if (mode <= 4) { A = g_entries; C = (mode == 3) ? g_ck : g_cv;
                     lda = HIDN; ldb = DH; ldc = DH; }
    else { A = g_merged; C = outp; lda = HIDN; ldb = HIDN; ldc = HIDN; }

    __shared__ float As[16][128];
    __shared__ float Bs[16][128];
    const int tid = threadIdx.x;
    const int row0 = blockIdx.y << 7;
    const int col0 = blockIdx.x << 7;
    const int ty = tid >> 4, tx = tid & 15;

    float acc[8][8], cmp[8][8];
#pragma unroll
    for (int i = 0; i < 8; i++)
#pragma unroll
        for (int j = 0; j < 8; j++) { acc[i][j] = 0.f; cmp[i][j] = 0.f; }

    for (int k0 = 0; k0 < HIDN; k0 += 16) {
#pragma unroll
        for (int t = 0; t < 2; t++) {
            int jj = tid + (t << 8);
            int m = jj >> 2, k4 = (jj & 3) << 2;
            float4 v = *(const float4*)(A + (size_t)(row0 + m) * lda + k0 + k4);
            As[k4 + 0][m] = v.x; As[k4 + 1][m] = v.y;
            As[k4 + 2][m] = v.z; As[k4 + 3][m] = v.w;
        }
#pragma unroll
        for (int t = 0; t < 2; t++) {
            int jj = tid + (t << 8);
            int kk = jj >> 5, n4 = (jj & 31) << 2;
            *(float4*)&Bs[kk][n4] = *(const float4*)(W + (size_t)(k0 + kk) * ldb + col0 + n4);
        }
        __syncthreads();
#pragma unroll
        for (int kk = 0; kk < 16; kk++) {
            float ra[8], rb[8];
            *(float4*)&ra[0] = *(const float4*)&As[kk][ty << 3];
            *(float4*)&ra[4] = *(const float4*)&As[kk][(ty << 3) + 4];
            *(float4*)&rb[0] = *(const float4*)&Bs[kk][tx << 3];
            *(float4*)&rb[4] = *(const float4*)&Bs[kk][(tx << 3) + 4];
#pragma unroll
            for (int i = 0; i < 8; i++)
#pragma unroll
                for (int j = 0; j < 8; j++) {
                    if (KH) {
                        float y = __fmaf_rn(ra[i], rb[j], -cmp[i][j]);
                        float t2 = __fadd_rn(acc[i][j], y);
                        cmp[i][j] = __fsub_rn(__fsub_rn(t2, acc[i][j]), y);
                        acc[i][j] = t2;
                    } else {
                        acc[i][j] += ra[i] * rb[j];
                    }
                }
        }
        __syncthreads();
    }
#pragma unroll
    for (int i = 0; i < 8; i++) {
        size_t r = row0 + (ty << 3) + i;
#pragma unroll
        for (int j = 0; j < 8; j++) {
            int c = col0 + (tx << 3) + j;
            C[r * ldc + c] = __fadd_rn(acc[i][j], bias[c]);
        }
    }
}

// ------------------------------------------------------------------
// NT GEMM (C = scale * A @ B^T), K = 128.
// mode 0 (KH=true): sc[h][s][c]  grid (8, 32, 16), causal tile skip
// mode 1 (KH=false): local scores grid (2, 1, 512), clamped B rows
// ------------------------------------------------------------------
template <bool KH>
__global__ __launch_bounds__(256)
void gemm_nt_scores(int mode)
{
    const float* A; const float* B; float* C;
    int lda, ldb, ldc, b_base, row0, col0;
    if (mode == 0) {
        int h = blockIdx.z;
        row0 = blockIdx.y << 7; col0 = blockIdx.x << 7;
        if (col0 >= (row0 >> 2) + 32) return;        // fully non-causal tile
        A = g_q + h * DH; lda = HIDN;
        B = g_ck; ldb = DH; b_base = 0;
        C = g_sc + (size_t)h * SQ * CB; ldc = CB;
    } else {
        int h = blockIdx.z >> 5, ch = blockIdx.z & 31;
        row0 = 0; col0 = blockIdx.x << 7;
        A = g_q + (size_t)(ch << 7) * HIDN + h * DH; lda = HIDN;
        B = g_lk + h * DH; ldb = HIDN; b_base = (ch << 7) - 128;
        C = g_scl + (size_t)blockIdx.z * 128 * 256; ldc = 256;
    }
    __shared__ float As[16][128];
    __shared__ float Bs[16][128];
    const int tid = threadIdx.x;
    const int ty = tid >> 4, tx = tid & 15;

    float acc[8][8], cmp[8][8];
#pragma unroll
    for (int i = 0; i < 8; i++)
#pragma unroll
        for (int j = 0; j < 8; j++) { acc[i][j] = 0.f; cmp[i][j] = 0.f; }

    for (int k0 = 0; k0 < DH; k0 += 16) {
#pragma unroll
        for (int t = 0; t < 2; t++) {
            int jj = tid + (t << 8);
            int m = jj >> 2, k4 = (jj & 3) << 2;
            float4 v = *(const float4*)(A + (size_t)(row0 + m) * lda + k0 + k4);
            As[k4 + 0][m] = v.x; As[k4 + 1][m] = v.y;
            As[k4 + 2][m] = v.z; As[k4 + 3][m] = v.w;
        }
#pragma unroll
        for (int t = 0; t < 2; t++) {
            int jj = tid + (t << 8);
            int n = jj >> 2, k4 = (jj & 3) << 2;
            int br = b_base + col0 + n;
            if (br < 0) br = 0;                       // masked later; keep reads in-bounds
            float4 v = *(const float4*)(B + (size_t)br * ldb + k0 + k4);
            Bs[k4 + 0][n] = v.x; Bs[k4 + 1][n] = v.y;
            Bs[k4 + 2][n] = v.z; Bs[k4 + 3][n] = v.w;
        }
        __syncthreads();
#pragma unroll
        for (int kk = 0; kk < 16; kk++) {
            float ra[8], rb[8];
            *(float4*)&ra[0] = *(const float4*)&As[kk][ty << 3];
            *(float4*)&ra[4] = *(const float4*)&As[kk][(ty << 3) + 4];
            *(float4*)&rb[0] = *(const float4*)&Bs[kk][tx << 3];
            *(float4*)&rb[4] = *(const float4*)&Bs[kk][(tx << 3) + 4];
#pragma unroll
            for (int i = 0; i < 8; i++)
#pragma unroll
                for (int j = 0; j < 8; j++) {
                    if (KH) {
                        float y = __fmaf_rn(ra[i], rb[j], -cmp[i][j]);
                        float t2 = __fadd_rn(acc[i][j], y);
                        cmp[i][j] = __fsub_rn(__fsub_rn(t2, acc[i][j]), y);
                        acc[i][j] = t2;
                    } else {
                        acc[i][j] += ra[i] * rb[j];
                    }
                }
        }
        __syncthreads();
    }
#pragma unroll
    for (int i = 0; i < 8; i++) {
        size_t r = row0 + (ty << 3) + i;
#pragma unroll
        for (int j = 0; j < 8; j++)
            C[r * ldc + col0 + (tx << 3) + j] = __fmul_rn(acc[i][j], ATT_SCALE);
    }
}

// local PV: ctx_local = P[128x256] @ Vwin[256x128]; merged = (sparse+local)*0.5
__global__ __launch_bounds__(256)
void local_pv()
{
    int h = blockIdx.z >> 5, ch = blockIdx.z & 31;
    const float* A = g_scl + (size_t)blockIdx.z * 128 * 256; // lda=256
    const float* B = g_lv + h * DH;                          // ldb=HIDN, clamped rows
    int b_base = (ch << 7) - 128;

    __shared__ float As[16][128];
    __shared__ float Bs[16][128];
    const int tid = threadIdx.x;
    const int ty = tid >> 4, tx = tid & 15;

    float acc[8][8];
#pragma unroll
    for (int i = 0; i < 8; i++)
#pragma unroll
        for (int j = 0; j < 8; j++) acc[i][j] = 0.f;

    for (int k0 = 0; k0 < 256; k0 += 16) {
#pragma unroll
        for (int t = 0; t < 2; t++) {
            int jj = tid + (t << 8);
            int m = jj >> 2, k4 = (jj & 3) << 2;
            float4 v = *(const float4*)(A + (size_t)m * 256 + k0 + k4);
            As[k4 + 0][m] = v.x; As[k4 + 1][m] = v.y;
            As[k4 + 2][m] = v.z; As[k4 + 3][m] = v.w;
        }
#pragma unroll
        for (int t = 0; t < 2; t++) {
            int jj = tid + (t << 8);
            int kk = jj >> 5, n4 = (jj & 31) << 2;
            int br = b_base + k0 + kk;
            if (br < 0) br = 0;                       // p==0 there, so harmless
            *(float4*)&Bs[kk][n4] = *(const float4*)(B + (size_t)br * HIDN + n4);
        }
        __syncthreads();
#pragma unroll
        for (int kk = 0; kk < 16; kk++) {
            float ra[8], rb[8];
            *(float4*)&ra[0] = *(const float4*)&As[kk][ty << 3];
            *(float4*)&ra[4] = *(const float4*)&As[kk][(ty << 3) + 4];
            *(float4*)&rb[0] = *(const float4*)&Bs[kk][tx << 3];
            *(float4*)&rb[4] = *(const float4*)&Bs[kk][(tx << 3) + 4];
#pragma unroll
            for (int i = 0; i < 8; i++)
#pragma unroll
                for (int j = 0; j < 8; j++) acc[i][j] += ra[i] * rb[j];
        }
        __syncthreads();
    }
#pragma unroll
    for (int i = 0; i < 8; i++) {
        float* dst = g_merged + (size_t)((ch << 7) + (ty << 3) + i) * HIDN + h * DH + (tx << 3);
#pragma unroll
        for (int j = 0; j < 8; j++)
            dst[j] = __fmul_rn(__fadd_rn(dst[j], acc[i][j]), 0.5f);
    }
}

// ------------------------------------------------------------------
// rmsnorm + rope, one warp per (row, head) 128-slice, in place.
// ------------------------------------------------------------------
__global__ void norm_rope(int mode, const float* __restrict__ w)
{
    int gw = (blockIdx.x * blockDim.x + threadIdx.x) >> 5;
    int lane = threadIdx.x & 31;
    float* buf; int rows, heads, rstride, pmul, padd;
    if (mode == 0)      { buf = g_q;  rows = SQ; heads = NHEAD; rstride = HIDN; pmul = 1; padd = 0; }
    else if (mode == 1) { buf = g_lk; rows = SQ; heads = NHEAD; rstride = HIDN; pmul = 1; padd = 0; }
    else                { buf = g_ck; rows = CB; heads = 1;     rstride = DH;   pmul = 4; padd = 3; }
    if (gw >= rows * heads) return;
    int row = gw / heads, h = gw - row * heads;
    float* p = buf + (size_t)row * rstride + h * DH;
    float x0 = p[lane], x1 = p[lane + 32], x2 = p[lane + 64], x3 = p[lane + 96];
    float ss = warp_sum(x0 * x0 + x1 * x1 + x2 * x2 + x3 * x3);
    float mean = __fadd_rn(__fmul_rn(ss, 0.0078125f), 1e-6f);
    float rs = __fdiv_rn(1.0f, __fsqrt_rn(mean));          // XLA rsqrt = 1/sqrt
    x0 = __fmul_rn(__fmul_rn(x0, rs), w[lane]);
    x1 = __fmul_rn(__fmul_rn(x1, rs), w[lane + 32]);
    x2 = __fmul_rn(__fmul_rn(x2, rs), w[lane + 64]);
    x3 = __fmul_rn(__fmul_rn(x3, rs), w[lane + 96]);
    // inv = 1.0f / powf(10000, lane/32), trig via double (CR-grade, fast-math-proof)
    float pf = (float)pow(10000.0, (double)lane * (1.0 / 32.0));
    float invf = __fdiv_rn(1.0f, pf);
    float ang = __fmul_rn((float)(row * pmul + padd), invf);
    float c = (float)cos((double)ang);
    float s = (float)sin((double)ang);
    float n0 = __fsub_rn(__fmul_rn(x0, c), __fmul_rn(x1, s));
    float n1 = __fadd_rn(__fmul_rn(x0, s), __fmul_rn(x1, c));
    p[lane] = n0; p[lane + 32] = n1; p[lane + 64] = x2; p[lane + 96] = x3;
}

__global__ void cmp_logits(const float* __restrict__ hidden, const float* __restrict__ Wc,
                           const float* __restrict__ bc)
{
    int gw = (blockIdx.x * blockDim.x + threadIdx.x) >> 5;
    int lane = threadIdx.x & 31;
    if (gw >= SQ) return;
    const float* hr = hidden + (size_t)gw * HIDN;
    float acc = 0.f, cmp = 0.f;
    for (int k = lane; k < HIDN; k += 32) {
        float y = __fmaf_rn(hr[k], Wc[k], -cmp);
        float t = __fadd_rn(acc, y);
        cmp = __fsub_rn(__fsub_rn(t, acc), y);
        acc = t;
    }
    acc = warp_sum(acc);
    if (lane == 0) g_wlog[gw] = __fadd_rn(acc, bc[0]);
}

__global__ void entries_kernel(const float* __restrict__ hidden)
{
    int c = blockIdx.x;
    float w0 = g_wlog[c * 4 + 0], w1 = g_wlog[c * 4 + 1];
    float w2 = g_wlog[c * 4 + 2], w3 = g_wlog[c * 4 + 3];
    float m = fmaxf(fmaxf(w0, w1), fmaxf(w2, w3));
    float e0 = (float)exp((double)__fsub_rn(w0, m));
    float e1 = (float)exp((double)__fsub_rn(w1, m));
    float e2 = (float)exp((double)__fsub_rn(w2, m));
    float e3 = (float)exp((double)__fsub_rn(w3, m));
    float sum = __fadd_rn(__fadd_rn(e0, e1), __fadd_rn(e2, e3));
    e0 = __fdiv_rn(e0, sum); e1 = __fdiv_rn(e1, sum);
    e2 = __fdiv_rn(e2, sum); e3 = __fdiv_rn(e3, sum);
    const float* h0 = hidden + (size_t)c * 4 * HIDN;
    float* dst = g_entries + (size_t)c * HIDN;
    for (int j = threadIdx.x; j < HIDN; j += blockDim.x)
        dst[j] = e0 * h0[j] + e1 * h0[HIDN + j] + e2 * h0[2 * HIDN + j] + e3 * h0[3 * HIDN + j];
}

// ------------------------------------------------------------------
// top-8 over causal prefix + softmax + gather cv; writes 1.0*ctx_sparse
// (local_pv later does (sparse+local)*0.5). One warp per (h, s).
// ------------------------------------------------------------------
__global__ void topk_sparse()
{
    int gw = (blockIdx.x * blockDim.x + threadIdx.x) >> 5;
    int lane = threadIdx.x & 31;
    if (gw >= NHEAD * SQ) return;
    int h = gw >> 12;
    int s = gw & (SQ - 1);
    int nc = (s + 1) >> 2;
    const float* row = g_sc + ((size_t)h * SQ + s) * CB;

    float bv[8]; int bi[8];
#pragma unroll
    for (int i = 0; i < 8; i++) { bv[i] = NEGV; bi[i] = -1; }
    for (int c = lane; c < nc; c += 32) {
        float v = row[c];
        if (v > bv[7]) {
            bv[7] = v; bi[7] = c;
#pragma unroll
            for (int j = 7; j > 0; j--) {
                if (bv[j] > bv[j - 1]) {
                    float tv = bv[j]; bv[j] = bv[j - 1]; bv[j - 1] = tv;
                    int txx = bi[j]; bi[j] = bi[j - 1]; bi[j - 1] = txx;
                }
            }
        }
    }
    // warp merge: 8 rounds of argmax (value desc, index asc tie-break)
    int ptr = 0;
    float tvv[8]; int tii[8];
#pragma unroll
    for (int t = 0; t < 8; t++) {
        float m = (ptr < 8) ? bv[ptr] : NEGV;
        int mi = (ptr < 8) ? bi[ptr] : 0x7fffffff;
#pragma unroll
        for (int o = 16; o; o >>= 1) {
            float om = __shfl_xor_sync(0xffffffffu, m, o);
            int oi = __shfl_xor_sync(0xffffffffu, mi, o);
            if (om > m || (om == m && oi < mi)) { m = om; mi = oi; }
        }
        tvv[t] = m; tii[t] = mi;
        if (ptr < 8 && bv[ptr] == m && bi[ptr] == mi) ptr++;
    }
    float m0 = tvv[0];
    float e[8]; float sum = 0.f;
#pragma unroll
    for (int t = 0; t < 8; t++) {
        e[t] = (tvv[t] > NEGH) ? (float)exp((double)__fsub_rn(tvv[t], m0)) : 0.f;
        sum += e[t];
    }
    float den = fmaxf(sum, 1e-9f);
    float c0 = 0.f, c1 = 0.f, c2 = 0.f, c3 = 0.f;
#pragma unroll
    for (int t = 0; t < 8; t++) {
        float wgt = __fdiv_rn(e[t], den);
        if (wgt > 0.f) {
            const float* vr = g_cv + (size_t)tii[t] * DH;
            c0 += wgt * vr[lane];      c1 += wgt * vr[lane + 32];
            c2 += wgt * vr[lane + 64]; c3 += wgt * vr[lane + 96];
        }
    }
    float* dst = g_merged + (size_t)s * HIDN + h * DH;
    dst[lane] = c0;      dst[lane + 32] = c1;
    dst[lane + 64] = c2; dst[lane + 96] = c3;
}

// masked softmax over 256 local keys; writes probabilities back (0 where masked)
__global__ void local_softmax()
{
    int gw = (blockIdx.x * blockDim.x + threadIdx.x) >> 5;
    int lane = threadIdx.x & 31;
    if (gw >= NHEAD * 32 * 128) return;
    int qi = gw & 127;
    int ch = (gw >> 7) & 31;
    float* rowp = g_scl + (size_t)gw * 256;
    int lo = (ch == 0) ? 128 : qi;   // chunk 0: only current-chunk keys (j>=128)
    int hi = qi + 128;
    float v[8];
    float m = NEGV;
#pragma unroll
    for (int t = 0; t < 8; t++) {
        int j = lane + (t << 5);
        bool ok = (j >= lo) && (j <= hi);
        v[t] = ok ? rowp[j] : NEGV;
        m = fmaxf(m, v[t]);
    }
    m = warp_max(m);
    float e[8]; float sum = 0.f;
#pragma unroll
    for (int t = 0; t < 8; t++) {
        int j = lane + (t << 5);
        bool ok = (j >= lo) && (j <= hi);
        e[t] = ok ? (float)exp((double)__fsub_rn(v[t], m)) : 0.f;
        sum += e[t];
    }
    sum = warp_sum(sum);
#pragma unroll
    for (int t = 0; t < 8; t++) rowp[lane + (t << 5)] = __fdiv_rn(e[t], sum);
}

// ------------------------------------------------------------------
extern "C" void kernel_launch(void* const* d_in, const int* in_sizes, int n_in,
                              void* d_out, int out_size)
{
    const float* hidden = (const float*)d_in[0];
    const float* Wq   = (const float*)d_in[1];
    const float* bq   = (const float*)d_in[2];
    const float* Wcmp = (const float*)d_in[3];
    const float* bcmp = (const float*)d_in[4];
    const float* Wk   = (const float*)d_in[5];
    const float* bk   = (const float*)d_in[6];
    const float* Wv   = (const float*)d_in[7];
    const float* bvv  = (const float*)d_in[8];
    const float* Wlk  = (const float*)d_in[9];
    const float* blkb = (const float*)d_in[10];
    const float* Wlv  = (const float*)d_in[11];
    const float* blvb = (const float*)d_in[12];
    const float* qnw  = (const float*)d_in[13];
    const float* knw  = (const float*)d_in[14];
    const float* Wo   = (const float*)d_in[15];
    const float* bo   = (const float*)d_in[16];
    float* out = (float*)d_out;

    dim3 thr(256);
    dim3 gBig(HIDN / 128, SQ / 128);   // 16 x 32

    sgemm_bias<true ><<<gBig, thr>>>(0, hidden, Wq,  bq,   nullptr);  // feeds top-k
    sgemm_bias<false><<<gBig, thr>>>(1, hidden, Wlk, blkb, nullptr);
    sgemm_bias<false><<<gBig, thr>>>(2, hidden, Wlv, blvb, nullptr);

    cmp_logits<<<SQ / 8, 256>>>(hidden, Wcmp, bcmp);
    entries_kernel<<<CB, 256>>>(hidden);

    sgemm_bias<true ><<<dim3(1, CB / 128), thr>>>(3, nullptr, Wk, bk,  nullptr); // feeds top-k
    sgemm_bias<false><<<dim3(1, CB / 128), thr>>>(4, nullptr, Wv, bvv, nullptr);

    norm_rope<<<(SQ * NHEAD) / 8, 256>>>(0, qnw);
    norm_rope<<<(SQ * NHEAD) / 8, 256>>>(1, knw);
    norm_rope<<<CB / 8, 256>>>(2, knw);

    gemm_nt_scores<true ><<<dim3(CB / 128, SQ / 128, NHEAD), thr>>>(0); // feeds top-k
    topk_sparse<<<(NHEAD * SQ) / 8, 256>>>();

    gemm_nt_scores<false><<<dim3(2, 1, NHEAD * 32), thr>>>(1);
    local_softmax<<<(NHEAD * 32 * 128) / 8, 256>>>();
    local_pv<<<dim3(1, 1, NHEAD * 32), thr>>>();

    sgemm_bias<false><<<gBig, thr>>>(5, nullptr, Wo, bo, out);
}

// round 5
// speedup vs baseline: 1.3143x; 1.3143x over previous
#include <cuda_runtime.h>
#include <math.h>

#define SQ 4096
#define HIDN 2048
#define NHEAD 16
#define DH 128
#define CB 1024
#define NEGV -1e30f
#define NEGH -5e29f
#define ATT_SCALE 0.08838834764831845f

// ------------- scratch (static __device__ globals; allocation-free) -------------
__device__ float g_q[(size_t)SQ * HIDN];        // q after norm+rope, [s][h*128+d]
__device__ float g_lk[(size_t)SQ * HIDN];
__device__ float g_lv[(size_t)SQ * HIDN];
__device__ float g_wlog[SQ];
__device__ float g_entries[(size_t)CB * HIDN];
__device__ float g_ck[CB * DH];
__device__ float g_cv[CB * DH];
__device__ float g_merged[(size_t)SQ * HIDN];   // sparse, then (sparse+local)*0.5
__device__ float g_sc[(size_t)NHEAD * SQ * CB]; // 268 MB compressed scores
__device__ float g_scl[(size_t)NHEAD * 32 * 128 * 256]; // 67 MB local scores/probs

__device__ __forceinline__ float warp_sum(float v) {
#pragma unroll
    for (int o = 16; o; o >>= 1) v += __shfl_xor_sync(0xffffffffu, v, o);
    return v;
}
__device__ __forceinline__ float warp_max(float v) {
#pragma unroll
    for (int o = 16; o; o >>= 1) v = fmaxf(v, __shfl_xor_sync(0xffffffffu, v, o));
    return v;
}

// ------------------------------------------------------------------
// Generic NN SGEMM with bias, K = HIDN = 2048 always.
// KH=true: chunked-Kahan accumulation — plain FMA within each 16-wide k0
// tile (tmp), exact Kahan fold of the tile sum into acc/cmp. Noise
// ~2^-24*sqrt(8) rel, 1.25 fma-pipe instr per MAC.
// ------------------------------------------------------------------
template <bool KH>
__global__ __launch_bounds__(256)
void sgemm_bias(int mode, const float* __restrict__ X,
                const float* __restrict__ W, const float* __restrict__ bias,
                float* __restrict__ outp)
{
    const float* A;
    float* C;
    int lda, ldb, ldc;
    if (mode <= 2) { A = X; C = (mode == 0) ? g_q : (mode == 1 ? g_lk : g_lv);
                     lda = HIDN; ldb = HIDN; ldc = HIDN; }
    else if (mode <= 4) { A = g_entries; C = (mode == 3) ? g_ck : g_cv;
                     lda = HIDN; ldb = DH; ldc = DH; }
    else { A = g_merged; C = outp; lda = HIDN; ldb = HIDN; ldc = HIDN; }

    __shared__ float As[16][128];
    __shared__ float Bs[16][128];
    const int tid = threadIdx.x;
    const int row0 = blockIdx.y << 7;
    const int col0 = blockIdx.x << 7;
    const int ty = tid >> 4, tx = tid & 15;

    float acc[8][8], cmp[8][8];
#pragma unroll
    for (int i = 0; i < 8; i++)
#pragma unroll
        for (int j = 0; j < 8; j++) { acc[i][j] = 0.f; cmp[i][j] = 0.f; }

    for (int k0 = 0; k0 < HIDN; k0 += 16) {
#pragma unroll
        for (int t = 0; t < 2; t++) {
            int jj = tid + (t << 8);
            int m = jj >> 2, k4 = (jj & 3) << 2;
            float4 v = *(const float4*)(A + (size_t)(row0 + m) * lda + k0 + k4);
            As[k4 + 0][m] = v.x; As[k4 + 1][m] = v.y;
            As[k4 + 2][m] = v.z; As[k4 + 3][m] = v.w;
        }
#pragma unroll
        for (int t = 0; t < 2; t++) {
            int jj = tid + (t << 8);
            int kk = jj >> 5, n4 = (jj & 31) << 2;
            *(float4*)&Bs[kk][n4] = *(const float4*)(W + (size_t)(k0 + kk) * ldb + col0 + n4);
        }
        __syncthreads();
        if (KH) {
            float tmp[8][8];
#pragma unroll
            for (int i = 0; i < 8; i++)
#pragma unroll
                for (int j = 0; j < 8; j++) tmp[i][j] = 0.f;
#pragma unroll
            for (int kk = 0; kk < 16; kk++) {
                float ra[8], rb[8];
                *(float4*)&ra[0] = *(const float4*)&As[kk][ty << 3];
                *(float4*)&ra[4] = *(const float4*)&As[kk][(ty << 3) + 4];
                *(float4*)&rb[0] = *(const float4*)&Bs[kk][tx << 3];
                *(float4*)&rb[4] = *(const float4*)&Bs[kk][(tx << 3) + 4];
#pragma unroll
                for (int i = 0; i < 8; i++)
#pragma unroll
                    for (int j = 0; j < 8; j++)
                        tmp[i][j] = __fmaf_rn(ra[i], rb[j], tmp[i][j]);
            }
            // exact Kahan fold of the tile partial into acc
#pragma unroll
            for (int i = 0; i < 8; i++)
#pragma unroll
                for (int j = 0; j < 8; j++) {
                    float y = __fsub_rn(tmp[i][j], cmp[i][j]);
                    float t2 = __fadd_rn(acc[i][j], y);
                    cmp[i][j] = __fsub_rn(__fsub_rn(t2, acc[i][j]), y);
                    acc[i][j] = t2;
                }
        } else {
#pragma unroll
            for (int kk = 0; kk < 16; kk++) {
                float ra[8], rb[8];
                *(float4*)&ra[0] = *(const float4*)&As[kk][ty << 3];
                *(float4*)&ra[4] = *(const float4*)&As[kk][(ty << 3) + 4];
                *(float4*)&rb[0] = *(const float4*)&Bs[kk][tx << 3];
                *(float4*)&rb[4] = *(const float4*)&Bs[kk][(tx << 3) + 4];
#pragma unroll
                for (int i = 0; i < 8; i++)
#pragma unroll
                    for (int j = 0; j < 8; j++) acc[i][j] += ra[i] * rb[j];
            }
        }
        __syncthreads();
    }
#pragma unroll
    for (int i = 0; i < 8; i++) {
        size_t r = row0 + (ty << 3) + i;
#pragma unroll
        for (int j = 0; j < 8; j++) {
            int c = col0 + (tx << 3) + j;
            C[r * ldc + c] = __fadd_rn(acc[i][j], bias[c]);
        }
    }
}

// ------------------------------------------------------------------
// NT GEMM (C = scale * A @ B^T), K = 128.
// mode 0 (KH=true): sc[h][s][c]  grid (8, 32, 16), causal tile skip
// mode 1 (KH=false): local scores grid (2, 1, 512), clamped B rows
// ------------------------------------------------------------------
template <bool KH>
__global__ __launch_bounds__(256)
void gemm_nt_scores(int mode)
{
    const float* A; const float* B; float* C;
    int lda, ldb, ldc, b_base, row0, col0;
    if (mode == 0) {
        int h = blockIdx.z;
        row0 = blockIdx.y << 7; col0 = blockIdx.x << 7;
        if (col0 >= (row0 >> 2) + 32) return;        // fully non-causal tile
        A = g_q + h * DH; lda = HIDN;
        B = g_ck; ldb = DH; b_base = 0;
        C = g_sc + (size_t)h * SQ * CB; ldc = CB;
    } else {
        int h = blockIdx.z >> 5, ch = blockIdx.z & 31;
        row0 = 0; col0 = blockIdx.x << 7;
        A = g_q + (size_t)(ch << 7) * HIDN + h * DH; lda = HIDN;
        B = g_lk + h * DH; ldb = HIDN; b_base = (ch << 7) - 128;
        C = g_scl + (size_t)blockIdx.z * 128 * 256; ldc = 256;
    }
    __shared__ float As[16][128];
    __shared__ float Bs[16][128];
    const int tid = threadIdx.x;
    const int ty = tid >> 4, tx = tid & 15;

    float acc[8][8], cmp[8][8];
#pragma unroll
    for (int i = 0; i < 8; i++)
#pragma unroll
        for (int j = 0; j < 8; j++) { acc[i][j] = 0.f; cmp[i][j] = 0.f; }

    for (int k0 = 0; k0 < DH; k0 += 16) {
#pragma unroll
        for (int t = 0; t < 2; t++) {
            int jj = tid + (t << 8);
            int m = jj >> 2, k4 = (jj & 3) << 2;
            float4 v = *(const float4*)(A + (size_t)(row0 + m) * lda + k0 + k4);
            As[k4 + 0][m] = v.x; As[k4 + 1][m] = v.y;
            As[k4 + 2][m] = v.z; As[k4 + 3][m] = v.w;
        }
#pragma unroll
        for (int t = 0; t < 2; t++) {
            int jj = tid + (t << 8);
            int n = jj >> 2, k4 = (jj & 3) << 2;
            int br = b_base + col0 + n;
            if (br < 0) br = 0;                       // masked later; keep reads in-bounds
            float4 v = *(const float4*)(B + (size_t)br * ldb + k0 + k4);
            Bs[k4 + 0][n] = v.x; Bs[k4 + 1][n] = v.y;
            Bs[k4 + 2][n] = v.z; Bs[k4 + 3][n] = v.w;
        }
        __syncthreads();
        if (KH) {
            float tmp[8][8];
#pragma unroll
            for (int i = 0; i < 8; i++)
#pragma unroll
                for (int j = 0; j < 8; j++) tmp[i][j] = 0.f;
#pragma unroll
            for (int kk = 0; kk < 16; kk++) {
                float ra[8], rb[8];
                *(float4*)&ra[0] = *(const float4*)&As[kk][ty << 3];
                *(float4*)&ra[4] = *(const float4*)&As[kk][(ty << 3) + 4];
                *(float4*)&rb[0] = *(const float4*)&Bs[kk][tx << 3];
                *(float4*)&rb[4] = *(const float4*)&Bs[kk][(tx << 3) + 4];
#pragma unroll
                for (int i = 0; i < 8; i++)
#pragma unroll
                    for (int j = 0; j < 8; j++)
                        tmp[i][j] = __fmaf_rn(ra[i], rb[j], tmp[i][j]);
            }
#pragma unroll
            for (int i = 0; i < 8; i++)
#pragma unroll
                for (int j = 0; j < 8; j++) {
                    float y = __fsub_rn(tmp[i][j], cmp[i][j]);
                    float t2 = __fadd_rn(acc[i][j], y);
                    cmp[i][j] = __fsub_rn(__fsub_rn(t2, acc[i][j]), y);
                    acc[i][j] = t2;
                }
        } else {
#pragma unroll
            for (int kk = 0; kk < 16; kk++) {
                float ra[8], rb[8];
                *(float4*)&ra[0] = *(const float4*)&As[kk][ty << 3];
                *(float4*)&ra[4] = *(const float4*)&As[kk][(ty << 3) + 4];
                *(float4*)&rb[0] = *(const float4*)&Bs[kk][tx << 3];
                *(float4*)&rb[4] = *(const float4*)&Bs[kk][(tx << 3) + 4];
#pragma unroll
                for (int i = 0; i < 8; i++)
#pragma unroll
                    for (int j = 0; j < 8; j++) acc[i][j] += ra[i] * rb[j];
            }
        }
        __syncthreads();
    }
#pragma unroll
    for (int i = 0; i < 8; i++) {
        size_t r = row0 + (ty << 3) + i;
#pragma unroll
        for (int j = 0; j < 8; j++)
            C[r * ldc + col0 + (tx << 3) + j] = __fmul_rn(acc[i][j], ATT_SCALE);
    }
}

// local PV: ctx_local = P[128x256] @ Vwin[256x128]; merged = (sparse+local)*0.5
__global__ __launch_bounds__(256)
void local_pv()
{
    int h = blockIdx.z >> 5, ch = blockIdx.z & 31;
    const float* A = g_scl + (size_t)blockIdx.z * 128 * 256; // lda=256
    const float* B = g_lv + h * DH;                          // ldb=HIDN, clamped rows
    int b_base = (ch << 7) - 128;

    __shared__ float As[16][128];
    __shared__ float Bs[16][128];
    const int tid = threadIdx.x;
    const int ty = tid >> 4, tx = tid & 15;

    float acc[8][8];
#pragma unroll
    for (int i = 0; i < 8; i++)
#pragma unroll
        for (int j = 0; j < 8; j++) acc[i][j] = 0.f;

    for (int k0 = 0; k0 < 256; k0 += 16) {
#pragma unroll
        for (int t = 0; t < 2; t++) {
            int jj = tid + (t << 8);
            int m = jj >> 2, k4 = (jj & 3) << 2;
            float4 v = *(const float4*)(A + (size_t)m * 256 + k0 + k4);
            As[k4 + 0][m] = v.x; As[k4 + 1][m] = v.y;
            As[k4 + 2][m] = v.z; As[k4 + 3][m] = v.w;
        }
#pragma unroll
        for (int t = 0; t < 2; t++) {
            int jj = tid + (t << 8);
            int kk = jj >> 5, n4 = (jj & 31) << 2;
            int br = b_base + k0 + kk;
            if (br < 0) br = 0;                       // p==0 there, so harmless
            *(float4*)&Bs[kk][n4] = *(const float4*)(B + (size_t)br * HIDN + n4);
        }
        __syncthreads();
#pragma unroll
        for (int kk = 0; kk < 16; kk++) {
            float ra[8], rb[8];
            *(float4*)&ra[0] = *(const float4*)&As[kk][ty << 3];
            *(float4*)&ra[4] = *(const float4*)&As[kk][(ty << 3) + 4];
            *(float4*)&rb[0] = *(const float4*)&Bs[kk][tx << 3];
            *(float4*)&rb[4] = *(const float4*)&Bs[kk][(tx << 3) + 4];
#pragma unroll
            for (int i = 0; i < 8; i++)
#pragma unroll
                for (int j = 0; j < 8; j++) acc[i][j] += ra[i] * rb[j];
        }
        __syncthreads();
    }
#pragma unroll
    for (int i = 0; i < 8; i++) {
        float* dst = g_merged + (size_t)((ch << 7) + (ty << 3) + i) * HIDN + h * DH + (tx << 3);
#pragma unroll
        for (int j = 0; j < 8; j++)
            dst[j] = __fmul_rn(__fadd_rn(dst[j], acc[i][j]), 0.5f);
    }
}

// ------------------------------------------------------------------
// rmsnorm + rope, one warp per (row, head) 128-slice, in place.
// ------------------------------------------------------------------
__global__ void norm_rope(int mode, const float* __restrict__ w)
{
    int gw = (blockIdx.x * blockDim.x + threadIdx.x) >> 5;
    int lane = threadIdx.x & 31;
    float* buf; int rows, heads, rstride, pmul, padd;
    if (mode == 0)      { buf = g_q;  rows = SQ; heads = NHEAD; rstride = HIDN; pmul = 1; padd = 0; }
    else if (mode == 1) { buf = g_lk; rows = SQ; heads = NHEAD; rstride = HIDN; pmul = 1; padd = 0; }
    else                { buf = g_ck; rows = CB; heads = 1;     rstride = DH;   pmul = 4; padd = 3; }
    if (gw >= rows * heads) return;
    int row = gw / heads, h = gw - row * heads;
    float* p = buf + (size_t)row * rstride + h * DH;
    float x0 = p[lane], x1 = p[lane + 32], x2 = p[lane + 64], x3 = p[lane + 96];
    float ss = warp_sum(x0 * x0 + x1 * x1 + x2 * x2 + x3 * x3);
    float mean = __fadd_rn(__fmul_rn(ss, 0.0078125f), 1e-6f);
    float rs = __fdiv_rn(1.0f, __fsqrt_rn(mean));          // XLA rsqrt = 1/sqrt
    x0 = __fmul_rn(__fmul_rn(x0, rs), w[lane]);
    x1 = __fmul_rn(__fmul_rn(x1, rs), w[lane + 32]);
    x2 = __fmul_rn(__fmul_rn(x2, rs), w[lane + 64]);
    x3 = __fmul_rn(__fmul_rn(x3, rs), w[lane + 96]);
    // inv = 1.0f / powf(10000, lane/32), trig via double (CR-grade, fast-math-proof)
    float pf = (float)pow(10000.0, (double)lane * (1.0 / 32.0));
    float invf = __fdiv_rn(1.0f, pf);
    float ang = __fmul_rn((float)(row * pmul + padd), invf);
    float c = (float)cos((double)ang);
    float s = (float)sin((double)ang);
    float n0 = __fsub_rn(__fmul_rn(x0, c), __fmul_rn(x1, s));
    float n1 = __fadd_rn(__fmul_rn(x0, s), __fmul_rn(x1, c));
    p[lane] = n0; p[lane + 32] = n1; p[lane + 64] = x2; p[lane + 96] = x3;
}

__global__ void cmp_logits(const float* __restrict__ hidden, const float* __restrict__ Wc,
                           const float* __restrict__ bc)
{
    int gw = (blockIdx.x * blockDim.x + threadIdx.x) >> 5;
    int lane = threadIdx.x & 31;
    if (gw >= SQ) return;
    const float* hr = hidden + (size_t)gw * HIDN;
    float acc = 0.f, cmp = 0.f;
    for (int k = lane; k < HIDN; k += 32) {
        float y = __fmaf_rn(hr[k], Wc[k], -cmp);
        float t = __fadd_rn(acc, y);
        cmp = __fsub_rn(__fsub_rn(t, acc), y);
        acc = t;
    }
    acc = warp_sum(acc);
    if (lane == 0) g_wlog[gw] = __fadd_rn(acc, bc[0]);
}

__global__ void entries_kernel(const float* __restrict__ hidden)
{
    int c = blockIdx.x;
    float w0 = g_wlog[c * 4 + 0], w1 = g_wlog[c * 4 + 1];
    float w2 = g_wlog[c * 4 + 2], w3 = g_wlog[c * 4 + 3];
    float m = fmaxf(fmaxf(w0, w1), fmaxf(w2, w3));
    float e0 = (float)exp((double)__fsub_rn(w0, m));
    float e1 = (float)exp((double)__fsub_rn(w1, m));
    float e2 = (float)exp((double)__fsub_rn(w2, m));
    float e3 = (float)exp((double)__fsub_rn(w3, m));
    float sum = __fadd_rn(__fadd_rn(e0, e1), __fadd_rn(e2, e3));
    e0 = __fdiv_rn(e0, sum); e1 = __fdiv_rn(e1, sum);
    e2 = __fdiv_rn(e2, sum); e3 = __fdiv_rn(e3, sum);
    const float* h0 = hidden + (size_t)c * 4 * HIDN;
    float* dst = g_entries + (size_t)c * HIDN;
    for (int j = threadIdx.x; j < HIDN; j += blockDim.x)
        dst[j] = e0 * h0[j] + e1 * h0[HIDN + j] + e2 * h0[2 * HIDN + j] + e3 * h0[3 * HIDN + j];
}

// ------------------------------------------------------------------
// top-8 over causal prefix + softmax + gather cv; writes 1.0*ctx_sparse
// (local_pv later does (sparse+local)*0.5). One warp per (h, s).
// ------------------------------------------------------------------
__global__ void topk_sparse()
{
    int gw = (blockIdx.x * blockDim.x + threadIdx.x) >> 5;
    int lane = threadIdx.x & 31;
    if (gw >= NHEAD * SQ) return;
    int h = gw >> 12;
    int s = gw & (SQ - 1);
    int nc = (s + 1) >> 2;
    const float* row = g_sc + ((size_t)h * SQ + s) * CB;

    float bv[8]; int bi[8];
#pragma unroll
    for (int i = 0; i < 8; i++) { bv[i] = NEGV; bi[i] = -1; }
    for (int c = lane; c < nc; c += 32) {
        float v = row[c];
        if (v > bv[7]) {
            bv[7] = v; bi[7] = c;
#pragma unroll
            for (int j = 7; j > 0; j--) {
                if (bv[j] > bv[j - 1]) {
                    float tv = bv[j]; bv[j] = bv[j - 1]; bv[j - 1] = tv;
                    int txx = bi[j]; bi[j] = bi[j - 1]; bi[j - 1] = txx;
                }
            }
        }
    }
    // warp merge: 8 rounds of argmax (value desc, index asc tie-break)
    int ptr = 0;
    float tvv[8]; int tii[8];
#pragma unroll
    for (int t = 0; t < 8; t++) {
        float m = (ptr < 8) ? bv[ptr] : NEGV;
        int mi = (ptr < 8) ? bi[ptr] : 0x7fffffff;
#pragma unroll
        for (int o = 16; o; o >>= 1) {
            float om = __shfl_xor_sync(0xffffffffu, m, o);
            int oi = __shfl_xor_sync(0xffffffffu, mi, o);
            if (om > m || (om == m && oi < mi)) { m = om; mi = oi; }
        }
        tvv[t] = m; tii[t] = mi;
        if (ptr < 8 && bv[ptr] == m && bi[ptr] == mi) ptr++;
    }
    float m0 = tvv[0];
    float e[8]; float sum = 0.f;
#pragma unroll
    for (int t = 0; t < 8; t++) {
        e[t] = (tvv[t] > NEGH) ? (float)exp((double)__fsub_rn(tvv[t], m0)) : 0.f;
        sum += e[t];
    }
    float den = fmaxf(sum, 1e-9f);
    float c0 = 0.f, c1 = 0.f, c2 = 0.f, c3 = 0.f;
#pragma unroll
    for (int t = 0; t < 8; t++) {
        float wgt = __fdiv_rn(e[t], den);
        if (wgt > 0.f) {
            const float* vr = g_cv + (size_t)tii[t] * DH;
            c0 += wgt * vr[lane];      c1 += wgt * vr[lane + 32];
            c2 += wgt * vr[lane + 64]; c3 += wgt * vr[lane + 96];
        }
    }
    float* dst = g_merged + (size_t)s * HIDN + h * DH;
    dst[lane] = c0;      dst[lane + 32] = c1;
    dst[lane + 64] = c2; dst[lane + 96] = c3;
}

// masked softmax over 256 local keys; writes probabilities back (0 where masked)
__global__ void local_softmax()
{
    int gw = (blockIdx.x * blockDim.x + threadIdx.x) >> 5;
    int lane = threadIdx.x & 31;
    if (gw >= NHEAD * 32 * 128) return;
    int qi = gw & 127;
    int ch = (gw >> 7) & 31;
    float* rowp = g_scl + (size_t)gw * 256;
    int lo = (ch == 0) ? 128 : qi;   // chunk 0: only current-chunk keys (j>=128)
    int hi = qi + 128;
    float v[8];
    float m = NEGV;
#pragma unroll
    for (int t = 0; t < 8; t++) {
        int j = lane + (t << 5);
        bool ok = (j >= lo) && (j <= hi);
        v[t] = ok ? rowp[j] : NEGV;
        m = fmaxf(m, v[t]);
    }
    m = warp_max(m);
    float e[8]; float sum = 0.f;
#pragma unroll
    for (int t = 0; t < 8; t++) {
        int j = lane + (t << 5);
        bool ok = (j >= lo) && (j <= hi);
        e[t] = ok ? (float)exp((double)__fsub_rn(v[t], m)) : 0.f;
        sum += e[t];
    }
    sum = warp_sum(sum);
#pragma unroll
    for (int t = 0; t < 8; t++) rowp[lane + (t << 5)] = __fdiv_rn(e[t], sum);
}

// ------------------------------------------------------------------
extern "C" void kernel_launch(void* const* d_in, const int* in_sizes, int n_in,
                              void* d_out, int out_size)
{
    const float* hidden = (const float*)d_in[0];
    const float* Wq   = (const float*)d_in[1];
    const float* bq   = (const float*)d_in[2];
    const float* Wcmp = (const float*)d_in[3];
    const float* bcmp = (const float*)d_in[4];
    const float* Wk   = (const float*)d_in[5];
    const float* bk   = (const float*)d_in[6];
    const float* Wv   = (const float*)d_in[7];
    const float* bvv  = (const float*)d_in[8];
    const float* Wlk  = (const float*)d_in[9];
    const float* blkb = (const float*)d_in[10];
    const float* Wlv  = (const float*)d_in[11];
    const float* blvb = (const float*)d_in[12];
    const float* qnw  = (const float*)d_in[13];
    const float* knw  = (const float*)d_in[14];
    const float* Wo   = (const float*)d_in[15];
    const float* bo   = (const float*)d_in[16];
    float* out = (float*)d_out;

    dim3 thr(256);
    dim3 gBig(HIDN / 128, SQ / 128);   // 16 x 32

    sgemm_bias<true ><<<gBig, thr>>>(0, hidden, Wq,  bq,   nullptr);  // feeds top-k
    sgemm_bias<false><<<gBig, thr>>>(1, hidden, Wlk, blkb, nullptr);
    sgemm_bias<false><<<gBig, thr>>>(2, hidden, Wlv, blvb, nullptr);

    cmp_logits<<<SQ / 8, 256>>>(hidden, Wcmp, bcmp);
    entries_kernel<<<CB, 256>>>(hidden);

    sgemm_bias<true ><<<dim3(1, CB / 128), thr>>>(3, nullptr, Wk, bk,  nullptr); // feeds top-k
    sgemm_bias<false><<<dim3(1, CB / 128), thr>>>(4, nullptr, Wv, bvv, nullptr);

    norm_rope<<<(SQ * NHEAD) / 8, 256>>>(0, qnw);
    norm_rope<<<(SQ * NHEAD) / 8, 256>>>(1, knw);
    norm_rope<<<CB / 8, 256>>>(2, knw);

    gemm_nt_scores<true ><<<dim3(CB / 128, SQ / 128, NHEAD), thr>>>(0); // feeds top-k
    topk_sparse<<<(NHEAD * SQ) / 8, 256>>>();

    gemm_nt_scores<false><<<dim3(2, 1, NHEAD * 32), thr>>>(1);
    local_softmax<<<(NHEAD * 32 * 128) / 8, 256>>>();
    local_pv<<<dim3(1, 1, NHEAD * 32), thr>>>();

    sgemm_bias<false><<<gBig, thr>>>(5, nullptr, Wo, bo, out);
}

// round 8
// speedup vs baseline: 1.6235x; 1.2353x over previous
#include <cuda_runtime.h>
#include <cuda_bf16.h>
#include <math.h>
#include <stdint.h>

#define SQ 4096
#define HIDN 2048
#define NHEAD 16
#define DH 128
#define CB 1024
#define NEGV -1e30f
#define NEGH -5e29f
#define ATT_SCALE 0.08838834764831845f

// ------------- scratch (static __device__ globals; allocation-free) -------------
__device__ float g_q[(size_t)SQ * HIDN];        // q after norm+rope, [s][h*128+d]
__device__ float g_lk[(size_t)SQ * HIDN];
__device__ float g_lv[(size_t)SQ * HIDN];
__device__ float g_wlog[SQ];
__device__ float g_entries[(size_t)CB * HIDN];
__device__ float g_ck[CB * DH];
__device__ float g_cv[CB * DH];
__device__ float g_merged[(size_t)SQ * HIDN];   // sparse, then (sparse+local)*0.5
__device__ float g_sc[(size_t)NHEAD * SQ * CB]; // 268 MB compressed scores
__device__ float g_scl[(size_t)NHEAD * 32 * 128 * 256]; // 67 MB local scores/probs

// bf16 split buffers for tensor-core GEMMs
__device__ __nv_bfloat16 g_hid_h[(size_t)SQ * HIDN];
__device__ __nv_bfloat16 g_hid_l[(size_t)SQ * HIDN];
__device__ __nv_bfloat16 g_mrg_h[(size_t)SQ * HIDN];
__device__ __nv_bfloat16 g_mrg_l[(size_t)SQ * HIDN];
__device__ __nv_bfloat16 g_wlk_h[(size_t)HIDN * HIDN];  // transposed [n][k]
__device__ __nv_bfloat16 g_wlk_l[(size_t)HIDN * HIDN];
__device__ __nv_bfloat16 g_wlv_h[(size_t)HIDN * HIDN];
__device__ __nv_bfloat16 g_wlv_l[(size_t)HIDN * HIDN];
__device__ __nv_bfloat16 g_wo_h[(size_t)HIDN * HIDN];
__device__ __nv_bfloat16 g_wo_l[(size_t)HIDN * HIDN];

__device__ __forceinline__ float warp_sum(float v) {
#pragma unroll
    for (int o = 16; o; o >>= 1) v += __shfl_xor_sync(0xffffffffu, v, o);
    return v;
}
__device__ __forceinline__ float warp_max(float v) {
#pragma unroll
    for (int o = 16; o; o >>= 1) v = fmaxf(v, __shfl_xor_sync(0xffffffffu, v, o));
    return v;
}

// ======================= mma.sync helpers (base PTX, sm_80+) =======================
__device__ __forceinline__ uint32_t smem_u32(const void* p) {
    uint32_t a;
    asm("{ .reg .u64 t; cvta.to.shared.u64 t, %1; cvt.u32.u64 %0, t; }" : "=r"(a) : "l"(p));
    return a;
}
__device__ __forceinline__ void ldsm4(uint32_t& r0, uint32_t& r1, uint32_t& r2, uint32_t& r3,
                                      uint32_t addr) {
    asm volatile("ldmatrix.sync.aligned.m8n8.x4.shared.b16 {%0,%1,%2,%3}, [%4];"
                 : "=r"(r0), "=r"(r1), "=r"(r2), "=r"(r3) : "r"(addr));
}
__device__ __forceinline__ void mma16816(float* d, const uint32_t* a, const uint32_t* b) {
    asm volatile(
        "mma.sync.aligned.m16n8k16.row.col.f32.bf16.bf16.f32 "
        "{%0,%1,%2,%3}, {%4,%5,%6,%7}, {%8,%9}, {%0,%1,%2,%3};"
        : "+f"(d[0]), "+f"(d[1]), "+f"(d[2]), "+f"(d[3])
        : "r"(a[0]), "r"(a[1]), "r"(a[2]), "r"(a[3]), "r"(b[0]), "r"(b[1]));
}
// 8-slot XOR swizzle over (row, 16B-chunk) of a [128][32] bf16 tile (64 B rows).
// slot = ((row&1)*4 + c) ^ ((row>>1)&7); conflict-free for ldmatrix 8-row groups.
__device__ __forceinline__ uint32_t swz(int row, int c) {
    int slot = (((row & 1) << 2) | c) ^ ((row >> 1) & 7);
    return (uint32_t)(((row >> 1) << 7) + (slot << 4));
}

// ------------------------------------------------------------------
// Tensor GEMM via mma.sync bf16x3: C[4096][2048] = A @ W + bias.
// A split (Ah/Al [m][k]); W split transposed (Bh/Bl [n][k] == col-major operand).
// D += Ah*Bh + Ah*Bl + Al*Bh, fp32 accum in registers.
// Block 128x128, 8 warps (2m x 4n), warp tile 64x32, K-step 32.
// ------------------------------------------------------------------
__global__ void __launch_bounds__(256)
gemm_tc(const __nv_bfloat16* __restrict__ Ah, const __nv_bfloat16* __restrict__ Al,
        const __nv_bfloat16* __restrict__ Bh, const __nv_bfloat16* __restrict__ Bl,
        const float* __restrict__ bias, float* __restrict__ C)
{
    __shared__ char smem[4 * 8192];   // sAh | sAl | sBh | sBl
    const uint32_t sb = smem_u32(smem);
    const uint32_t SA_H = 0, SA_L = 8192, SB_H = 16384, SB_L = 24576;
    const int tid = threadIdx.x;
    const int lane = tid & 31, wid = tid >> 5;
    const int wm = wid >> 2;          // 0..1 -> m offset wm*64
    const int wn = wid & 3;           // 0..3 -> n offset wn*32
    const int row0 = blockIdx.y << 7;
    const int n0 = blockIdx.x << 7;

    float acc[4][4][4];
#pragma unroll
    for (int mi = 0; mi < 4; mi++)
#pragma unroll
        for (int ni = 0; ni < 4; ni++)
#pragma unroll
            for (int t = 0; t < 4; t++) acc[mi][ni][t] = 0.f;

    const int lr = lane & 15, lc = lane >> 4;   // ldmatrix address split

    for (int k0 = 0; k0 < HIDN; k0 += 32) {
        // stage 4 tiles of [128][32] bf16; 512 16B-chunks each, 2 per thread
#pragma unroll
        for (int i = 0; i < 2; i++) {
            const int idx = tid + (i << 8);
            const int row = idx >> 2, c = idx & 3;
            const uint32_t off = swz(row, c);
            const size_t ga = (size_t)(row0 + row) * HIDN + k0 + (c << 3);
            const size_t gb = (size_t)(n0 + row) * HIDN + k0 + (c << 3);
            *(uint4*)(smem + SA_H + off) = *(const uint4*)(Ah + ga);
            *(uint4*)(smem + SA_L + off) = *(const uint4*)(Al + ga);
            *(uint4*)(smem + SB_H + off) = *(const uint4*)(Bh + gb);
            *(uint4*)(smem + SB_L + off) = *(const uint4*)(Bl + gb);
        }
        __syncthreads();
#pragma unroll
        for (int kh = 0; kh < 2; kh++) {
            const int kc = kh * 2 + lc;
            uint32_t a_h[4][4], a_l[4][4];
#pragma unroll
            for (int mi = 0; mi < 4; mi++) {
                const int r = wm * 64 + mi * 16 + lr;
                const uint32_t o = swz(r, kc);
                ldsm4(a_h[mi][0], a_h[mi][1], a_h[mi][2], a_h[mi][3], sb + SA_H + o);
                ldsm4(a_l[mi][0], a_l[mi][1], a_l[mi][2], a_l[mi][3], sb + SA_L + o);
            }
            uint32_t b_h[4][2], b_l[4][2];
#pragma unroll
            for (int np = 0; np < 2; np++) {
                const int r = wn * 32 + np * 16 + lr;
                const uint32_t o = swz(r, kc);
                uint32_t r0, r1, r2, r3;
                ldsm4(r0, r1, r2, r3, sb + SB_H + o);
                b_h[np * 2][0] = r0; b_h[np * 2 + 1][0] = r1;
                b_h[np * 2][1] = r2; b_h[np * 2 + 1][1] = r3;
                ldsm4(r0, r1, r2, r3, sb + SB_L + o);
                b_l[np * 2][0] = r0; b_l[np * 2 + 1][0] = r1;
                b_l[np * 2][1] = r2; b_l[np * 2 + 1][1] = r3;
            }
#pragma unroll
            for (int mi = 0; mi < 4; mi++)
#pragma unroll
                for (int ni = 0; ni < 4; ni++) {
                    mma16816(acc[mi][ni], a_h[mi], b_h[ni]);
                    mma16816(acc[mi][ni], a_h[mi], b_l[ni]);
                    mma16816(acc[mi][ni], a_l[mi], b_h[ni]);
                }
        }
        __syncthreads();
    }
    // epilogue
#pragma unroll
    for (int mi = 0; mi < 4; mi++) {
        const int r = row0 + wm * 64 + mi * 16 + (lane >> 2);
#pragma unroll
        for (int ni = 0; ni < 4; ni++) {
            const int cc = n0 + wn * 32 + ni * 8 + ((lane & 3) << 1);
            const float b0 = bias[cc], b1 = bias[cc + 1];
            C[(size_t)r * HIDN + cc]           = __fadd_rn(acc[mi][ni][0], b0);
            C[(size_t)r * HIDN + cc + 1]       = __fadd_rn(acc[mi][ni][1], b1);
            C[(size_t)(r + 8) * HIDN + cc]     = __fadd_rn(acc[mi][ni][2], b0);
            C[(size_t)(r + 8) * HIDN + cc + 1] = __fadd_rn(acc[mi][ni][3], b1);
        }
    }
}

// split fp32 -> bf16 hi + bf16 lo (residual)
__global__ void split_plain(const float* __restrict__ src,
                            __nv_bfloat16* __restrict__ h, __nv_bfloat16* __restrict__ l,
                            int n)
{
    int i = blockIdx.x * blockDim.x + threadIdx.x;
    if (i >= n) return;
    float x = src[i];
    __nv_bfloat16 hi = __float2bfloat16(x);
    h[i] = hi;
    l[i] = __float2bfloat16(__fsub_rn(x, __bfloat162float(hi)));
}

// transpose + split: W [K=2048][N=2048] -> T{h,l} [n][k]
__global__ void tsplit(const float* __restrict__ W,
                       __nv_bfloat16* __restrict__ Th, __nv_bfloat16* __restrict__ Tl)
{
    __shared__ float tile[32][33];
    const int n0 = blockIdx.x << 5, k0 = blockIdx.y << 5;
    const int tx = threadIdx.x & 31, ty = threadIdx.x >> 5;  // 256 thr = 32x8
#pragma unroll
    for (int i = 0; i < 32; i += 8)
        tile[ty + i][tx] = W[(size_t)(k0 + ty + i) * HIDN + n0 + tx];
    __syncthreads();
#pragma unroll
    for (int i = 0; i < 32; i += 8) {
        float x = tile[tx][ty + i];
        __nv_bfloat16 hi = __float2bfloat16(x);
        size_t o = (size_t)(n0 + ty + i) * HIDN + k0 + tx;
        Th[o] = hi;
        Tl[o] = __float2bfloat16(__fsub_rn(x, __bfloat162float(hi)));
    }
}

// ------------------------------------------------------------------
// SIMT SGEMM with bias (kept for selection-critical GEMMs), K = 2048.
// KH=true: chunked-Kahan (tile-16 partials folded exactly).
// mode 0: hidden@Wq -> g_q   3: entries@Wk -> g_ck   4: entries@Wv -> g_cv
// ------------------------------------------------------------------
template <bool KH>
__global__ __launch_bounds__(256)
void sgemm_bias(int mode, const float* __restrict__ X,
                const float* __restrict__ W, const float* __restrict__ bias,
                float* __restrict__ outp)
{
    const float* A;
    float* C;
    int lda, ldb, ldc;
    if (mode == 0) { A = X; C = g_q; lda = HIDN; ldb = HIDN; ldc = HIDN; }
    else { A = g_entries; C = (mode == 3) ? g_ck : g_cv; lda = HIDN; ldb = DH; ldc = DH; }

    __shared__ float As[16][128];
    __shared__ float Bs[16][128];
    const int tid = threadIdx.x;
    const int row0 = blockIdx.y << 7;
    const int col0 = blockIdx.x << 7;
    const int ty = tid >> 4, tx = tid & 15;

    float acc[8][8], cmp[8][8];
#pragma unroll
    for (int i = 0; i < 8; i++)
#pragma unroll
        for (int j = 0; j < 8; j++) { acc[i][j] = 0.f; cmp[i][j] = 0.f; }

    for (int k0 = 0; k0 < HIDN; k0 += 16) {
#pragma unroll
        for (int t = 0; t < 2; t++) {
            int jj = tid + (t << 8);
            int m = jj >> 2, k4 = (jj & 3) << 2;
            float4 v = *(const float4*)(A + (size_t)(row0 + m) * lda + k0 + k4);
            As[k4 + 0][m] = v.x; As[k4 + 1][m] = v.y;
            As[k4 + 2][m] = v.z; As[k4 + 3][m] = v.w;
        }
#pragma unroll
        for (int t = 0; t < 2; t++) {
            int jj = tid + (t << 8);
            int kk = jj >> 5, n4 = (jj & 31) << 2;
            *(float4*)&Bs[kk][n4] = *(const float4*)(W + (size_t)(k0 + kk) * ldb + col0 + n4);
        }
        __syncthreads();
        if (KH) {
            float tmp[8][8];
#pragma unroll
            for (int i = 0; i < 8; i++)
#pragma unroll
                for (int j = 0; j < 8; j++) tmp[i][j] = 0.f;
#pragma unroll
            for (int kk = 0; kk < 16; kk++) {
                float ra[8], rb[8];
                *(float4*)&ra[0] = *(const float4*)&As[kk][ty << 3];
                *(float4*)&ra[4] = *(const float4*)&As[kk][(ty << 3) + 4];
                *(float4*)&rb[0] = *(const float4*)&Bs[kk][tx << 3];
                *(float4*)&rb[4] = *(const float4*)&Bs[kk][(tx << 3) + 4];
#pragma unroll
                for (int i = 0; i < 8; i++)
#pragma unroll
                    for (int j = 0; j < 8; j++)
                        tmp[i][j] = __fmaf_rn(ra[i], rb[j], tmp[i][j]);
            }
#pragma unroll
            for (int i = 0; i < 8; i++)
#pragma unroll
                for (int j = 0; j < 8; j++) {
                    float y = __fsub_rn(tmp[i][j], cmp[i][j]);
                    float t2 = __fadd_rn(acc[i][j], y);
                    cmp[i][j] = __fsub_rn(__fsub_rn(t2, acc[i][j]), y);
                    acc[i][j] = t2;
                }
        } else {
#pragma unroll
            for (int kk = 0; kk < 16; kk++) {
                float ra[8], rb[8];
                *(float4*)&ra[0] = *(const float4*)&As[kk][ty << 3];
                *(float4*)&ra[4] = *(const float4*)&As[kk][(ty << 3) + 4];
                *(float4*)&rb[0] = *(const float4*)&Bs[kk][tx << 3];
                *(float4*)&rb[4] = *(const float4*)&Bs[kk][(tx << 3) + 4];
#pragma unroll
                for (int i = 0; i < 8; i++)
#pragma unroll
                    for (int j = 0; j < 8; j++) acc[i][j] += ra[i] * rb[j];
            }
        }
        __syncthreads();
    }
#pragma unroll
    for (int i = 0; i < 8; i++) {
        size_t r = row0 + (ty << 3) + i;
#pragma unroll
        for (int j = 0; j < 8; j++) {
            int c = col0 + (tx << 3) + j;
            C[r * ldc + c] = __fadd_rn(acc[i][j], bias[c]);
        }
    }
}

// ------------------------------------------------------------------
// NT GEMM (C = scale * A @ B^T), K = 128.
// mode 0 (KH=true): sc[h][s][c]  grid (8, 32, 16), causal tile skip
// mode 1 (KH=false): local scores grid (2, 1, 512), clamped B rows
// ------------------------------------------------------------------
template <bool KH>
__global__ __launch_bounds__(256)
void gemm_nt_scores(int mode)
{
    const float* A; const float* B; float* C;
    int lda, ldb, ldc, b_base, row0, col0;
    if (mode == 0) {
        int h = blockIdx.z;
        row0 = blockIdx.y << 7; col0 = blockIdx.x << 7;
        if (col0 >= (row0 >> 2) + 32) return;        // fully non-causal tile
        A = g_q + h * DH; lda = HIDN;
        B = g_ck; ldb = DH; b_base = 0;
        C = g_sc + (size_t)h * SQ * CB; ldc = CB;
    } else {
        int h = blockIdx.z >> 5, ch = blockIdx.z & 31;
        row0 = 0; col0 = blockIdx.x << 7;
        A = g_q + (size_t)(ch << 7) * HIDN + h * DH; lda = HIDN;
        B = g_lk + h * DH; ldb = HIDN; b_base = (ch << 7) - 128;
        C = g_scl + (size_t)blockIdx.z * 128 * 256; ldc = 256;
    }
    __shared__ float As[16][128];
    __shared__ float Bs[16][128];
    const int tid = threadIdx.x;
    const int ty = tid >> 4, tx = tid & 15;

    float acc[8][8], cmp[8][8];
#pragma unroll
    for (int i = 0; i < 8; i++)
#pragma unroll
        for (int j = 0; j < 8; j++) { acc[i][j] = 0.f; cmp[i][j] = 0.f; }

    for (int k0 = 0; k0 < DH; k0 += 16) {
#pragma unroll
        for (int t = 0; t < 2; t++) {
            int jj = tid + (t << 8);
            int m = jj >> 2, k4 = (jj & 3) << 2;
            float4 v = *(const float4*)(A + (size_t)(row0 + m) * lda + k0 + k4);
            As[k4 + 0][m] = v.x; As[k4 + 1][m] = v.y;
            As[k4 + 2][m] = v.z; As[k4 + 3][m] = v.w;
        }
#pragma unroll
        for (int t = 0; t < 2; t++) {
            int jj = tid + (t << 8);
            int n = jj >> 2, k4 = (jj & 3) << 2;
            int br = b_base + col0 + n;
            if (br < 0) br = 0;                       // masked later; keep reads in-bounds
            float4 v = *(const float4*)(B + (size_t)br * ldb + k0 + k4);
            Bs[k4 + 0][n] = v.x; Bs[k4 + 1][n] = v.y;
            Bs[k4 + 2][n] = v.z; Bs[k4 + 3][n] = v.w;
        }
        __syncthreads();
        if (KH) {
            float tmp[8][8];
#pragma unroll
            for (int i = 0; i < 8; i++)
#pragma unroll
                for (int j = 0; j < 8; j++) tmp[i][j] = 0.f;
#pragma unroll
            for (int kk = 0; kk < 16; kk++) {
                float ra[8], rb[8];
                *(float4*)&ra[0] = *(const float4*)&As[kk][ty << 3];
                *(float4*)&ra[4] = *(const float4*)&As[kk][(ty << 3) + 4];
                *(float4*)&rb[0] = *(const float4*)&Bs[kk][tx << 3];
                *(float4*)&rb[4] = *(const float4*)&Bs[kk][(tx << 3) + 4];
#pragma unroll
                for (int i = 0; i < 8; i++)
#pragma unroll
                    for (int j = 0; j < 8; j++)
                        tmp[i][j] = __fmaf_rn(ra[i], rb[j], tmp[i][j]);
            }
#pragma unroll
            for (int i = 0; i < 8; i++)
#pragma unroll
                for (int j = 0; j < 8; j++) {
                    float y = __fsub_rn(tmp[i][j], cmp[i][j]);
                    float t2 = __fadd_rn(acc[i][j], y);
                    cmp[i][j] = __fsub_rn(__fsub_rn(t2, acc[i][j]), y);
                    acc[i][j] = t2;
                }
        } else {
#pragma unroll
            for (int kk = 0; kk < 16; kk++) {
                float ra[8], rb[8];
                *(float4*)&ra[0] = *(const float4*)&As[kk][ty << 3];
                *(float4*)&ra[4] = *(const float4*)&As[kk][(ty << 3) + 4];
                *(float4*)&rb[0] = *(const float4*)&Bs[kk][tx << 3];
                *(float4*)&rb[4] = *(const float4*)&Bs[kk][(tx << 3) + 4];
#pragma unroll
                for (int i = 0; i < 8; i++)
#pragma unroll
                    for (int j = 0; j < 8; j++) acc[i][j] += ra[i] * rb[j];
            }
        }
        __syncthreads();
    }
#pragma unroll
    for (int i = 0; i < 8; i++) {
        size_t r = row0 + (ty << 3) + i;
#pragma unroll
        for (int j = 0; j < 8; j++)
            C[r * ldc + col0 + (tx << 3) + j] = __fmul_rn(acc[i][j], ATT_SCALE);
    }
}

// local PV: ctx_local = P[128x256] @ Vwin[256x128]; merged = (sparse+local)*0.5
__global__ __launch_bounds__(256)
void local_pv()
{
    int h = blockIdx.z >> 5, ch = blockIdx.z & 31;
    const float* A = g_scl + (size_t)blockIdx.z * 128 * 256; // lda=256
    const float* B = g_lv + h * DH;                          // ldb=HIDN, clamped rows
    int b_base = (ch << 7) - 128;

    __shared__ float As[16][128];
    __shared__ float Bs[16][128];
    const int tid = threadIdx.x;
    const int ty = tid >> 4, tx = tid & 15;

    float acc[8][8];
#pragma unroll
    for (int i = 0; i < 8; i++)
#pragma unroll
        for (int j = 0; j < 8; j++) acc[i][j] = 0.f;

    for (int k0 = 0; k0 < 256; k0 += 16) {
#pragma unroll
        for (int t = 0; t < 2; t++) {
            int jj = tid + (t << 8);
            int m = jj >> 2, k4 = (jj & 3) << 2;
            float4 v = *(const float4*)(A + (size_t)m * 256 + k0 + k4);
            As[k4 + 0][m] = v.x; As[k4 + 1][m] = v.y;
            As[k4 + 2][m] = v.z; As[k4 + 3][m] = v.w;
        }
#pragma unroll
        for (int t = 0; t < 2; t++) {
            int jj = tid + (t << 8);
            int kk = jj >> 5, n4 = (jj & 31) << 2;
            int br = b_base + k0 + kk;
            if (br < 0) br = 0;                       // p==0 there, so harmless
            *(float4*)&Bs[kk][n4] = *(const float4*)(B + (size_t)br * HIDN + n4);
        }
        __syncthreads();
#pragma unroll
        for (int kk = 0; kk < 16; kk++) {
            float ra[8], rb[8];
            *(float4*)&ra[0] = *(const float4*)&As[kk][ty << 3];
            *(float4*)&ra[4] = *(const float4*)&As[kk][(ty << 3) + 4];
            *(float4*)&rb[0] = *(const float4*)&Bs[kk][tx << 3];
            *(float4*)&rb[4] = *(const float4*)&Bs[kk][(tx << 3) + 4];
#pragma unroll
            for (int i = 0; i < 8; i++)
#pragma unroll
                for (int j = 0; j < 8; j++) acc[i][j] += ra[i] * rb[j];
        }
        __syncthreads();
    }
#pragma unroll
    for (int i = 0; i < 8; i++) {
        float* dst = g_merged + (size_t)((ch << 7) + (ty << 3) + i) * HIDN + h * DH + (tx << 3);
#pragma unroll
        for (int j = 0; j < 8; j++)
            dst[j] = __fmul_rn(__fadd_rn(dst[j], acc[i][j]), 0.5f);
    }
}

// ------------------------------------------------------------------
// rmsnorm + rope, one warp per (row, head) 128-slice, in place.
// ------------------------------------------------------------------
__global__ void norm_rope(int mode, const float* __restrict__ w)
{
    int gw = (blockIdx.x * blockDim.x + threadIdx.x) >> 5;
    int lane = threadIdx.x & 31;
    float* buf; int rows, heads, rstride, pmul, padd;
    if (mode == 0)      { buf = g_q;  rows = SQ; heads = NHEAD; rstride = HIDN; pmul = 1; padd = 0; }
    else if (mode == 1) { buf = g_lk; rows = SQ; heads = NHEAD; rstride = HIDN; pmul = 1; padd = 0; }
    else                { buf = g_ck; rows = CB; heads = 1;     rstride = DH;   pmul = 4; padd = 3; }
    if (gw >= rows * heads) return;
    int row = gw / heads, h = gw - row * heads;
    float* p = buf + (size_t)row * rstride + h * DH;
    float x0 = p[lane], x1 = p[lane + 32], x2 = p[lane + 64], x3 = p[lane + 96];
    float ss = warp_sum(x0 * x0 + x1 * x1 + x2 * x2 + x3 * x3);
    float mean = __fadd_rn(__fmul_rn(ss, 0.0078125f), 1e-6f);
    float rs = __fdiv_rn(1.0f, __fsqrt_rn(mean));          // XLA rsqrt = 1/sqrt
    x0 = __fmul_rn(__fmul_rn(x0, rs), w[lane]);
    x1 = __fmul_rn(__fmul_rn(x1, rs), w[lane + 32]);
    x2 = __fmul_rn(__fmul_rn(x2, rs), w[lane + 64]);
    x3 = __fmul_rn(__fmul_rn(x3, rs), w[lane + 96]);
    // inv = 1.0f / powf(10000, lane/32), trig via double (CR-grade, fast-math-proof)
    float pf = (float)pow(10000.0, (double)lane * (1.0 / 32.0));
    float invf = __fdiv_rn(1.0f, pf);
    float ang = __fmul_rn((float)(row * pmul + padd), invf);
    float c = (float)cos((double)ang);
    float s = (float)sin((double)ang);
    float n0 = __fsub_rn(__fmul_rn(x0, c), __fmul_rn(x1, s));
    float n1 = __fadd_rn(__fmul_rn(x0, s), __fmul_rn(x1, c));
    p[lane] = n0; p[lane + 32] = n1; p[lane + 64] = x2; p[lane + 96] = x3;
}

__global__ void cmp_logits(const float* __restrict__ hidden, const float* __restrict__ Wc,
                           const float* __restrict__ bc)
{
    int gw = (blockIdx.x * blockDim.x + threadIdx.x) >> 5;
    int lane = threadIdx.x & 31;
    if (gw >= SQ) return;
    const float* hr = hidden + (size_t)gw * HIDN;
    float acc = 0.f, cmp = 0.f;
    for (int k = lane; k < HIDN; k += 32) {
        float y = __fmaf_rn(hr[k], Wc[k], -cmp);
        float t = __fadd_rn(acc, y);
        cmp = __fsub_rn(__fsub_rn(t, acc), y);
        acc = t;
    }
    acc = warp_sum(acc);
    if (lane == 0) g_wlog[gw] = __fadd_rn(acc, bc[0]);
}

__global__ void entries_kernel(const float* __restrict__ hidden)
{
    int c = blockIdx.x;
    float w0 = g_wlog[c * 4 + 0], w1 = g_wlog[c * 4 + 1];
    float w2 = g_wlog[c * 4 + 2], w3 = g_wlog[c * 4 + 3];
    float m = fmaxf(fmaxf(w0, w1), fmaxf(w2, w3));
    float e0 = (float)exp((double)__fsub_rn(w0, m));
    float e1 = (float)exp((double)__fsub_rn(w1, m));
    float e2 = (float)exp((double)__fsub_rn(w2, m));
    float e3 = (float)exp((double)__fsub_rn(w3, m));
    float sum = __fadd_rn(__fadd_rn(e0, e1), __fadd_rn(e2, e3));
    e0 = __fdiv_rn(e0, sum); e1 = __fdiv_rn(e1, sum);
    e2 = __fdiv_rn(e2, sum); e3 = __fdiv_rn(e3, sum);
    const float* h0 = hidden + (size_t)c * 4 * HIDN;
    float* dst = g_entries + (size_t)c * HIDN;
    for (int j = threadIdx.x; j < HIDN; j += blockDim.x)
        dst[j] = e0 * h0[j] + e1 * h0[HIDN + j] + e2 * h0[2 * HIDN + j] + e3 * h0[3 * HIDN + j];
}

// ------------------------------------------------------------------
// top-8 over causal prefix + softmax + gather cv; writes 1.0*ctx_sparse
// (local_pv later does (sparse+local)*0.5). One warp per (h, s).
// ------------------------------------------------------------------
__global__ void topk_sparse()
{
    int gw = (blockIdx.x * blockDim.x + threadIdx.x) >> 5;
    int lane = threadIdx.x & 31;
    if (gw >= NHEAD * SQ) return;
    int h = gw >> 12;
    int s = gw & (SQ - 1);
    int nc = (s + 1) >> 2;
    const float* row = g_sc + ((size_t)h * SQ + s) * CB;

    float bv[8]; int bi[8];
#pragma unroll
    for (int i = 0; i < 8; i++) { bv[i] = NEGV; bi[i] = -1; }
    for (int c = lane; c < nc; c += 32) {
        float v = row[c];
        if (v > bv[7]) {
            bv[7] = v; bi[7] = c;
#pragma unroll
            for (int j = 7; j > 0; j--) {
                if (bv[j] > bv[j - 1]) {
                    float tv = bv[j]; bv[j] = bv[j - 1]; bv[j - 1] = tv;
                    int txx = bi[j]; bi[j] = bi[j - 1]; bi[j - 1] = txx;
                }
            }
        }
    }
    // warp merge: 8 rounds of argmax (value desc, index asc tie-break)
    int ptr = 0;
    float tvv[8]; int tii[8];
#pragma unroll
    for (int t = 0; t < 8; t++) {
        float m = (ptr < 8) ? bv[ptr] : NEGV;
        int mi = (ptr < 8) ? bi[ptr] : 0x7fffffff;
#pragma unroll
        for (int o = 16; o; o >>= 1) {
            float om = __shfl_xor_sync(0xffffffffu, m, o);
            int oi = __shfl_xor_sync(0xffffffffu, mi, o);
            if (om > m || (om == m && oi < mi)) { m = om; mi = oi; }
        }
        tvv[t] = m; tii[t] = mi;
        if (ptr < 8 && bv[ptr] == m && bi[ptr] == mi) ptr++;
    }
    float m0 = tvv[0];
    float e[8]; float sum = 0.f;
#pragma unroll
    for (int t = 0; t < 8; t++) {
        e[t] = (tvv[t] > NEGH) ? (float)exp((double)__fsub_rn(tvv[t], m0)) : 0.f;
        sum += e[t];
    }
    float den = fmaxf(sum, 1e-9f);
    float c0 = 0.f, c1 = 0.f, c2 = 0.f, c3 = 0.f;
#pragma unroll
    for (int t = 0; t < 8; t++) {
        float wgt = __fdiv_rn(e[t], den);
        if (wgt > 0.f) {
            const float* vr = g_cv + (size_t)tii[t] * DH;
            c0 += wgt * vr[lane];      c1 += wgt * vr[lane + 32];
            c2 += wgt * vr[lane + 64]; c3 += wgt * vr[lane + 96];
        }
    }
    float* dst = g_merged + (size_t)s * HIDN + h * DH;
    dst[lane] = c0;      dst[lane + 32] = c1;
    dst[lane + 64] = c2; dst[lane + 96] = c3;
}

// masked softmax over 256 local keys; writes probabilities back (0 where masked)
__global__ void local_softmax()
{
    int gw = (blockIdx.x * blockDim.x + threadIdx.x) >> 5;
    int lane = threadIdx.x & 31;
    if (gw >= NHEAD * 32 * 128) return;
    int qi = gw & 127;
    int ch = (gw >> 7) & 31;
    float* rowp = g_scl + (size_t)gw * 256;
    int lo = (ch == 0) ? 128 : qi;   // chunk 0: only current-chunk keys (j>=128)
    int hi = qi + 128;
    float v[8];
    float m = NEGV;
#pragma unroll
    for (int t = 0; t < 8; t++) {
        int j = lane + (t << 5);
        bool ok = (j >= lo) && (j <= hi);
        v[t] = ok ? rowp[j] : NEGV;
        m = fmaxf(m, v[t]);
    }
    m = warp_max(m);
    float e[8]; float sum = 0.f;
#pragma unroll
    for (int t = 0; t < 8; t++) {
        int j = lane + (t << 5);
        bool ok = (j >= lo) && (j <= hi);
        e[t] = ok ? (float)exp((double)__fsub_rn(v[t], m)) : 0.f;
        sum += e[t];
    }
    sum = warp_sum(sum);
#pragma unroll
    for (int t = 0; t < 8; t++) rowp[lane + (t << 5)] = __fdiv_rn(e[t], sum);
}

// ------------------------------------------------------------------
extern "C" void kernel_launch(void* const* d_in, const int* in_sizes, int n_in,
                              void* d_out, int out_size)
{
    const float* hidden = (const float*)d_in[0];
    const float* Wq   = (const float*)d_in[1];
    const float* bq   = (const float*)d_in[2];
    const float* Wcmp = (const float*)d_in[3];
    const float* bcmp = (const float*)d_in[4];
    const float* Wk   = (const float*)d_in[5];
    const float* bk   = (const float*)d_in[6];
    const float* Wv   = (const float*)d_in[7];
    const float* bvv  = (const float*)d_in[8];
    const float* Wlk  = (const float*)d_in[9];
    const float* blkb = (const float*)d_in[10];
    const float* Wlv  = (const float*)d_in[11];
    const float* blvb = (const float*)d_in[12];
    const float* qnw  = (const float*)d_in[13];
    const float* knw  = (const float*)d_in[14];
    const float* Wo   = (const float*)d_in[15];
    const float* bo   = (const float*)d_in[16];
    float* out = (float*)d_out;

    // device-global bf16 buffers (symbol lookup once)
    static __nv_bfloat16 *hid_h = nullptr, *hid_l, *mrg_h, *mrg_l,
                         *wlk_h, *wlk_l, *wlv_h, *wlv_l, *wo_h, *wo_l;
    static float *p_lk = nullptr, *p_lv, *p_merged;
    if (!hid_h) {
        cudaGetSymbolAddress((void**)&hid_h, g_hid_h);
        cudaGetSymbolAddress((void**)&hid_l, g_hid_l);
        cudaGetSymbolAddress((void**)&mrg_h, g_mrg_h);
        cudaGetSymbolAddress((void**)&mrg_l, g_mrg_l);
        cudaGetSymbolAddress((void**)&wlk_h, g_wlk_h);
        cudaGetSymbolAddress((void**)&wlk_l, g_wlk_l);
        cudaGetSymbolAddress((void**)&wlv_h, g_wlv_h);
        cudaGetSymbolAddress((void**)&wlv_l, g_wlv_l);
        cudaGetSymbolAddress((void**)&wo_h, g_wo_h);
        cudaGetSymbolAddress((void**)&wo_l, g_wo_l);
        cudaGetSymbolAddress((void**)&p_lk, g_lk);
        cudaGetSymbolAddress((void**)&p_lv, g_lv);
        cudaGetSymbolAddress((void**)&p_merged, g_merged);
    }

    dim3 thr(256);
    const int NELT = SQ * HIDN;

    // splits (independent of everything else)
    split_plain<<<(NELT + 255) / 256, 256>>>(hidden, hid_h, hid_l, NELT);
    tsplit<<<dim3(64, 64), 256>>>(Wlk, wlk_h, wlk_l);
    tsplit<<<dim3(64, 64), 256>>>(Wlv, wlv_h, wlv_l);
    tsplit<<<dim3(64, 64), 256>>>(Wo,  wo_h,  wo_l);

    // selection-critical projection (chunked-Kahan SIMT)
    sgemm_bias<true><<<dim3(HIDN / 128, SQ / 128), thr>>>(0, hidden, Wq, bq, nullptr);

    // smooth projections on tensor cores (mma.sync bf16x3)
    gemm_tc<<<dim3(HIDN / 128, SQ / 128), 256>>>(hid_h, hid_l, wlk_h, wlk_l, blkb, p_lk);
    gemm_tc<<<dim3(HIDN / 128, SQ / 128), 256>>>(hid_h, hid_l, wlv_h, wlv_l, blvb, p_lv);

    cmp_logits<<<SQ / 8, 256>>>(hidden, Wcmp, bcmp);
    entries_kernel<<<CB, 256>>>(hidden);

    sgemm_bias<true ><<<dim3(1, CB / 128), thr>>>(3, nullptr, Wk, bk,  nullptr); // feeds top-k
    sgemm_bias<false><<<dim3(1, CB / 128), thr>>>(4, nullptr, Wv, bvv, nullptr);

    norm_rope<<<(SQ * NHEAD) / 8, 256>>>(0, qnw);
    norm_rope<<<(SQ * NHEAD) / 8, 256>>>(1, knw);
    norm_rope<<<CB / 8, 256>>>(2, knw);

    gemm_nt_scores<true ><<<dim3(CB / 128, SQ / 128, NHEAD), thr>>>(0); // feeds top-k
    topk_sparse<<<(NHEAD * SQ) / 8, 256>>>();

    gemm_nt_scores<false><<<dim3(2, 1, NHEAD * 32), thr>>>(1);
    local_softmax<<<(NHEAD * 32 * 128) / 8, 256>>>();
    local_pv<<<dim3(1, 1, NHEAD * 32), thr>>>();

    // output projection on tensor cores
    split_plain<<<(NELT + 255) / 256, 256>>>(p_merged, mrg_h, mrg_l, NELT);
    gemm_tc<<<dim3(HIDN / 128, SQ / 128), 256>>>(mrg_h, mrg_l, wo_h, wo_l, bo, out);
}

// round 9
// speedup vs baseline: 1.6426x; 1.0117x over previous
#include <cuda_runtime.h>
#include <cuda_bf16.h>
#include <math.h>
#include <stdint.h>

#define SQ 4096
#define HIDN 2048
#define NHEAD 16
#define DH 128
#define CB 1024
#define NEGV -1e30f
#define NEGH -5e29f
#define ATT_SCALE 0.08838834764831845f

// ------------- scratch (static __device__ globals; allocation-free) -------------
__device__ float g_q[(size_t)SQ * HIDN];        // q after norm+rope, [s][h*128+d]
__device__ float g_lk[(size_t)SQ * HIDN];
__device__ float g_lv[(size_t)SQ * HIDN];
__device__ float g_wlog[SQ];
__device__ float g_entries[(size_t)CB * HIDN];
__device__ float g_ck[CB * DH];
__device__ float g_cv[CB * DH];
__device__ float g_merged[(size_t)SQ * HIDN];   // sparse, then (sparse+local)*0.5
__device__ float g_sc[(size_t)NHEAD * SQ * CB]; // 268 MB compressed scores
__device__ float g_scl[(size_t)NHEAD * 32 * 128 * 256]; // 67 MB local scores

// bf16 split buffers for tensor-core GEMMs
__device__ __nv_bfloat16 g_hid_h[(size_t)SQ * HIDN];
__device__ __nv_bfloat16 g_hid_l[(size_t)SQ * HIDN];
__device__ __nv_bfloat16 g_mrg_h[(size_t)SQ * HIDN];
__device__ __nv_bfloat16 g_mrg_l[(size_t)SQ * HIDN];
__device__ __nv_bfloat16 g_qh[(size_t)SQ * HIDN];
__device__ __nv_bfloat16 g_ql[(size_t)SQ * HIDN];
__device__ __nv_bfloat16 g_lkh[(size_t)SQ * HIDN];
__device__ __nv_bfloat16 g_lkl[(size_t)SQ * HIDN];
__device__ __nv_bfloat16 g_lvh[(size_t)SQ * HIDN];
__device__ __nv_bfloat16 g_lvl[(size_t)SQ * HIDN];
__device__ __nv_bfloat16 g_sph[(size_t)NHEAD * 32 * 128 * 256];  // prob splits
__device__ __nv_bfloat16 g_spl[(size_t)NHEAD * 32 * 128 * 256];
__device__ __nv_bfloat16 g_wlk_h[(size_t)HIDN * HIDN];  // transposed [n][k]
__device__ __nv_bfloat16 g_wlk_l[(size_t)HIDN * HIDN];
__device__ __nv_bfloat16 g_wlv_h[(size_t)HIDN * HIDN];
__device__ __nv_bfloat16 g_wlv_l[(size_t)HIDN * HIDN];
__device__ __nv_bfloat16 g_wo_h[(size_t)HIDN * HIDN];
__device__ __nv_bfloat16 g_wo_l[(size_t)HIDN * HIDN];

__device__ __forceinline__ float warp_sum(float v) {
#pragma unroll
    for (int o = 16; o; o >>= 1) v += __shfl_xor_sync(0xffffffffu, v, o);
    return v;
}
__device__ __forceinline__ float warp_max(float v) {
#pragma unroll
    for (int o = 16; o; o >>= 1) v = fmaxf(v, __shfl_xor_sync(0xffffffffu, v, o));
    return v;
}

// ======================= mma.sync helpers (base PTX, sm_80+) =======================
__device__ __forceinline__ uint32_t smem_u32(const void* p) {
    uint32_t a;
    asm("{ .reg .u64 t; cvta.to.shared.u64 t, %1; cvt.u32.u64 %0, t; }" : "=r"(a) : "l"(p));
    return a;
}
__device__ __forceinline__ void ldsm4(uint32_t& r0, uint32_t& r1, uint32_t& r2, uint32_t& r3,
                                      uint32_t addr) {
    asm volatile("ldmatrix.sync.aligned.m8n8.x4.shared.b16 {%0,%1,%2,%3}, [%4];"
                 : "=r"(r0), "=r"(r1), "=r"(r2), "=r"(r3) : "r"(addr));
}
__device__ __forceinline__ void ldsm4t(uint32_t& r0, uint32_t& r1, uint32_t& r2, uint32_t& r3,
                                       uint32_t addr) {
    asm volatile("ldmatrix.sync.aligned.m8n8.x4.trans.shared.b16 {%0,%1,%2,%3}, [%4];"
                 : "=r"(r0), "=r"(r1), "=r"(r2), "=r"(r3) : "r"(addr));
}
__device__ __forceinline__ void mma16816(float* d, const uint32_t* a, const uint32_t* b) {
    asm volatile(
        "mma.sync.aligned.m16n8k16.row.col.f32.bf16.bf16.f32 "
        "{%0,%1,%2,%3}, {%4,%5,%6,%7}, {%8,%9}, {%0,%1,%2,%3};"
        : "+f"(d[0]), "+f"(d[1]), "+f"(d[2]), "+f"(d[3])
        : "r"(a[0]), "r"(a[1]), "r"(a[2]), "r"(a[3]), "r"(b[0]), "r"(b[1]));
}
// 8-slot XOR swizzle over (row, 16B-chunk) of a [128][32] bf16 tile (64 B rows).
__device__ __forceinline__ uint32_t swz(int row, int c) {
    int slot = (((row & 1) << 2) | c) ^ ((row >> 1) & 7);
    return (uint32_t)(((row >> 1) << 7) + (slot << 4));
}
// swizzle for [32 k][128 d] bf16 tile (256 B rows), chunk = 16B of d
__device__ __forceinline__ uint32_t vswz(int row, int c) {
    return (uint32_t)((row << 8) + ((c ^ (row & 7)) << 4));
}

// ------------------------------------------------------------------
// Tensor GEMM via mma.sync bf16x3: C[4096][2048] = A @ W + bias.
// Block 128x128, 8 warps (2m x 4n), warp tile 64x32, K-step 32.
// ------------------------------------------------------------------
__global__ void __launch_bounds__(256)
gemm_tc(const __nv_bfloat16* __restrict__ Ah, const __nv_bfloat16* __restrict__ Al,
        const __nv_bfloat16* __restrict__ Bh, const __nv_bfloat16* __restrict__ Bl,
        const float* __restrict__ bias, float* __restrict__ C)
{
    __shared__ char smem[4 * 8192];
    const uint32_t sb = smem_u32(smem);
    const uint32_t SA_H = 0, SA_L = 8192, SB_H = 16384, SB_L = 24576;
    const int tid = threadIdx.x;
    const int lane = tid & 31, wid = tid >> 5;
    const int wm = wid >> 2, wn = wid & 3;
    const int row0 = blockIdx.y << 7;
    const int n0 = blockIdx.x << 7;

    float acc[4][4][4];
#pragma unroll
    for (int mi = 0; mi < 4; mi++)
#pragma unroll
        for (int ni = 0; ni < 4; ni++)
#pragma unroll
            for (int t = 0; t < 4; t++) acc[mi][ni][t] = 0.f;

    const int lr = lane & 15, lc = lane >> 4;

    for (int k0 = 0; k0 < HIDN; k0 += 32) {
#pragma unroll
        for (int i = 0; i < 2; i++) {
            const int idx = tid + (i << 8);
            const int row = idx >> 2, c = idx & 3;
            const uint32_t off = swz(row, c);
            const size_t ga = (size_t)(row0 + row) * HIDN + k0 + (c << 3);
            const size_t gb = (size_t)(n0 + row) * HIDN + k0 + (c << 3);
            *(uint4*)(smem + SA_H + off) = *(const uint4*)(Ah + ga);
            *(uint4*)(smem + SA_L + off) = *(const uint4*)(Al + ga);
            *(uint4*)(smem + SB_H + off) = *(const uint4*)(Bh + gb);
            *(uint4*)(smem + SB_L + off) = *(const uint4*)(Bl + gb);
        }
        __syncthreads();
#pragma unroll
        for (int kh = 0; kh < 2; kh++) {
            const int kc = kh * 2 + lc;
            uint32_t a_h[4][4], a_l[4][4];
#pragma unroll
            for (int mi = 0; mi < 4; mi++) {
                const int r = wm * 64 + mi * 16 + lr;
                const uint32_t o = swz(r, kc);
                ldsm4(a_h[mi][0], a_h[mi][1], a_h[mi][2], a_h[mi][3], sb + SA_H + o);
                ldsm4(a_l[mi][0], a_l[mi][1], a_l[mi][2], a_l[mi][3], sb + SA_L + o);
            }
            uint32_t b_h[4][2], b_l[4][2];
#pragma unroll
            for (int np = 0; np < 2; np++) {
                const int r = wn * 32 + np * 16 + lr;
                const uint32_t o = swz(r, kc);
                uint32_t r0, r1, r2, r3;
                ldsm4(r0, r1, r2, r3, sb + SB_H + o);
                b_h[np * 2][0] = r0; b_h[np * 2 + 1][0] = r1;
                b_h[np * 2][1] = r2; b_h[np * 2 + 1][1] = r3;
                ldsm4(r0, r1, r2, r3, sb + SB_L + o);
                b_l[np * 2][0] = r0; b_l[np * 2 + 1][0] = r1;
                b_l[np * 2][1] = r2; b_l[np * 2 + 1][1] = r3;
            }
#pragma unroll
            for (int mi = 0; mi < 4; mi++)
#pragma unroll
                for (int ni = 0; ni < 4; ni++) {
                    mma16816(acc[mi][ni], a_h[mi], b_h[ni]);
                    mma16816(acc[mi][ni], a_h[mi], b_l[ni]);
                    mma16816(acc[mi][ni], a_l[mi], b_h[ni]);
                }
        }
        __syncthreads();
    }
#pragma unroll
    for (int mi = 0; mi < 4; mi++) {
        const int r = row0 + wm * 64 + mi * 16 + (lane >> 2);
#pragma unroll
        for (int ni = 0; ni < 4; ni++) {
            const int cc = n0 + wn * 32 + ni * 8 + ((lane & 3) << 1);
            const float b0 = bias[cc], b1 = bias[cc + 1];
            C[(size_t)r * HIDN + cc]           = __fadd_rn(acc[mi][ni][0], b0);
            C[(size_t)r * HIDN + cc + 1]       = __fadd_rn(acc[mi][ni][1], b1);
            C[(size_t)(r + 8) * HIDN + cc]     = __fadd_rn(acc[mi][ni][2], b0);
            C[(size_t)(r + 8) * HIDN + cc + 1] = __fadd_rn(acc[mi][ni][3], b1);
        }
    }
}

// ------------------------------------------------------------------
// Local QK^T on tensor cores: per (h, ch) chunk, scores[128 q][256 keys].
// grid (2, NHEAD*32): blockIdx.x = key half (n0 = 0/128). K = 128.
// B rows = lk split, window rows clamped (masked later in softmax).
// ------------------------------------------------------------------
__global__ void __launch_bounds__(256)
gemm_tc_qk()
{
    __shared__ char smem[4 * 8192];
    const uint32_t sb = smem_u32(smem);
    const uint32_t SA_H = 0, SA_L = 8192, SB_H = 16384, SB_L = 24576;
    const int tid = threadIdx.x;
    const int lane = tid & 31, wid = tid >> 5;
    const int wm = wid >> 2, wn = wid & 3;
    const int z = blockIdx.y;
    const int h = z >> 5, ch = z & 31;
    const int n0 = blockIdx.x << 7;
    const int b_base = (ch << 7) - 128 + n0;
    const int colA = h * DH;

    float acc[4][4][4];
#pragma unroll
    for (int mi = 0; mi < 4; mi++)
#pragma unroll
        for (int ni = 0; ni < 4; ni++)
#pragma unroll
            for (int t = 0; t < 4; t++) acc[mi][ni][t] = 0.f;

    const int lr = lane & 15, lc = lane >> 4;

    for (int k0 = 0; k0 < DH; k0 += 32) {
#pragma unroll
        for (int i = 0; i < 2; i++) {
            const int idx = tid + (i << 8);
            const int row = idx >> 2, c = idx & 3;
            const uint32_t off = swz(row, c);
            const size_t ga = (size_t)((ch << 7) + row) * HIDN + colA + k0 + (c << 3);
            int br = b_base + row; if (br < 0) br = 0;
            const size_t gb = (size_t)br * HIDN + colA + k0 + (c << 3);
            *(uint4*)(smem + SA_H + off) = *(const uint4*)(g_qh + ga);
            *(uint4*)(smem + SA_L + off) = *(const uint4*)(g_ql + ga);
            *(uint4*)(smem + SB_H + off) = *(const uint4*)(g_lkh + gb);
            *(uint4*)(smem + SB_L + off) = *(const uint4*)(g_lkl + gb);
        }
        __syncthreads();
#pragma unroll
        for (int kh = 0; kh < 2; kh++) {
            const int kc = kh * 2 + lc;
            uint32_t a_h[4][4], a_l[4][4];
#pragma unroll
            for (int mi = 0; mi < 4; mi++) {
                const int r = wm * 64 + mi * 16 + lr;
                const uint32_t o = swz(r, kc);
                ldsm4(a_h[mi][0], a_h[mi][1], a_h[mi][2], a_h[mi][3], sb + SA_H + o);
                ldsm4(a_l[mi][0], a_l[mi][1], a_l[mi][2], a_l[mi][3], sb + SA_L + o);
            }
            uint32_t b_h[4][2], b_l[4][2];
#pragma unroll
            for (int np = 0; np < 2; np++) {
                const int r = wn * 32 + np * 16 + lr;
                const uint32_t o = swz(r, kc);
                uint32_t r0, r1, r2, r3;
                ldsm4(r0, r1, r2, r3, sb + SB_H + o);
                b_h[np * 2][0] = r0; b_h[np * 2 + 1][0] = r1;
                b_h[np * 2][1] = r2; b_h[np * 2 + 1][1] = r3;
                ldsm4(r0, r1, r2, r3, sb + SB_L + o);
                b_l[np * 2][0] = r0; b_l[np * 2 + 1][0] = r1;
                b_l[np * 2][1] = r2; b_l[np * 2 + 1][1] = r3;
            }
#pragma unroll
            for (int mi = 0; mi < 4; mi++)
#pragma unroll
                for (int ni = 0; ni < 4; ni++) {
                    mma16816(acc[mi][ni], a_h[mi], b_h[ni]);
                    mma16816(acc[mi][ni], a_h[mi], b_l[ni]);
                    mma16816(acc[mi][ni], a_l[mi], b_h[ni]);
                }
        }
        __syncthreads();
    }
    float* C = g_scl + (size_t)z * 128 * 256;
#pragma unroll
    for (int mi = 0; mi < 4; mi++) {
        const int r = wm * 64 + mi * 16 + (lane >> 2);
#pragma unroll
        for (int ni = 0; ni < 4; ni++) {
            const int cc = n0 + wn * 32 + ni * 8 + ((lane & 3) << 1);
            C[(size_t)r * 256 + cc]           = __fmul_rn(acc[mi][ni][0], ATT_SCALE);
            C[(size_t)r * 256 + cc + 1]       = __fmul_rn(acc[mi][ni][1], ATT_SCALE);
            C[(size_t)(r + 8) * 256 + cc]     = __fmul_rn(acc[mi][ni][2], ATT_SCALE);
            C[(size_t)(r + 8) * 256 + cc + 1] = __fmul_rn(acc[mi][ni][3], ATT_SCALE);
        }
    }
}

// ------------------------------------------------------------------
// Local PV on tensor cores: per (h, ch): ctx[128 q][128 d] = P[128x256]@V[256x128].
// V stays [k][d] in smem; B fragments via ldmatrix.x4.trans.
// Epilogue: merged = (sparse + local) * 0.5.
// ------------------------------------------------------------------
__global__ void __launch_bounds__(256)
gemm_tc_pv()
{
    __shared__ char smem[4 * 8192];
    const uint32_t sb = smem_u32(smem);
    const uint32_t SP_H = 0, SP_L = 8192, SV_H = 16384, SV_L = 24576;
    const int tid = threadIdx.x;
    const int lane = tid & 31, wid = tid >> 5;
    const int wm = wid >> 2, wn = wid & 3;
    const int z = blockIdx.x;
    const int h = z >> 5, ch = z & 31;
    const int vbase = (ch << 7) - 128;
    const int colV = h * DH;
    const __nv_bfloat16* Ph = g_sph + (size_t)z * 128 * 256;
    const __nv_bfloat16* Pl = g_spl + (size_t)z * 128 * 256;

    float acc[4][4][4];
#pragma unroll
    for (int mi = 0; mi < 4; mi++)
#pragma unroll
        for (int ni = 0; ni < 4; ni++)
#pragma unroll
            for (int t = 0; t < 4; t++) acc[mi][ni][t] = 0.f;

    const int lr = lane & 15, lc = lane >> 4;

    for (int k0 = 0; k0 < 256; k0 += 32) {
        // stage P tiles [128 q][32 k]
#pragma unroll
        for (int i = 0; i < 2; i++) {
            const int idx = tid + (i << 8);
            const int row = idx >> 2, c = idx & 3;
            const uint32_t off = swz(row, c);
            const size_t gp = (size_t)row * 256 + k0 + (c << 3);
            *(uint4*)(smem + SP_H + off) = *(const uint4*)(Ph + gp);
            *(uint4*)(smem + SP_L + off) = *(const uint4*)(Pl + gp);
        }
        // stage V tiles [32 k][128 d]
#pragma unroll
        for (int i = 0; i < 2; i++) {
            const int idx = tid + (i << 8);
            const int row = idx >> 4, c = idx & 15;
            const uint32_t off = vswz(row, c);
            int vr = vbase + k0 + row; if (vr < 0) vr = 0;
            const size_t gv = (size_t)vr * HIDN + colV + (c << 3);
            *(uint4*)(smem + SV_H + off) = *(const uint4*)(g_lvh + gv);
            *(uint4*)(smem + SV_L + off) = *(const uint4*)(g_lvl + gv);
        }
        __syncthreads();
#pragma unroll
        for (int kh = 0; kh < 2; kh++) {
            const int kc = kh * 2 + lc;
            uint32_t a_h[4][4], a_l[4][4];
#pragma unroll
            for (int mi = 0; mi < 4; mi++) {
                const int r = wm * 64 + mi * 16 + lr;
                const uint32_t o = swz(r, kc);
                ldsm4(a_h[mi][0], a_h[mi][1], a_h[mi][2], a_h[mi][3], sb + SP_H + o);
                ldsm4(a_l[mi][0], a_l[mi][1], a_l[mi][2], a_l[mi][3], sb + SP_L + o);
            }
            // B via trans: rows = k (16), chunks = d (16B = 8 d)
            uint32_t b_h[4][2], b_l[4][2];
#pragma unroll
            for (int j = 0; j < 2; j++) {
                const int krow = kh * 16 + lr;
                const int dchunk = wn * 4 + j * 2 + lc;
                const uint32_t o = vswz(krow, dchunk);
                uint32_t r0, r1, r2, r3;
                ldsm4t(r0, r1, r2, r3, sb + SV_H + o);
                b_h[j * 2][0] = r0; b_h[j * 2][1] = r1;
                b_h[j * 2 + 1][0] = r2; b_h[j * 2 + 1][1] = r3;
                ldsm4t(r0, r1, r2, r3, sb + SV_L + o);
                b_l[j * 2][0] = r0; b_l[j * 2][1] = r1;
                b_l[j * 2 + 1][0] = r2; b_l[j * 2 + 1][1] = r3;
            }
#pragma unroll
            for (int mi = 0; mi < 4; mi++)
#pragma unroll
                for (int ni = 0; ni < 4; ni++) {
                    mma16816(acc[mi][ni], a_h[mi], b_h[ni]);
                    mma16816(acc[mi][ni], a_h[mi], b_l[ni]);
                    mma16816(acc[mi][ni], a_l[mi], b_h[ni]);
                }
        }
        __syncthreads();
    }
    // epilogue: merged = (sparse + local) * 0.5
#pragma unroll
    for (int mi = 0; mi < 4; mi++) {
        const int r = (ch << 7) + wm * 64 + mi * 16 + (lane >> 2);
#pragma unroll
        for (int ni = 0; ni < 4; ni++) {
            const int cc = colV + wn * 32 + ni * 8 + ((lane & 3) << 1);
            float* d0 = g_merged + (size_t)r * HIDN + cc;
            float* d1 = g_merged + (size_t)(r + 8) * HIDN + cc;
            d0[0] = __fmul_rn(__fadd_rn(d0[0], acc[mi][ni][0]), 0.5f);
            d0[1] = __fmul_rn(__fadd_rn(d0[1], acc[mi][ni][1]), 0.5f);
            d1[0] = __fmul_rn(__fadd_rn(d1[0], acc[mi][ni][2]), 0.5f);
            d1[1] = __fmul_rn(__fadd_rn(d1[1], acc[mi][ni][3]), 0.5f);
        }
    }
}

// split fp32 -> bf16 hi + bf16 lo (residual)
__global__ void split_plain(const float* __restrict__ src,
                            __nv_bfloat16* __restrict__ h, __nv_bfloat16* __restrict__ l,
                            int n)
{
    int i = blockIdx.x * blockDim.x + threadIdx.x;
    if (i >= n) return;
    float x = src[i];
    __nv_bfloat16 hi = __float2bfloat16(x);
    h[i] = hi;
    l[i] = __float2bfloat16(__fsub_rn(x, __bfloat162float(hi)));
}

// transpose + split: W [K=2048][N=2048] -> T{h,l} [n][k]
__global__ void tsplit(const float* __restrict__ W,
                       __nv_bfloat16* __restrict__ Th, __nv_bfloat16* __restrict__ Tl)
{
    __shared__ float tile[32][33];
    const int n0 = blockIdx.x << 5, k0 = blockIdx.y << 5;
    const int tx = threadIdx.x & 31, ty = threadIdx.x >> 5;
#pragma unroll
    for (int i = 0; i < 32; i += 8)
        tile[ty + i][tx] = W[(size_t)(k0 + ty + i) * HIDN + n0 + tx];
    __syncthreads();
#pragma unroll
    for (int i = 0; i < 32; i += 8) {
        float x = tile[tx][ty + i];
        __nv_bfloat16 hi = __float2bfloat16(x);
        size_t o = (size_t)(n0 + ty + i) * HIDN + k0 + tx;
        Th[o] = hi;
        Tl[o] = __float2bfloat16(__fsub_rn(x, __bfloat162float(hi)));
    }
}

// ------------------------------------------------------------------
// SIMT SGEMM with bias (kept for selection-critical GEMMs), K = 2048.
// ------------------------------------------------------------------
template <bool KH>
__global__ __launch_bounds__(256)
void sgemm_bias(int mode, const float* __restrict__ X,
                const float* __restrict__ W, const float* __restrict__ bias,
                float* __restrict__ outp)
{
    const float* A;
    float* C;
    int lda, ldb, ldc;
    if (mode == 0) { A = X; C = g_q; lda = HIDN; ldb = HIDN; ldc = HIDN; }
    else { A = g_entries; C = (mode == 3) ? g_ck : g_cv; lda = HIDN; ldb = DH; ldc = DH; }

    __shared__ float As[16][128];
    __shared__ float Bs[16][128];
    const int tid = threadIdx.x;
    const int row0 = blockIdx.y << 7;
    const int col0 = blockIdx.x << 7;
    const int ty = tid >> 4, tx = tid & 15;

    float acc[8][8], cmp[8][8];
#pragma unroll
    for (int i = 0; i < 8; i++)
#pragma unroll
        for (int j = 0; j < 8; j++) { acc[i][j] = 0.f; cmp[i][j] = 0.f; }

    for (int k0 = 0; k0 < HIDN; k0 += 16) {
#pragma unroll
        for (int t = 0; t < 2; t++) {
            int jj = tid + (t << 8);
            int m = jj >> 2, k4 = (jj & 3) << 2;
            float4 v = *(const float4*)(A + (size_t)(row0 + m) * lda + k0 + k4);
            As[k4 + 0][m] = v.x; As[k4 + 1][m] = v.y;
            As[k4 + 2][m] = v.z; As[k4 + 3][m] = v.w;
        }
#pragma unroll
        for (int t = 0; t < 2; t++) {
            int jj = tid + (t << 8);
            int kk = jj >> 5, n4 = (jj & 31) << 2;
            *(float4*)&Bs[kk][n4] = *(const float4*)(W + (size_t)(k0 + kk) * ldb + col0 + n4);
        }
        __syncthreads();
        if (KH) {
            float tmp[8][8];
#pragma unroll
            for (int i = 0; i < 8; i++)
#pragma unroll
                for (int j = 0; j < 8; j++) tmp[i][j] = 0.f;
#pragma unroll
            for (int kk = 0; kk < 16; kk++) {
                float ra[8], rb[8];
                *(float4*)&ra[0] = *(const float4*)&As[kk][ty << 3];
                *(float4*)&ra[4] = *(const float4*)&As[kk][(ty << 3) + 4];
                *(float4*)&rb[0] = *(const float4*)&Bs[kk][tx << 3];
                *(float4*)&rb[4] = *(const float4*)&Bs[kk][(tx << 3) + 4];
#pragma unroll
                for (int i = 0; i < 8; i++)
#pragma unroll
                    for (int j = 0; j < 8; j++)
                        tmp[i][j] = __fmaf_rn(ra[i], rb[j], tmp[i][j]);
            }
#pragma unroll
            for (int i = 0; i < 8; i++)
#pragma unroll
                for (int j = 0; j < 8; j++) {
                    float y = __fsub_rn(tmp[i][j], cmp[i][j]);
                    float t2 = __fadd_rn(acc[i][j], y);
                    cmp[i][j] = __fsub_rn(__fsub_rn(t2, acc[i][j]), y);
                    acc[i][j] = t2;
                }
        } else {
#pragma unroll
            for (int kk = 0; kk < 16; kk++) {
                float ra[8], rb[8];
                *(float4*)&ra[0] = *(const float4*)&As[kk][ty << 3];
                *(float4*)&ra[4] = *(const float4*)&As[kk][(ty << 3) + 4];
                *(float4*)&rb[0] = *(const float4*)&Bs[kk][tx << 3];
                *(float4*)&rb[4] = *(const float4*)&Bs[kk][(tx << 3) + 4];
#pragma unroll
                for (int i = 0; i < 8; i++)
#pragma unroll
                    for (int j = 0; j < 8; j++) acc[i][j] += ra[i] * rb[j];
            }
        }
        __syncthreads();
    }
#pragma unroll
    for (int i = 0; i < 8; i++) {
        size_t r = row0 + (ty << 3) + i;
#pragma unroll
        for (int j = 0; j < 8; j++) {
            int c = col0 + (tx << 3) + j;
            C[r * ldc + c] = __fadd_rn(acc[i][j], bias[c]);
        }
    }
}

// ------------------------------------------------------------------
// NT GEMM (chunked-Kahan): sc[h][s][c] = scale * q @ ck^T, K = 128.
// grid (8, 32, 16), causal tile skip. Feeds top-k: stays exact-grade.
// ------------------------------------------------------------------
__global__ __launch_bounds__(256)
void gemm_nt_scores()
{
    int h = blockIdx.z;
    int row0 = blockIdx.y << 7, col0 = blockIdx.x << 7;
    if (col0 >= (row0 >> 2) + 32) return;
    const float* A = g_q + h * DH;
    const float* B = g_ck;
    float* C = g_sc + (size_t)h * SQ * CB;

    __shared__ float As[16][128];
    __shared__ float Bs[16][128];
    const int tid = threadIdx.x;
    const int ty = tid >> 4, tx = tid & 15;

    float acc[8][8], cmp[8][8];
#pragma unroll
    for (int i = 0; i < 8; i++)
#pragma unroll
        for (int j = 0; j < 8; j++) { acc[i][j] = 0.f; cmp[i][j] = 0.f; }

    for (int k0 = 0; k0 < DH; k0 += 16) {
#pragma unroll
        for (int t = 0; t < 2; t++) {
            int jj = tid + (t << 8);
            int m = jj >> 2, k4 = (jj & 3) << 2;
            float4 v = *(const float4*)(A + (size_t)(row0 + m) * HIDN + k0 + k4);
            As[k4 + 0][m] = v.x; As[k4 + 1][m] = v.y;
            As[k4 + 2][m] = v.z; As[k4 + 3][m] = v.w;
        }
#pragma unroll
        for (int t = 0; t < 2; t++) {
            int jj = tid + (t << 8);
            int n = jj >> 2, k4 = (jj & 3) << 2;
            float4 v = *(const float4*)(B + (size_t)(col0 + n) * DH + k0 + k4);
            Bs[k4 + 0][n] = v.x; Bs[k4 + 1][n] = v.y;
            Bs[k4 + 2][n] = v.z; Bs[k4 + 3][n] = v.w;
        }
        __syncthreads();
        float tmp[8][8];
#pragma unroll
        for (int i = 0; i < 8; i++)
#pragma unroll
            for (int j = 0; j < 8; j++) tmp[i][j] = 0.f;
#pragma unroll
        for (int kk = 0; kk < 16; kk++) {
            float ra[8], rb[8];
            *(float4*)&ra[0] = *(const float4*)&As[kk][ty << 3];
            *(float4*)&ra[4] = *(const float4*)&As[kk][(ty << 3) + 4];
            *(float4*)&rb[0] = *(const float4*)&Bs[kk][tx << 3];
            *(float4*)&rb[4] = *(const float4*)&Bs[kk][(tx << 3) + 4];
#pragma unroll
            for (int i = 0; i < 8; i++)
#pragma unroll
                for (int j = 0; j < 8; j++)
                    tmp[i][j] = __fmaf_rn(ra[i], rb[j], tmp[i][j]);
        }
#pragma unroll
        for (int i = 0; i < 8; i++)
#pragma unroll
            for (int j = 0; j < 8; j++) {
                float y = __fsub_rn(tmp[i][j], cmp[i][j]);
                float t2 = __fadd_rn(acc[i][j], y);
                cmp[i][j] = __fsub_rn(__fsub_rn(t2, acc[i][j]), y);
                acc[i][j] = t2;
            }
        __syncthreads();
    }
#pragma unroll
    for (int i = 0; i < 8; i++) {
        size_t r = row0 + (ty << 3) + i;
#pragma unroll
        for (int j = 0; j < 8; j++)
            C[r * CB + col0 + (tx << 3) + j] = __fmul_rn(acc[i][j], ATT_SCALE);
    }
}

// ------------------------------------------------------------------
// rmsnorm + rope, one warp per (row, head) 128-slice, in place.
// ------------------------------------------------------------------
__global__ void norm_rope(int mode, const float* __restrict__ w)
{
    int gw = (blockIdx.x * blockDim.x + threadIdx.x) >> 5;
    int lane = threadIdx.x & 31;
    float* buf; int rows, heads, rstride, pmul, padd;
    if (mode == 0)      { buf = g_q;  rows = SQ; heads = NHEAD; rstride = HIDN; pmul = 1; padd = 0; }
    else if (mode == 1) { buf = g_lk; rows = SQ; heads = NHEAD; rstride = HIDN; pmul = 1; padd = 0; }
    else                { buf = g_ck; rows = CB; heads = 1;     rstride = DH;   pmul = 4; padd = 3; }
    if (gw >= rows * heads) return;
    int row = gw / heads, h = gw - row * heads;
    float* p = buf + (size_t)row * rstride + h * DH;
    float x0 = p[lane], x1 = p[lane + 32], x2 = p[lane + 64], x3 = p[lane + 96];
    float ss = warp_sum(x0 * x0 + x1 * x1 + x2 * x2 + x3 * x3);
    float mean = __fadd_rn(__fmul_rn(ss, 0.0078125f), 1e-6f);
    float rs = __fdiv_rn(1.0f, __fsqrt_rn(mean));          // XLA rsqrt = 1/sqrt
    x0 = __fmul_rn(__fmul_rn(x0, rs), w[lane]);
    x1 = __fmul_rn(__fmul_rn(x1, rs), w[lane + 32]);
    x2 = __fmul_rn(__fmul_rn(x2, rs), w[lane + 64]);
    x3 = __fmul_rn(__fmul_rn(x3, rs), w[lane + 96]);
    float pf = (float)pow(10000.0, (double)lane * (1.0 / 32.0));
    float invf = __fdiv_rn(1.0f, pf);
    float ang = __fmul_rn((float)(row * pmul + padd), invf);
    float c = (float)cos((double)ang);
    float s = (float)sin((double)ang);
    float n0 = __fsub_rn(__fmul_rn(x0, c), __fmul_rn(x1, s));
    float n1 = __fadd_rn(__fmul_rn(x0, s), __fmul_rn(x1, c));
    p[lane] = n0; p[lane + 32] = n1; p[lane + 64] = x2; p[lane + 96] = x3;
}

__global__ void cmp_logits(const float* __restrict__ hidden, const float* __restrict__ Wc,
                           const float* __restrict__ bc)
{
    int gw = (blockIdx.x * blockDim.x + threadIdx.x) >> 5;
    int lane = threadIdx.x & 31;
    if (gw >= SQ) return;
    const float* hr = hidden + (size_t)gw * HIDN;
    float acc = 0.f, cmp = 0.f;
    for (int k = lane; k < HIDN; k += 32) {
        float y = __fmaf_rn(hr[k], Wc[k], -cmp);
        float t = __fadd_rn(acc, y);
        cmp = __fsub_rn(__fsub_rn(t, acc), y);
        acc = t;
    }
    acc = warp_sum(acc);
    if (lane == 0) g_wlog[gw] = __fadd_rn(acc, bc[0]);
}

__global__ void entries_kernel(const float* __restrict__ hidden)
{
    int c = blockIdx.x;
    float w0 = g_wlog[c * 4 + 0], w1 = g_wlog[c * 4 + 1];
    float w2 = g_wlog[c * 4 + 2], w3 = g_wlog[c * 4 + 3];
    float m = fmaxf(fmaxf(w0, w1), fmaxf(w2, w3));
    float e0 = (float)exp((double)__fsub_rn(w0, m));
    float e1 = (float)exp((double)__fsub_rn(w1, m));
    float e2 = (float)exp((double)__fsub_rn(w2, m));
    float e3 = (float)exp((double)__fsub_rn(w3, m));
    float sum = __fadd_rn(__fadd_rn(e0, e1), __fadd_rn(e2, e3));
    e0 = __fdiv_rn(e0, sum); e1 = __fdiv_rn(e1, sum);
    e2 = __fdiv_rn(e2, sum); e3 = __fdiv_rn(e3, sum);
    const float* h0 = hidden + (size_t)c * 4 * HIDN;
    float* dst = g_entries + (size_t)c * HIDN;
    for (int j = threadIdx.x; j < HIDN; j += blockDim.x)
        dst[j] = e0 * h0[j] + e1 * h0[HIDN + j] + e2 * h0[2 * HIDN + j] + e3 * h0[3 * HIDN + j];
}

// ------------------------------------------------------------------
// top-8 over causal prefix + softmax + gather cv; writes 1.0*ctx_sparse
// ------------------------------------------------------------------
__global__ void topk_sparse()
{
    int gw = (blockIdx.x * blockDim.x + threadIdx.x) >> 5;
    int lane = threadIdx.x & 31;
    if (gw >= NHEAD * SQ) return;
    int h = gw >> 12;
    int s = gw & (SQ - 1);
    int nc = (s + 1) >> 2;
    const float* row = g_sc + ((size_t)h * SQ + s) * CB;

    float bv[8]; int bi[8];
#pragma unroll
    for (int i = 0; i < 8; i++) { bv[i] = NEGV; bi[i] = -1; }
    for (int c = lane; c < nc; c += 32) {
        float v = row[c];
        if (v > bv[7]) {
            bv[7] = v; bi[7] = c;
#pragma unroll
            for (int j = 7; j > 0; j--) {
                if (bv[j] > bv[j - 1]) {
                    float tv = bv[j]; bv[j] = bv[j - 1]; bv[j - 1] = tv;
                    int txx = bi[j]; bi[j] = bi[j - 1]; bi[j - 1] = txx;
                }
            }
        }
    }
    int ptr = 0;
    float tvv[8]; int tii[8];
#pragma unroll
    for (int t = 0; t < 8; t++) {
        float m = (ptr < 8) ? bv[ptr] : NEGV;
        int mi = (ptr < 8) ? bi[ptr] : 0x7fffffff;
#pragma unroll
        for (int o = 16; o; o >>= 1) {
            float om = __shfl_xor_sync(0xffffffffu, m, o);
            int oi = __shfl_xor_sync(0xffffffffu, mi, o);
            if (om > m || (om == m && oi < mi)) { m = om; mi = oi; }
        }
        tvv[t] = m; tii[t] = mi;
        if (ptr < 8 && bv[ptr] == m && bi[ptr] == mi) ptr++;
    }
    float m0 = tvv[0];
    float e[8]; float sum = 0.f;
#pragma unroll
    for (int t = 0; t < 8; t++) {
        e[t] = (tvv[t] > NEGH) ? (float)exp((double)__fsub_rn(tvv[t], m0)) : 0.f;
        sum += e[t];
    }
    float den = fmaxf(sum, 1e-9f);
    float c0 = 0.f, c1 = 0.f, c2 = 0.f, c3 = 0.f;
#pragma unroll
    for (int t = 0; t < 8; t++) {
        float wgt = __fdiv_rn(e[t], den);
        if (wgt > 0.f) {
            const float* vr = g_cv + (size_t)tii[t] * DH;
            c0 += wgt * vr[lane];      c1 += wgt * vr[lane + 32];
            c2 += wgt * vr[lane + 64]; c3 += wgt * vr[lane + 96];
        }
    }
    float* dst = g_merged + (size_t)s * HIDN + h * DH;
    dst[lane] = c0;      dst[lane + 32] = c1;
    dst[lane + 64] = c2; dst[lane + 96] = c3;
}

// masked softmax over 256 local keys; writes bf16 split probs (0 where masked)
__global__ void local_softmax()
{
    int gw = (blockIdx.x * blockDim.x + threadIdx.x) >> 5;
    int lane = threadIdx.x & 31;
    if (gw >= NHEAD * 32 * 128) return;
    int qi = gw & 127;
    int ch = (gw >> 7) & 31;
    const float* rowp = g_scl + (size_t)gw * 256;
    __nv_bfloat16* oh = g_sph + (size_t)gw * 256;
    __nv_bfloat16* ol = g_spl + (size_t)gw * 256;
    int lo = (ch == 0) ? 128 : qi;
    int hi = qi + 128;
    float v[8];
    float m = NEGV;
#pragma unroll
    for (int t = 0; t < 8; t++) {
        int j = lane + (t << 5);
        bool ok = (j >= lo) && (j <= hi);
        v[t] = ok ? rowp[j] : NEGV;
        m = fmaxf(m, v[t]);
    }
    m = warp_max(m);
    float e[8]; float sum = 0.f;
#pragma unroll
    for (int t = 0; t < 8; t++) {
        int j = lane + (t << 5);
        bool ok = (j >= lo) && (j <= hi);
        e[t] = ok ? (float)exp((double)__fsub_rn(v[t], m)) : 0.f;
        sum += e[t];
    }
    sum = warp_sum(sum);
#pragma unroll
    for (int t = 0; t < 8; t++) {
        float p = __fdiv_rn(e[t], sum);
        __nv_bfloat16 hh = __float2bfloat16(p);
        oh[lane + (t << 5)] = hh;
        ol[lane + (t << 5)] = __float2bfloat16(__fsub_rn(p, __bfloat162float(hh)));
    }
}

// ------------------------------------------------------------------
extern "C" void kernel_launch(void* const* d_in, const int* in_sizes, int n_in,
                              void* d_out, int out_size)
{
    const float* hidden = (const float*)d_in[0];
    const float* Wq   = (const float*)d_in[1];
    const float* bq   = (const float*)d_in[2];
    const float* Wcmp = (const float*)d_in[3];
    const float* bcmp = (const float*)d_in[4];
    const float* Wk   = (const float*)d_in[5];
    const float* bk   = (const float*)d_in[6];
    const float* Wv   = (const float*)d_in[7];
    const float* bvv  = (const float*)d_in[8];
    const float* Wlk  = (const float*)d_in[9];
    const float* blkb = (const float*)d_in[10];
    const float* Wlv  = (const float*)d_in[11];
    const float* blvb = (const float*)d_in[12];
    const float* qnw  = (const float*)d_in[13];
    const float* knw  = (const float*)d_in[14];
    const float* Wo   = (const float*)d_in[15];
    const float* bo   = (const float*)d_in[16];
    float* out = (float*)d_out;

    static __nv_bfloat16 *hid_h = nullptr, *hid_l, *mrg_h, *mrg_l,
                         *wlk_h, *wlk_l, *wlv_h, *wlv_l, *wo_h, *wo_l,
                         *qh, *ql, *lkh, *lkl, *lvh, *lvl;
    static float *p_q = nullptr, *p_lk, *p_lv, *p_merged;
    if (!hid_h) {
        cudaGetSymbolAddress((void**)&hid_h, g_hid_h);
        cudaGetSymbolAddress((void**)&hid_l, g_hid_l);
        cudaGetSymbolAddress((void**)&mrg_h, g_mrg_h);
        cudaGetSymbolAddress((void**)&mrg_l, g_mrg_l);
        cudaGetSymbolAddress((void**)&wlk_h, g_wlk_h);
        cudaGetSymbolAddress((void**)&wlk_l, g_wlk_l);
        cudaGetSymbolAddress((void**)&wlv_h, g_wlv_h);
        cudaGetSymbolAddress((void**)&wlv_l, g_wlv_l);
        cudaGetSymbolAddress((void**)&wo_h, g_wo_h);
        cudaGetSymbolAddress((void**)&wo_l, g_wo_l);
        cudaGetSymbolAddress((void**)&qh, g_qh);
        cudaGetSymbolAddress((void**)&ql, g_ql);
        cudaGetSymbolAddress((void**)&lkh, g_lkh);
        cudaGetSymbolAddress((void**)&lkl, g_lkl);
        cudaGetSymbolAddress((void**)&lvh, g_lvh);
        cudaGetSymbolAddress((void**)&lvl, g_lvl);
        cudaGetSymbolAddress((void**)&p_q, g_q);
        cudaGetSymbolAddress((void**)&p_lk, g_lk);
        cudaGetSymbolAddress((void**)&p_lv, g_lv);
        cudaGetSymbolAddress((void**)&p_merged, g_merged);
    }

    dim3 thr(256);
    const int NELT = SQ * HIDN;

    // splits of inputs/weights
    split_plain<<<(NELT + 255) / 256, 256>>>(hidden, hid_h, hid_l, NELT);
    tsplit<<<dim3(64, 64), 256>>>(Wlk, wlk_h, wlk_l);
    tsplit<<<dim3(64, 64), 256>>>(Wlv, wlv_h, wlv_l);
    tsplit<<<dim3(64, 64), 256>>>(Wo,  wo_h,  wo_l);

    // selection-critical projection (chunked-Kahan SIMT)
    sgemm_bias<true><<<dim3(HIDN / 128, SQ / 128), thr>>>(0, hidden, Wq, bq, nullptr);

    // smooth projections on tensor cores (mma.sync bf16x3)
    gemm_tc<<<dim3(HIDN / 128, SQ / 128), 256>>>(hid_h, hid_l, wlk_h, wlk_l, blkb, p_lk);
    gemm_tc<<<dim3(HIDN / 128, SQ / 128), 256>>>(hid_h, hid_l, wlv_h, wlv_l, blvb, p_lv);

    cmp_logits<<<SQ / 8, 256>>>(hidden, Wcmp, bcmp);
    entries_kernel<<<CB, 256>>>(hidden);

    sgemm_bias<true ><<<dim3(1, CB / 128), thr>>>(3, nullptr, Wk, bk,  nullptr); // feeds top-k
    sgemm_bias<false><<<dim3(1, CB / 128), thr>>>(4, nullptr, Wv, bvv, nullptr);

    norm_rope<<<(SQ * NHEAD) / 8, 256>>>(0, qnw);
    norm_rope<<<(SQ * NHEAD) / 8, 256>>>(1, knw);
    norm_rope<<<CB / 8, 256>>>(2, knw);

    // bf16 splits for local attention (post norm/rope)
    split_plain<<<(NELT + 255) / 256, 256>>>(p_q,  qh,  ql,  NELT);
    split_plain<<<(NELT + 255) / 256, 256>>>(p_lk, lkh, lkl, NELT);
    split_plain<<<(NELT + 255) / 256, 256>>>(p_lv, lvh, lvl, NELT);

    gemm_nt_scores<<<dim3(CB / 128, SQ / 128, NHEAD), thr>>>(); // feeds top-k (Kahan)
    topk_sparse<<<(NHEAD * SQ) / 8, 256>>>();

    // local attention on tensor cores
    gemm_tc_qk<<<dim3(2, NHEAD * 32), 256>>>();
    local_softmax<<<(NHEAD * 32 * 128) / 8, 256>>>();
    gemm_tc_pv<<<NHEAD * 32, 256>>>();

    // output projection on tensor cores
    split_plain<<<(NELT + 255) / 256, 256>>>(p_merged, mrg_h, mrg_l, NELT);
    gemm_tc<<<dim3(HIDN / 128, SQ / 128), 256>>>(mrg_h, mrg_l, wo_h, wo_l, bo, out);
}

// round 11
// speedup vs baseline: 1.7736x; 1.0798x over previous
#include <cuda_runtime.h>
#include <cuda_bf16.h>
#include <math.h>
#include <stdint.h>

#define SQ 4096
#define HIDN 2048
#define NHEAD 16
#define DH 128
#define CB 1024
#define NEGV -1e30f
#define NEGH -5e29f
#define ATT_SCALE 0.08838834764831845f

// ------------- scratch (static __device__ globals; allocation-free) -------------
__device__ float g_q[(size_t)SQ * HIDN];
__device__ float g_lk[(size_t)SQ * HIDN];
__device__ float g_lv[(size_t)SQ * HIDN];
__device__ float g_wlog[SQ];
__device__ float g_entries[(size_t)CB * HIDN];
__device__ float g_ck[CB * DH];
__device__ float g_cv[CB * DH];
__device__ float g_merged[(size_t)SQ * HIDN];
__device__ float g_sc[(size_t)NHEAD * SQ * CB];
__device__ float g_scl[(size_t)NHEAD * 32 * 128 * 256];

// bf16 split buffers
__device__ __nv_bfloat16 g_hid_h[(size_t)SQ * HIDN];
__device__ __nv_bfloat16 g_hid_l[(size_t)SQ * HIDN];
__device__ __nv_bfloat16 g_hid_m[(size_t)SQ * HIDN];
__device__ __nv_bfloat16 g_mrg_h[(size_t)SQ * HIDN];
__device__ __nv_bfloat16 g_mrg_l[(size_t)SQ * HIDN];
__device__ __nv_bfloat16 g_qh[(size_t)SQ * HIDN];
__device__ __nv_bfloat16 g_ql[(size_t)SQ * HIDN];
__device__ __nv_bfloat16 g_qm[(size_t)SQ * HIDN];
__device__ __nv_bfloat16 g_lkh[(size_t)SQ * HIDN];
__device__ __nv_bfloat16 g_lkl[(size_t)SQ * HIDN];
__device__ __nv_bfloat16 g_lvh[(size_t)SQ * HIDN];
__device__ __nv_bfloat16 g_lvl[(size_t)SQ * HIDN];
__device__ __nv_bfloat16 g_ck1[CB * DH];
__device__ __nv_bfloat16 g_ck2[CB * DH];
__device__ __nv_bfloat16 g_ck3[CB * DH];
__device__ __nv_bfloat16 g_sph[(size_t)NHEAD * 32 * 128 * 256];
__device__ __nv_bfloat16 g_spl[(size_t)NHEAD * 32 * 128 * 256];
__device__ __nv_bfloat16 g_wq1[(size_t)HIDN * HIDN];
__device__ __nv_bfloat16 g_wq2[(size_t)HIDN * HIDN];
__device__ __nv_bfloat16 g_wq3[(size_t)HIDN * HIDN];
__device__ __nv_bfloat16 g_wlk_h[(size_t)HIDN * HIDN];
__device__ __nv_bfloat16 g_wlk_l[(size_t)HIDN * HIDN];
__device__ __nv_bfloat16 g_wlv_h[(size_t)HIDN * HIDN];
__device__ __nv_bfloat16 g_wlv_l[(size_t)HIDN * HIDN];
__device__ __nv_bfloat16 g_wo_h[(size_t)HIDN * HIDN];
__device__ __nv_bfloat16 g_wo_l[(size_t)HIDN * HIDN];

__device__ __forceinline__ float warp_sum(float v) {
#pragma unroll
    for (int o = 16; o; o >>= 1) v += __shfl_xor_sync(0xffffffffu, v, o);
    return v;
}
__device__ __forceinline__ float warp_max(float v) {
#pragma unroll
    for (int o = 16; o; o >>= 1) v = fmaxf(v, __shfl_xor_sync(0xffffffffu, v, o));
    return v;
}

// ======================= mma.sync helpers (base PTX, sm_80+) =======================
__device__ __forceinline__ uint32_t smem_u32(const void* p) {
    uint32_t a;
    asm("{ .reg .u64 t; cvta.to.shared.u64 t, %1; cvt.u32.u64 %0, t; }" : "=r"(a) : "l"(p));
    return a;
}
__device__ __forceinline__ void ldsm4(uint32_t& r0, uint32_t& r1, uint32_t& r2, uint32_t& r3,
                                      uint32_t addr) {
    asm volatile("ldmatrix.sync.aligned.m8n8.x4.shared.b16 {%0,%1,%2,%3}, [%4];"
                 : "=r"(r0), "=r"(r1), "=r"(r2), "=r"(r3) : "r"(addr));
}
__device__ __forceinline__ void ldsm4t(uint32_t& r0, uint32_t& r1, uint32_t& r2, uint32_t& r3,
                                       uint32_t addr) {
    asm volatile("ldmatrix.sync.aligned.m8n8.x4.trans.shared.b16 {%0,%1,%2,%3}, [%4];"
                 : "=r"(r0), "=r"(r1), "=r"(r2), "=r"(r3) : "r"(addr));
}
__device__ __forceinline__ void mma16816(float* d, const uint32_t* a, const uint32_t* b) {
    asm volatile(
        "mma.sync.aligned.m16n8k16.row.col.f32.bf16.bf16.f32 "
        "{%0,%1,%2,%3}, {%4,%5,%6,%7}, {%8,%9}, {%0,%1,%2,%3};"
        : "+f"(d[0]), "+f"(d[1]), "+f"(d[2]), "+f"(d[3])
        : "r"(a[0]), "r"(a[1]), "r"(a[2]), "r"(a[3]), "r"(b[0]), "r"(b[1]));
}
__device__ __forceinline__ uint32_t swz(int row, int c) {
    int slot = (((row & 1) << 2) | c) ^ ((row >> 1) & 7);
    return (uint32_t)(((row >> 1) << 7) + (slot << 4));
}
__device__ __forceinline__ uint32_t vswz(int row, int c) {
    return (uint32_t)((row << 8) + ((c ^ (row & 7)) << 4));
}

// ------------------------------------------------------------------
// Selection-grade TC GEMM: bf16 tri-split 6-pass + per-K-tile Kahan fold
// of the fp32 accumulator (chain noise ~2^-24*sqrt(12) ~ 2e-7).
// Block 128(m) x 64(n), 8 warps (2m x 4n), warp tile 64x16, K-step 32.
// C = A@B^T (+bias | *scale). causal: tile skip for compressed scores.
// ------------------------------------------------------------------
__global__ void __launch_bounds__(256)
gemm_tc6k(const __nv_bfloat16* __restrict__ A1, const __nv_bfloat16* __restrict__ A2,
          const __nv_bfloat16* __restrict__ A3,
          const __nv_bfloat16* __restrict__ B1, const __nv_bfloat16* __restrict__ B2,
          const __nv_bfloat16* __restrict__ B3,
          const float* __restrict__ bias, float* __restrict__ C,
          int lda, int ldb, int ldc, int K,
          size_t a_zoff, size_t c_zoff, float scale, int causal)
{
    const int row0 = blockIdx.y << 7;
    const int n0 = blockIdx.x << 6;
    if (causal && n0 >= (row0 >> 2) + 32) return;
    A1 += blockIdx.z * a_zoff; A2 += blockIdx.z * a_zoff; A3 += blockIdx.z * a_zoff;
    C += blockIdx.z * c_zoff;

    __shared__ char smem[3 * 8192 + 3 * 4096];   // A1|A2|A3 [128][32], B1|B2|B3 [64][32]
    const uint32_t sb = smem_u32(smem);
    const uint32_t OB1 = 24576, OB2 = 28672, OB3 = 32768;
    const int tid = threadIdx.x;
    const int lane = tid & 31, wid = tid >> 5;
    const int wm = wid >> 2, wn = wid & 3;

    float acc[4][2][4], cmp[4][2][4];
#pragma unroll
    for (int mi = 0; mi < 4; mi++)
#pragma unroll
        for (int ni = 0; ni < 2; ni++)
#pragma unroll
            for (int t = 0; t < 4; t++) { acc[mi][ni][t] = 0.f; cmp[mi][ni][t] = 0.f; }

    const int lr = lane & 15, lc = lane >> 4;

    for (int k0 = 0; k0 < K; k0 += 32) {
        // stage A tiles: 512 16B chunks, 2 per thread
#pragma unroll
        for (int i = 0; i < 2; i++) {
            const int idx = tid + (i << 8);
            const int row = idx >> 2, c = idx & 3;
            const uint32_t off = swz(row, c);
            const size_t ga = (size_t)(row0 + row) * lda + k0 + (c << 3);
            *(uint4*)(smem + 0     + off) = *(const uint4*)(A1 + ga);
            *(uint4*)(smem + 8192  + off) = *(const uint4*)(A2 + ga);
            *(uint4*)(smem + 16384 + off) = *(const uint4*)(A3 + ga);
        }
        // stage B tiles: 256 chunks, 1 per thread
        {
            const int row = tid >> 2, c = tid & 3;
            const uint32_t off = swz(row, c);
            const size_t gb = (size_t)(n0 + row) * ldb + k0 + (c << 3);
            *(uint4*)(smem + OB1 + off) = *(const uint4*)(B1 + gb);
            *(uint4*)(smem + OB2 + off) = *(const uint4*)(B2 + gb);
            *(uint4*)(smem + OB3 + off) = *(const uint4*)(B3 + gb);
        }
        __syncthreads();

        float tmp[4][2][4];
#pragma unroll
        for (int mi = 0; mi < 4; mi++)
#pragma unroll
            for (int ni = 0; ni < 2; ni++)
#pragma unroll
                for (int t = 0; t < 4; t++) tmp[mi][ni][t] = 0.f;

#pragma unroll
        for (int kh = 0; kh < 2; kh++) {
            const int kc = kh * 2 + lc;
            uint32_t a1[4][4], a2[4][4], a3[4][4];
#pragma unroll
            for (int mi = 0; mi < 4; mi++) {
                const int r = wm * 64 + mi * 16 + lr;
                const uint32_t o = swz(r, kc);
                ldsm4(a1[mi][0], a1[mi][1], a1[mi][2], a1[mi][3], sb + 0 + o);
                ldsm4(a2[mi][0], a2[mi][1], a2[mi][2], a2[mi][3], sb + 8192 + o);
                ldsm4(a3[mi][0], a3[mi][1], a3[mi][2], a3[mi][3], sb + 16384 + o);
            }
            uint32_t b1[2][2], b2[2][2], b3[2][2];
            {
                const int r = wn * 16 + lr;
                const uint32_t o = swz(r, kc);
                uint32_t r0, r1, r2, r3;
                ldsm4(r0, r1, r2, r3, sb + OB1 + o);
                b1[0][0] = r0; b1[1][0] = r1; b1[0][1] = r2; b1[1][1] = r3;
                ldsm4(r0, r1, r2, r3, sb + OB2 + o);
                b2[0][0] = r0; b2[1][0] = r1; b2[0][1] = r2; b2[1][1] = r3;
                ldsm4(r0, r1, r2, r3, sb + OB3 + o);
                b3[0][0] = r0; b3[1][0] = r1; b3[0][1] = r2; b3[1][1] = r3;
            }
#pragma unroll
            for (int mi = 0; mi < 4; mi++)
#pragma unroll
                for (int ni = 0; ni < 2; ni++) {
                    mma16816(tmp[mi][ni], a1[mi], b1[ni]);
                    mma16816(tmp[mi][ni], a1[mi], b2[ni]);
                    mma16816(tmp[mi][ni], a2[mi], b1[ni]);
                    mma16816(tmp[mi][ni], a2[mi], b2[ni]);
                    mma16816(tmp[mi][ni], a1[mi], b3[ni]);
                    mma16816(tmp[mi][ni], a3[mi], b1[ni]);
                }
        }
        // exact Kahan fold of the K-tile partial
#pragma unroll
        for (int mi = 0; mi < 4; mi++)
#pragma unroll
            for (int ni = 0; ni < 2; ni++)
#pragma unroll
                for (int t = 0; t < 4; t++) {
                    float y = __fsub_rn(tmp[mi][ni][t], cmp[mi][ni][t]);
                    float t2 = __fadd_rn(acc[mi][ni][t], y);
                    cmp[mi][ni][t] = __fsub_rn(__fsub_rn(t2, acc[mi][ni][t]), y);
                    acc[mi][ni][t] = t2;
                }
        __syncthreads();
    }
#pragma unroll
    for (int mi = 0; mi < 4; mi++) {
        const int r = row0 + wm * 64 + mi * 16 + (lane >> 2);
#pragma unroll
        for (int ni = 0; ni < 2; ni++) {
            const int cc = n0 + wn * 16 + ni * 8 + ((lane & 3) << 1);
            if (bias) {
                const float b0 = bias[cc], b1v = bias[cc + 1];
                C[(size_t)r * ldc + cc]           = __fadd_rn(acc[mi][ni][0], b0);
                C[(size_t)r * ldc + cc + 1]       = __fadd_rn(acc[mi][ni][1], b1v);
                C[(size_t)(r + 8) * ldc + cc]     = __fadd_rn(acc[mi][ni][2], b0);
                C[(size_t)(r + 8) * ldc + cc + 1] = __fadd_rn(acc[mi][ni][3], b1v);
            } else {
                C[(size_t)r * ldc + cc]           = __fmul_rn(acc[mi][ni][0], scale);
                C[(size_t)r * ldc + cc + 1]       = __fmul_rn(acc[mi][ni][1], scale);
                C[(size_t)(r + 8) * ldc + cc]     = __fmul_rn(acc[mi][ni][2], scale);
                C[(size_t)(r + 8) * ldc + cc + 1] = __fmul_rn(acc[mi][ni][3], scale);
            }
        }
    }
}

// ------------------------------------------------------------------
// Smooth tensor GEMM bf16x3: C = A @ W + bias. Block 128x128.
// ------------------------------------------------------------------
__global__ void __launch_bounds__(256)
gemm_tc(const __nv_bfloat16* __restrict__ Ah, const __nv_bfloat16* __restrict__ Al,
        const __nv_bfloat16* __restrict__ Bh, const __nv_bfloat16* __restrict__ Bl,
        const float* __restrict__ bias, float* __restrict__ C)
{
    __shared__ char smem[4 * 8192];
    const uint32_t sb = smem_u32(smem);
    const uint32_t SA_H = 0, SA_L = 8192, SB_H = 16384, SB_L = 24576;
    const int tid = threadIdx.x;
    const int lane = tid & 31, wid = tid >> 5;
    const int wm = wid >> 2, wn = wid & 3;
    const int row0 = blockIdx.y << 7;
    const int n0 = blockIdx.x << 7;

    float acc[4][4][4];
#pragma unroll
    for (int mi = 0; mi < 4; mi++)
#pragma unroll
        for (int ni = 0; ni < 4; ni++)
#pragma unroll
            for (int t = 0; t < 4; t++) acc[mi][ni][t] = 0.f;

    const int lr = lane & 15, lc = lane >> 4;

    for (int k0 = 0; k0 < HIDN; k0 += 32) {
#pragma unroll
        for (int i = 0; i < 2; i++) {
            const int idx = tid + (i << 8);
            const int row = idx >> 2, c = idx & 3;
            const uint32_t off = swz(row, c);
            const size_t ga = (size_t)(row0 + row) * HIDN + k0 + (c << 3);
            const size_t gb = (size_t)(n0 + row) * HIDN + k0 + (c << 3);
            *(uint4*)(smem + SA_H + off) = *(const uint4*)(Ah + ga);
            *(uint4*)(smem + SA_L + off) = *(const uint4*)(Al + ga);
            *(uint4*)(smem + SB_H + off) = *(const uint4*)(Bh + gb);
            *(uint4*)(smem + SB_L + off) = *(const uint4*)(Bl + gb);
        }
        __syncthreads();
#pragma unroll
        for (int kh = 0; kh < 2; kh++) {
            const int kc = kh * 2 + lc;
            uint32_t a_h[4][4], a_l[4][4];
#pragma unroll
            for (int mi = 0; mi < 4; mi++) {
                const int r = wm * 64 + mi * 16 + lr;
                const uint32_t o = swz(r, kc);
                ldsm4(a_h[mi][0], a_h[mi][1], a_h[mi][2], a_h[mi][3], sb + SA_H + o);
                ldsm4(a_l[mi][0], a_l[mi][1], a_l[mi][2], a_l[mi][3], sb + SA_L + o);
            }
            uint32_t b_h[4][2], b_l[4][2];
#pragma unroll
            for (int np = 0; np < 2; np++) {
                const int r = wn * 32 + np * 16 + lr;
                const uint32_t o = swz(r, kc);
                uint32_t r0, r1, r2, r3;
                ldsm4(r0, r1, r2, r3, sb + SB_H + o);
                b_h[np * 2][0] = r0; b_h[np * 2 + 1][0] = r1;
                b_h[np * 2][1] = r2; b_h[np * 2 + 1][1] = r3;
                ldsm4(r0, r1, r2, r3, sb + SB_L + o);
                b_l[np * 2][0] = r0; b_l[np * 2 + 1][0] = r1;
                b_l[np * 2][1] = r2; b_l[np * 2 + 1][1] = r3;
            }
#pragma unroll
            for (int mi = 0; mi < 4; mi++)
#pragma unroll
                for (int ni = 0; ni < 4; ni++) {
                    mma16816(acc[mi][ni], a_h[mi], b_h[ni]);
                    mma16816(acc[mi][ni], a_h[mi], b_l[ni]);
                    mma16816(acc[mi][ni], a_l[mi], b_h[ni]);
                }
        }
        __syncthreads();
    }
#pragma unroll
    for (int mi = 0; mi < 4; mi++) {
        const int r = row0 + wm * 64 + mi * 16 + (lane >> 2);
#pragma unroll
        for (int ni = 0; ni < 4; ni++) {
            const int cc = n0 + wn * 32 + ni * 8 + ((lane & 3) << 1);
            const float b0 = bias[cc], b1 = bias[cc + 1];
            C[(size_t)r * HIDN + cc]           = __fadd_rn(acc[mi][ni][0], b0);
            C[(size_t)r * HIDN + cc + 1]       = __fadd_rn(acc[mi][ni][1], b1);
            C[(size_t)(r + 8) * HIDN + cc]     = __fadd_rn(acc[mi][ni][2], b0);
            C[(size_t)(r + 8) * HIDN + cc + 1] = __fadd_rn(acc[mi][ni][3], b1);
        }
    }
}

// ------------------------------------------------------------------
// Local QK^T: per (h, ch), scores[128 q][256 keys].
// ------------------------------------------------------------------
__global__ void __launch_bounds__(256)
gemm_tc_qk()
{
    __shared__ char smem[4 * 8192];
    const uint32_t sb = smem_u32(smem);
    const uint32_t SA_H = 0, SA_L = 8192, SB_H = 16384, SB_L = 24576;
    const int tid = threadIdx.x;
    const int lane = tid & 31, wid = tid >> 5;
    const int wm = wid >> 2, wn = wid & 3;
    const int z = blockIdx.y;
    const int h = z >> 5, ch = z & 31;
    const int n0 = blockIdx.x << 7;
    const int b_base = (ch << 7) - 128 + n0;
    const int colA = h * DH;

    float acc[4][4][4];
#pragma unroll
    for (int mi = 0; mi < 4; mi++)
#pragma unroll
        for (int ni = 0; ni < 4; ni++)
#pragma unroll
            for (int t = 0; t < 4; t++) acc[mi][ni][t] = 0.f;

    const int lr = lane & 15, lc = lane >> 4;

    for (int k0 = 0; k0 < DH; k0 += 32) {
#pragma unroll
        for (int i = 0; i < 2; i++) {
            const int idx = tid + (i << 8);
            const int row = idx >> 2, c = idx & 3;
            const uint32_t off = swz(row, c);
            const size_t ga = (size_t)((ch << 7) + row) * HIDN + colA + k0 + (c << 3);
            int br = b_base + row; if (br < 0) br = 0;
            const size_t gb = (size_t)br * HIDN + colA + k0 + (c << 3);
            *(uint4*)(smem + SA_H + off) = *(const uint4*)(g_qh + ga);
            *(uint4*)(smem + SA_L + off) = *(const uint4*)(g_ql + ga);
            *(uint4*)(smem + SB_H + off) = *(const uint4*)(g_lkh + gb);
            *(uint4*)(smem + SB_L + off) = *(const uint4*)(g_lkl + gb);
        }
        __syncthreads();
#pragma unroll
        for (int kh = 0; kh < 2; kh++) {
            const int kc = kh * 2 + lc;
            uint32_t a_h[4][4], a_l[4][4];
#pragma unroll
            for (int mi = 0; mi < 4; mi++) {
                const int r = wm * 64 + mi * 16 + lr;
                const uint32_t o = swz(r, kc);
                ldsm4(a_h[mi][0], a_h[mi][1], a_h[mi][2], a_h[mi][3], sb + SA_H + o);
                ldsm4(a_l[mi][0], a_l[mi][1], a_l[mi][2], a_l[mi][3], sb + SA_L + o);
            }
            uint32_t b_h[4][2], b_l[4][2];
#pragma unroll
            for (int np = 0; np < 2; np++) {
                const int r = wn * 32 + np * 16 + lr;
                const uint32_t o = swz(r, kc);
                uint32_t r0, r1, r2, r3;
                ldsm4(r0, r1, r2, r3, sb + SB_H + o);
                b_h[np * 2][0] = r0; b_h[np * 2 + 1][0] = r1;
                b_h[np * 2][1] = r2; b_h[np * 2 + 1][1] = r3;
                ldsm4(r0, r1, r2, r3, sb + SB_L + o);
                b_l[np * 2][0] = r0; b_l[np * 2 + 1][0] = r1;
                b_l[np * 2][1] = r2; b_l[np * 2 + 1][1] = r3;
            }
#pragma unroll
            for (int mi = 0; mi < 4; mi++)
#pragma unroll
                for (int ni = 0; ni < 4; ni++) {
                    mma16816(acc[mi][ni], a_h[mi], b_h[ni]);
                    mma16816(acc[mi][ni], a_h[mi], b_l[ni]);
                    mma16816(acc[mi][ni], a_l[mi], b_h[ni]);
                }
        }
        __syncthreads();
    }
    float* C = g_scl + (size_t)z * 128 * 256;
#pragma unroll
    for (int mi = 0; mi < 4; mi++) {
        const int r = wm * 64 + mi * 16 + (lane >> 2);
#pragma unroll
        for (int ni = 0; ni < 4; ni++) {
            const int cc = n0 + wn * 32 + ni * 8 + ((lane & 3) << 1);
            C[(size_t)r * 256 + cc]           = __fmul_rn(acc[mi][ni][0], ATT_SCALE);
            C[(size_t)r * 256 + cc + 1]       = __fmul_rn(acc[mi][ni][1], ATT_SCALE);
            C[(size_t)(r + 8) * 256 + cc]     = __fmul_rn(acc[mi][ni][2], ATT_SCALE);
            C[(size_t)(r + 8) * 256 + cc + 1] = __fmul_rn(acc[mi][ni][3], ATT_SCALE);
        }
    }
}

// ------------------------------------------------------------------
// Local PV: ctx = P[128x256]@V[256x128], merged epilogue.
// ------------------------------------------------------------------
__global__ void __launch_bounds__(256)
gemm_tc_pv()
{
    __shared__ char smem[4 * 8192];
    const uint32_t sb = smem_u32(smem);
    const uint32_t SP_H = 0, SP_L = 8192, SV_H = 16384, SV_L = 24576;
    const int tid = threadIdx.x;
    const int lane = tid & 31, wid = tid >> 5;
    const int wm = wid >> 2, wn = wid & 3;
    const int z = blockIdx.x;
    const int h = z >> 5, ch = z & 31;
    const int vbase = (ch << 7) - 128;
    const int colV = h * DH;
    const __nv_bfloat16* Ph = g_sph + (size_t)z * 128 * 256;
    const __nv_bfloat16* Pl = g_spl + (size_t)z * 128 * 256;

    float acc[4][4][4];
#pragma unroll
    for (int mi = 0; mi < 4; mi++)
#pragma unroll
        for (int ni = 0; ni < 4; ni++)
#pragma unroll
            for (int t = 0; t < 4; t++) acc[mi][ni][t] = 0.f;

    const int lr = lane & 15, lc = lane >> 4;

    for (int k0 = 0; k0 < 256; k0 += 32) {
#pragma unroll
        for (int i = 0; i < 2; i++) {
            const int idx = tid + (i << 8);
            const int row = idx >> 2, c = idx & 3;
            const uint32_t off = swz(row, c);
            const size_t gp = (size_t)row * 256 + k0 + (c << 3);
            *(uint4*)(smem + SP_H + off) = *(const uint4*)(Ph + gp);
            *(uint4*)(smem + SP_L + off) = *(const uint4*)(Pl + gp);
        }
#pragma unroll
        for (int i = 0; i < 2; i++) {
            const int idx = tid + (i << 8);
            const int row = idx >> 4, c = idx & 15;
            const uint32_t off = vswz(row, c);
            int vr = vbase + k0 + row; if (vr < 0) vr = 0;
            const size_t gv = (size_t)vr * HIDN + colV + (c << 3);
            *(uint4*)(smem + SV_H + off) = *(const uint4*)(g_lvh + gv);
            *(uint4*)(smem + SV_L + off) = *(const uint4*)(g_lvl + gv);
        }
        __syncthreads();
#pragma unroll
        for (int kh = 0; kh < 2; kh++) {
            const int kc = kh * 2 + lc;
            uint32_t a_h[4][4], a_l[4][4];
#pragma unroll
            for (int mi = 0; mi < 4; mi++) {
                const int r = wm * 64 + mi * 16 + lr;
                const uint32_t o = swz(r, kc);
                ldsm4(a_h[mi][0], a_h[mi][1], a_h[mi][2], a_h[mi][3], sb + SP_H + o);
                ldsm4(a_l[mi][0], a_l[mi][1], a_l[mi][2], a_l[mi][3], sb + SP_L + o);
            }
            uint32_t b_h[4][2], b_l[4][2];
#pragma unroll
            for (int j = 0; j < 2; j++) {
                const int krow = kh * 16 + lr;
                const int dchunk = wn * 4 + j * 2 + lc;
                const uint32_t o = vswz(krow, dchunk);
                uint32_t r0, r1, r2, r3;
                ldsm4t(r0, r1, r2, r3, sb + SV_H + o);
                b_h[j * 2][0] = r0; b_h[j * 2][1] = r1;
                b_h[j * 2 + 1][0] = r2; b_h[j * 2 + 1][1] = r3;
                ldsm4t(r0, r1, r2, r3, sb + SV_L + o);
                b_l[j * 2][0] = r0; b_l[j * 2][1] = r1;
                b_l[j * 2 + 1][0] = r2; b_l[j * 2 + 1][1] = r3;
            }
#pragma unroll
            for (int mi = 0; mi < 4; mi++)
#pragma unroll
                for (int ni = 0; ni < 4; ni++) {
                    mma16816(acc[mi][ni], a_h[mi], b_h[ni]);
                    mma16816(acc[mi][ni], a_h[mi], b_l[ni]);
                    mma16816(acc[mi][ni], a_l[mi], b_h[ni]);
                }
        }
        __syncthreads();
    }
#pragma unroll
    for (int mi = 0; mi < 4; mi++) {
        const int r = (ch << 7) + wm * 64 + mi * 16 + (lane >> 2);
#pragma unroll
        for (int ni = 0; ni < 4; ni++) {
            const int cc = colV + wn * 32 + ni * 8 + ((lane & 3) << 1);
            float* d0 = g_merged + (size_t)r * HIDN + cc;
            float* d1 = g_merged + (size_t)(r + 8) * HIDN + cc;
            d0[0] = __fmul_rn(__fadd_rn(d0[0], acc[mi][ni][0]), 0.5f);
            d0[1] = __fmul_rn(__fadd_rn(d0[1], acc[mi][ni][1]), 0.5f);
            d1[0] = __fmul_rn(__fadd_rn(d1[0], acc[mi][ni][2]), 0.5f);
            d1[1] = __fmul_rn(__fadd_rn(d1[1], acc[mi][ni][3]), 0.5f);
        }
    }
}

// split fp32 -> bf16 hi + lo
__global__ void split_plain(const float* __restrict__ src,
                            __nv_bfloat16* __restrict__ h, __nv_bfloat16* __restrict__ l,
                            int n)
{
    int i = blockIdx.x * blockDim.x + threadIdx.x;
    if (i >= n) return;
    float x = src[i];
    __nv_bfloat16 hi = __float2bfloat16(x);
    h[i] = hi;
    l[i] = __float2bfloat16(__fsub_rn(x, __bfloat162float(hi)));
}

// tri-split fp32 -> 3 bf16 components
__global__ void split3_plain(const float* __restrict__ src,
                             __nv_bfloat16* __restrict__ b1, __nv_bfloat16* __restrict__ b2,
                             __nv_bfloat16* __restrict__ b3, int n)
{
    int i = blockIdx.x * blockDim.x + threadIdx.x;
    if (i >= n) return;
    float x = src[i];
    __nv_bfloat16 h1 = __float2bfloat16(x);
    float r1 = __fsub_rn(x, __bfloat162float(h1));
    __nv_bfloat16 h2 = __float2bfloat16(r1);
    float r2 = __fsub_rn(r1, __bfloat162float(h2));
    b1[i] = h1; b2[i] = h2;
    b3[i] = __float2bfloat16(r2);
}

// transpose + split: W [K][N] -> T{h,l} [n][k]
__global__ void tsplit(const float* __restrict__ W,
                       __nv_bfloat16* __restrict__ Th, __nv_bfloat16* __restrict__ Tl)
{
    __shared__ float tile[32][33];
    const int n0 = blockIdx.x << 5, k0 = blockIdx.y << 5;
    const int tx = threadIdx.x & 31, ty = threadIdx.x >> 5;
#pragma unroll
    for (int i = 0; i < 32; i += 8)
        tile[ty + i][tx] = W[(size_t)(k0 + ty + i) * HIDN + n0 + tx];
    __syncthreads();
#pragma unroll
    for (int i = 0; i < 32; i += 8) {
        float x = tile[tx][ty + i];
        __nv_bfloat16 hi = __float2bfloat16(x);
        size_t o = (size_t)(n0 + ty + i) * HIDN + k0 + tx;
        Th[o] = hi;
        Tl[o] = __float2bfloat16(__fsub_rn(x, __bfloat162float(hi)));
    }
}

// transpose + tri-split: W [K][N] -> 3 bf16 [n][k]
__global__ void tsplit3(const float* __restrict__ W,
                        __nv_bfloat16* __restrict__ T1, __nv_bfloat16* __restrict__ T2,
                        __nv_bfloat16* __restrict__ T3)
{
    __shared__ float tile[32][33];
    const int n0 = blockIdx.x << 5, k0 = blockIdx.y << 5;
    const int tx = threadIdx.x & 31, ty = threadIdx.x >> 5;
#pragma unroll
    for (int i = 0; i < 32; i += 8)
        tile[ty + i][tx] = W[(size_t)(k0 + ty + i) * HIDN + n0 + tx];
    __syncthreads();
#pragma unroll
    for (int i = 0; i < 32; i += 8) {
        float x = tile[tx][ty + i];
        __nv_bfloat16 h1 = __float2bfloat16(x);
        float r1 = __fsub_rn(x, __bfloat162float(h1));
        __nv_bfloat16 h2 = __float2bfloat16(r1);
        float r2 = __fsub_rn(r1, __bfloat162float(h2));
        size_t o = (size_t)(n0 + ty + i) * HIDN + k0 + tx;
        T1[o] = h1; T2[o] = h2;
        T3[o] = __float2bfloat16(r2);
    }
}

// ------------------------------------------------------------------
// SIMT SGEMM (small entries GEMMs only), K = 2048.
// ------------------------------------------------------------------
template <bool KH>
__global__ __launch_bounds__(256)
void sgemm_bias(int mode, const float* __restrict__ W, const float* __restrict__ bias)
{
    const float* A = g_entries;
    float* C = (mode == 3) ? g_ck : g_cv;
    const int lda = HIDN, ldb = DH, ldc = DH;

    __shared__ float As[16][128];
    __shared__ float Bs[16][128];
    const int tid = threadIdx.x;
    const int row0 = blockIdx.y << 7;
    const int col0 = 0;
    const int ty = tid >> 4, tx = tid & 15;

    float acc[8][8], cmp[8][8];
#pragma unroll
    for (int i = 0; i < 8; i++)
#pragma unroll
        for (int j = 0; j < 8; j++) { acc[i][j] = 0.f; cmp[i][j] = 0.f; }

    for (int k0 = 0; k0 < HIDN; k0 += 16) {
#pragma unroll
        for (int t = 0; t < 2; t++) {
            int jj = tid + (t << 8);
            int m = jj >> 2, k4 = (jj & 3) << 2;
            float4 v = *(const float4*)(A + (size_t)(row0 + m) * lda + k0 + k4);
            As[k4 + 0][m] = v.x; As[k4 + 1][m] = v.y;
            As[k4 + 2][m] = v.z; As[k4 + 3][m] = v.w;
        }
#pragma unroll
        for (int t = 0; t < 2; t++) {
            int jj = tid + (t << 8);
            int kk = jj >> 5, n4 = (jj & 31) << 2;
            *(float4*)&Bs[kk][n4] = *(const float4*)(W + (size_t)(k0 + kk) * ldb + col0 + n4);
        }
        __syncthreads();
        if (KH) {
            float tmp[8][8];
#pragma unroll
            for (int i = 0; i < 8; i++)
#pragma unroll
                for (int j = 0; j < 8; j++) tmp[i][j] = 0.f;
#pragma unroll
            for (int kk = 0; kk < 16; kk++) {
                float ra[8], rb[8];
                *(float4*)&ra[0] = *(const float4*)&As[kk][ty << 3];
                *(float4*)&ra[4] = *(const float4*)&As[kk][(ty << 3) + 4];
                *(float4*)&rb[0] = *(const float4*)&Bs[kk][tx << 3];
                *(float4*)&rb[4] = *(const float4*)&Bs[kk][(tx << 3) + 4];
#pragma unroll
                for (int i = 0; i < 8; i++)
#pragma unroll
                    for (int j = 0; j < 8; j++)
                        tmp[i][j] = __fmaf_rn(ra[i], rb[j], tmp[i][j]);
            }
#pragma unroll
            for (int i = 0; i < 8; i++)
#pragma unroll
                for (int j = 0; j < 8; j++) {
                    float y = __fsub_rn(tmp[i][j], cmp[i][j]);
                    float t2 = __fadd_rn(acc[i][j], y);
                    cmp[i][j] = __fsub_rn(__fsub_rn(t2, acc[i][j]), y);
                    acc[i][j] = t2;
                }
        } else {
#pragma unroll
            for (int kk = 0; kk < 16; kk++) {
                float ra[8], rb[8];
                *(float4*)&ra[0] = *(const float4*)&As[kk][ty << 3];
                *(float4*)&ra[4] = *(const float4*)&As[kk][(ty << 3) + 4];
                *(float4*)&rb[0] = *(const float4*)&Bs[kk][tx << 3];
                *(float4*)&rb[4] = *(const float4*)&Bs[kk][(tx << 3) + 4];
#pragma unroll
                for (int i = 0; i < 8; i++)
#pragma unroll
                    for (int j = 0; j < 8; j++) acc[i][j] += ra[i] * rb[j];
            }
        }
        __syncthreads();
    }
#pragma unroll
    for (int i = 0; i < 8; i++) {
        size_t r = row0 + (ty << 3) + i;
#pragma unroll
        for (int j = 0; j < 8; j++) {
            int c = col0 + (tx << 3) + j;
            C[r * ldc + c] = __fadd_rn(acc[i][j], bias[c]);
        }
    }
}

// ------------------------------------------------------------------
// rmsnorm + rope, one warp per (row, head) 128-slice, in place.
// ------------------------------------------------------------------
__global__ void norm_rope(int mode, const float* __restrict__ w)
{
    int gw = (blockIdx.x * blockDim.x + threadIdx.x) >> 5;
    int lane = threadIdx.x & 31;
    float* buf; int rows, heads, rstride, pmul, padd;
    if (mode == 0)      { buf = g_q;  rows = SQ; heads = NHEAD; rstride = HIDN; pmul = 1; padd = 0; }
    else if (mode == 1) { buf = g_lk; rows = SQ; heads = NHEAD; rstride = HIDN; pmul = 1; padd = 0; }
    else                { buf = g_ck; rows = CB; heads = 1;     rstride = DH;   pmul = 4; padd = 3; }
    if (gw >= rows * heads) return;
    int row = gw / heads, h = gw - row * heads;
    float* p = buf + (size_t)row * rstride + h * DH;
    float x0 = p[lane], x1 = p[lane + 32], x2 = p[lane + 64], x3 = p[lane + 96];
    float ss = warp_sum(x0 * x0 + x1 * x1 + x2 * x2 + x3 * x3);
    float mean = __fadd_rn(__fmul_rn(ss, 0.0078125f), 1e-6f);
    float rs = __fdiv_rn(1.0f, __fsqrt_rn(mean));
    x0 = __fmul_rn(__fmul_rn(x0, rs), w[lane]);
    x1 = __fmul_rn(__fmul_rn(x1, rs), w[lane + 32]);
    x2 = __fmul_rn(__fmul_rn(x2, rs), w[lane + 64]);
    x3 = __fmul_rn(__fmul_rn(x3, rs), w[lane + 96]);
    float pf = (float)pow(10000.0, (double)lane * (1.0 / 32.0));
    float invf = __fdiv_rn(1.0f, pf);
    float ang = __fmul_rn((float)(row * pmul + padd), invf);
    float c = (float)cos((double)ang);
    float s = (float)sin((double)ang);
    float n0 = __fsub_rn(__fmul_rn(x0, c), __fmul_rn(x1, s));
    float n1 = __fadd_rn(__fmul_rn(x0, s), __fmul_rn(x1, c));
    p[lane] = n0; p[lane + 32] = n1; p[lane + 64] = x2; p[lane + 96] = x3;
}

__global__ void cmp_logits(const float* __restrict__ hidden, const float* __restrict__ Wc,
                           const float* __restrict__ bc)
{
    int gw = (blockIdx.x * blockDim.x + threadIdx.x) >> 5;
    int lane = threadIdx.x & 31;
    if (gw >= SQ) return;
    const float* hr = hidden + (size_t)gw * HIDN;
    float acc = 0.f, cmp = 0.f;
    for (int k = lane; k < HIDN; k += 32) {
        float y = __fmaf_rn(hr[k], Wc[k], -cmp);
        float t = __fadd_rn(acc, y);
        cmp = __fsub_rn(__fsub_rn(t, acc), y);
        acc = t;
    }
    acc = warp_sum(acc);
    if (lane == 0) g_wlog[gw] = __fadd_rn(acc, bc[0]);
}

__global__ void entries_kernel(const float* __restrict__ hidden)
{
    int c = blockIdx.x;
    float w0 = g_wlog[c * 4 + 0], w1 = g_wlog[c * 4 + 1];
    float w2 = g_wlog[c * 4 + 2], w3 = g_wlog[c * 4 + 3];
    float m = fmaxf(fmaxf(w0, w1), fmaxf(w2, w3));
    float e0 = (float)exp((double)__fsub_rn(w0, m));
    float e1 = (float)exp((double)__fsub_rn(w1, m));
    float e2 = (float)exp((double)__fsub_rn(w2, m));
    float e3 = (float)exp((double)__fsub_rn(w3, m));
    float sum = __fadd_rn(__fadd_rn(e0, e1), __fadd_rn(e2, e3));
    e0 = __fdiv_rn(e0, sum); e1 = __fdiv_rn(e1, sum);
    e2 = __fdiv_rn(e2, sum); e3 = __fdiv_rn(e3, sum);
    const float* h0 = hidden + (size_t)c * 4 * HIDN;
    float* dst = g_entries + (size_t)c * HIDN;
    for (int j = threadIdx.x; j < HIDN; j += blockDim.x)
        dst[j] = e0 * h0[j] + e1 * h0[HIDN + j] + e2 * h0[2 * HIDN + j] + e3 * h0[3 * HIDN + j];
}

// ------------------------------------------------------------------
// top-8 over causal prefix + softmax + gather cv; writes 1.0*ctx_sparse
// ------------------------------------------------------------------
__global__ void topk_sparse()
{
    int gw = (blockIdx.x * blockDim.x + threadIdx.x) >> 5;
    int lane = threadIdx.x & 31;
    if (gw >= NHEAD * SQ) return;
    int h = gw >> 12;
    int s = gw & (SQ - 1);
    int nc = (s + 1) >> 2;
    const float* row = g_sc + ((size_t)h * SQ + s) * CB;

    float bv[8]; int bi[8];
#pragma unroll
    for (int i = 0; i < 8; i++) { bv[i] = NEGV; bi[i] = -1; }
    for (int c = lane; c < nc; c += 32) {
        float v = row[c];
        if (v > bv[7]) {
            bv[7] = v; bi[7] = c;
#pragma unroll
            for (int j = 7; j > 0; j--) {
                if (bv[j] > bv[j - 1]) {
                    float tv = bv[j]; bv[j] = bv[j - 1]; bv[j - 1] = tv;
                    int txx = bi[j]; bi[j] = bi[j - 1]; bi[j - 1] = txx;
                }
            }
        }
    }
    int ptr = 0;
    float tvv[8]; int tii[8];
#pragma unroll
    for (int t = 0; t < 8; t++) {
        float m = (ptr < 8) ? bv[ptr] : NEGV;
        int mi = (ptr < 8) ? bi[ptr] : 0x7fffffff;
#pragma unroll
        for (int o = 16; o; o >>= 1) {
            float om = __shfl_xor_sync(0xffffffffu, m, o);
            int oi = __shfl_xor_sync(0xffffffffu, mi, o);
            if (om > m || (om == m && oi < mi)) { m = om; mi = oi; }
        }
        tvv[t] = m; tii[t] = mi;
        if (ptr < 8 && bv[ptr] == m && bi[ptr] == mi) ptr++;
    }
    float m0 = tvv[0];
    float e[8]; float sum = 0.f;
#pragma unroll
    for (int t = 0; t < 8; t++) {
        e[t] = (tvv[t] > NEGH) ? (float)exp((double)__fsub_rn(tvv[t], m0)) : 0.f;
        sum += e[t];
    }
    float den = fmaxf(sum, 1e-9f);
    float c0 = 0.f, c1 = 0.f, c2 = 0.f, c3 = 0.f;
#pragma unroll
    for (int t = 0; t < 8; t++) {
        float wgt = __fdiv_rn(e[t], den);
        if (wgt > 0.f) {
            const float* vr = g_cv + (size_t)tii[t] * DH;
            c0 += wgt * vr[lane];      c1 += wgt * vr[lane + 32];
            c2 += wgt * vr[lane + 64]; c3 += wgt * vr[lane + 96];
        }
    }
    float* dst = g_merged + (size_t)s * HIDN + h * DH;
    dst[lane] = c0;      dst[lane + 32] = c1;
    dst[lane + 64] = c2; dst[lane + 96] = c3;
}

// masked softmax over 256 local keys; writes bf16 split probs
__global__ void local_softmax()
{
    int gw = (blockIdx.x * blockDim.x + threadIdx.x) >> 5;
    int lane = threadIdx.x & 31;
    if (gw >= NHEAD * 32 * 128) return;
    int qi = gw & 127;
    int ch = (gw >> 7) & 31;
    const float* rowp = g_scl + (size_t)gw * 256;
    __nv_bfloat16* oh = g_sph + (size_t)gw * 256;
    __nv_bfloat16* ol = g_spl + (size_t)gw * 256;
    int lo = (ch == 0) ? 128 : qi;
    int hi = qi + 128;
    float v[8];
    float m = NEGV;
#pragma unroll
    for (int t = 0; t < 8; t++) {
        int j = lane + (t << 5);
        bool ok = (j >= lo) && (j <= hi);
        v[t] = ok ? rowp[j] : NEGV;
        m = fmaxf(m, v[t]);
    }
    m = warp_max(m);
    float e[8]; float sum = 0.f;
#pragma unroll
    for (int t = 0; t < 8; t++) {
        int j = lane + (t << 5);
        bool ok = (j >= lo) && (j <= hi);
        e[t] = ok ? (float)exp((double)__fsub_rn(v[t], m)) : 0.f;
        sum += e[t];
    }
    sum = warp_sum(sum);
#pragma unroll
    for (int t = 0; t < 8; t++) {
        float p = __fdiv_rn(e[t], sum);
        __nv_bfloat16 hh = __float2bfloat16(p);
        oh[lane + (t << 5)] = hh;
        ol[lane + (t << 5)] = __float2bfloat16(__fsub_rn(p, __bfloat162float(hh)));
    }
}

// ------------------------------------------------------------------
extern "C" void kernel_launch(void* const* d_in, const int* in_sizes, int n_in,
                              void* d_out, int out_size)
{
    const float* hidden = (const float*)d_in[0];
    const float* Wq   = (const float*)d_in[1];
    const float* bq   = (const float*)d_in[2];
    const float* Wcmp = (const float*)d_in[3];
    const float* bcmp = (const float*)d_in[4];
    const float* Wk   = (const float*)d_in[5];
    const float* bk   = (const float*)d_in[6];
    const float* Wv   = (const float*)d_in[7];
    const float* bvv  = (const float*)d_in[8];
    const float* Wlk  = (const float*)d_in[9];
    const float* blkb = (const float*)d_in[10];
    const float* Wlv  = (const float*)d_in[11];
    const float* blvb = (const float*)d_in[12];
    const float* qnw  = (const float*)d_in[13];
    const float* knw  = (const float*)d_in[14];
    const float* Wo   = (const float*)d_in[15];
    const float* bo   = (const float*)d_in[16];
    float* out = (float*)d_out;

    static __nv_bfloat16 *hid_h = nullptr, *hid_l, *hid_m, *mrg_h, *mrg_l,
                         *wlk_h, *wlk_l, *wlv_h, *wlv_l, *wo_h, *wo_l,
                         *qh, *ql, *qm, *lkh, *lkl, *lvh, *lvl,
                         *wq1, *wq2, *wq3, *ck1, *ck2, *ck3;
    static float *p_q = nullptr, *p_lk, *p_lv, *p_merged, *p_ck, *p_sc;
    if (!hid_h) {
        cudaGetSymbolAddress((void**)&hid_h, g_hid_h);
        cudaGetSymbolAddress((void**)&hid_l, g_hid_l);
        cudaGetSymbolAddress((void**)&hid_m, g_hid_m);
        cudaGetSymbolAddress((void**)&mrg_h, g_mrg_h);
        cudaGetSymbolAddress((void**)&mrg_l, g_mrg_l);
        cudaGetSymbolAddress((void**)&wlk_h, g_wlk_h);
        cudaGetSymbolAddress((void**)&wlk_l, g_wlk_l);
        cudaGetSymbolAddress((void**)&wlv_h, g_wlv_h);
        cudaGetSymbolAddress((void**)&wlv_l, g_wlv_l);
        cudaGetSymbolAddress((void**)&wo_h, g_wo_h);
        cudaGetSymbolAddress((void**)&wo_l, g_wo_l);
        cudaGetSymbolAddress((void**)&qh, g_qh);
        cudaGetSymbolAddress((void**)&ql, g_ql);
        cudaGetSymbolAddress((void**)&qm, g_qm);
        cudaGetSymbolAddress((void**)&lkh, g_lkh);
        cudaGetSymbolAddress((void**)&lkl, g_lkl);
        cudaGetSymbolAddress((void**)&lvh, g_lvh);
        cudaGetSymbolAddress((void**)&lvl, g_lvl);
        cudaGetSymbolAddress((void**)&wq1, g_wq1);
        cudaGetSymbolAddress((void**)&wq2, g_wq2);
        cudaGetSymbolAddress((void**)&wq3, g_wq3);
        cudaGetSymbolAddress((void**)&ck1, g_ck1);
        cudaGetSymbolAddress((void**)&ck2, g_ck2);
        cudaGetSymbolAddress((void**)&ck3, g_ck3);
        cudaGetSymbolAddress((void**)&p_q, g_q);
        cudaGetSymbolAddress((void**)&p_lk, g_lk);
        cudaGetSymbolAddress((void**)&p_lv, g_lv);
        cudaGetSymbolAddress((void**)&p_merged, g_merged);
        cudaGetSymbolAddress((void**)&p_ck, g_ck);
        cudaGetSymbolAddress((void**)&p_sc, g_sc);
    }

    const int NELT = SQ * HIDN;

    // splits of inputs/weights
    split3_plain<<<(NELT + 255) / 256, 256>>>(hidden, hid_h, hid_m, hid_l, NELT);
    tsplit3<<<dim3(64, 64), 256>>>(Wq, wq1, wq2, wq3);
    tsplit<<<dim3(64, 64), 256>>>(Wlk, wlk_h, wlk_l);
    tsplit<<<dim3(64, 64), 256>>>(Wlv, wlv_h, wlv_l);
    tsplit<<<dim3(64, 64), 256>>>(Wo,  wo_h,  wo_l);

    // Wq: tri-split 6-pass TC with per-K-tile Kahan fold (selection-grade)
    gemm_tc6k<<<dim3(HIDN / 64, SQ / 128, 1), 256>>>(
        hid_h, hid_m, hid_l, wq1, wq2, wq3, bq, p_q,
        HIDN, HIDN, HIDN, HIDN, 0, 0, 1.0f, 0);

    // smooth projections (bf16x3, first two hidden components)
    gemm_tc<<<dim3(HIDN / 128, SQ / 128), 256>>>(hid_h, hid_m, wlk_h, wlk_l, blkb, p_lk);
    gemm_tc<<<dim3(HIDN / 128, SQ / 128), 256>>>(hid_h, hid_m, wlv_h, wlv_l, blvb, p_lv);

    cmp_logits<<<SQ / 8, 256>>>(hidden, Wcmp, bcmp);
    entries_kernel<<<CB, 256>>>(hidden);

    sgemm_bias<true ><<<dim3(1, CB / 128), 256>>>(3, Wk, bk);   // feeds top-k (Kahan)
    sgemm_bias<false><<<dim3(1, CB / 128), 256>>>(4, Wv, bvv);

    norm_rope<<<(SQ * NHEAD) / 8, 256>>>(0, qnw);
    norm_rope<<<(SQ * NHEAD) / 8, 256>>>(1, knw);
    norm_rope<<<CB / 8, 256>>>(2, knw);

    // splits post norm/rope
    split3_plain<<<(NELT + 255) / 256, 256>>>(p_q, qh, ql, qm, NELT);
    split3_plain<<<(CB * DH + 255) / 256, 256>>>(p_ck, ck1, ck2, ck3, CB * DH);
    split_plain<<<(NELT + 255) / 256, 256>>>(p_lk, lkh, lkl, NELT);
    split_plain<<<(NELT + 255) / 256, 256>>>(p_lv, lvh, lvl, NELT);

    // compressed scores: tri-split 6-pass TC + Kahan fold, causal tile skip
    gemm_tc6k<<<dim3(CB / 64, SQ / 128, NHEAD), 256>>>(
        qh, ql, qm, ck1, ck2, ck3, nullptr, p_sc,
        HIDN, DH, CB, DH, (size_t)DH, (size_t)SQ * CB, ATT_SCALE, 1);

    topk_sparse<<<(NHEAD * SQ) / 8, 256>>>();

    // local attention on tensor cores
    gemm_tc_qk<<<dim3(2, NHEAD * 32), 256>>>();
    local_softmax<<<(NHEAD * 32 * 128) / 8, 256>>>();
    gemm_tc_pv<<<NHEAD * 32, 256>>>();

    // output projection on tensor cores
    split_plain<<<(NELT + 255) / 256, 256>>>(p_merged, mrg_h, mrg_l, NELT);
    gemm_tc<<<dim3(HIDN / 128, SQ / 128), 256>>>(mrg_h, mrg_l, wo_h, wo_l, bo, out);
}

// round 12
// speedup vs baseline: 1.9562x; 1.1030x over previous
#include <cuda_runtime.h>
#include <cuda_bf16.h>
#include <math.h>
#include <stdint.h>

#define SQ 4096
#define HIDN 2048
#define NHEAD 16
#define DH 128
#define CB 1024
#define NEGV -1e30f
#define NEGH -5e29f
#define ATT_SCALE 0.08838834764831845f

// ------------- scratch (static __device__ globals; allocation-free) -------------
__device__ float g_q[(size_t)SQ * HIDN];
__device__ float g_lk[(size_t)SQ * HIDN];
__device__ float g_lv[(size_t)SQ * HIDN];
__device__ float g_wlog[SQ];
__device__ float g_entries[(size_t)CB * HIDN];
__device__ float g_ck[CB * DH];
__device__ float g_cv[CB * DH];
__device__ float g_merged[(size_t)SQ * HIDN];
__device__ float g_sc[(size_t)NHEAD * SQ * CB];
__device__ float g_scl[(size_t)NHEAD * 32 * 128 * 256];

// bf16 split buffers
__device__ __nv_bfloat16 g_hid_h[(size_t)SQ * HIDN];
__device__ __nv_bfloat16 g_hid_l[(size_t)SQ * HIDN];
__device__ __nv_bfloat16 g_hid_m[(size_t)SQ * HIDN];
__device__ __nv_bfloat16 g_mrg_h[(size_t)SQ * HIDN];
__device__ __nv_bfloat16 g_mrg_l[(size_t)SQ * HIDN];
__device__ __nv_bfloat16 g_qh[(size_t)SQ * HIDN];
__device__ __nv_bfloat16 g_ql[(size_t)SQ * HIDN];
__device__ __nv_bfloat16 g_qm[(size_t)SQ * HIDN];
__device__ __nv_bfloat16 g_lkh[(size_t)SQ * HIDN];
__device__ __nv_bfloat16 g_lkl[(size_t)SQ * HIDN];
__device__ __nv_bfloat16 g_lvh[(size_t)SQ * HIDN];
__device__ __nv_bfloat16 g_lvl[(size_t)SQ * HIDN];
__device__ __nv_bfloat16 g_ck1[CB * DH];
__device__ __nv_bfloat16 g_ck2[CB * DH];
__device__ __nv_bfloat16 g_ck3[CB * DH];
__device__ __nv_bfloat16 g_sph[(size_t)NHEAD * 32 * 128 * 256];
__device__ __nv_bfloat16 g_spl[(size_t)NHEAD * 32 * 128 * 256];
__device__ __nv_bfloat16 g_wq1[(size_t)HIDN * HIDN];
__device__ __nv_bfloat16 g_wq2[(size_t)HIDN * HIDN];
__device__ __nv_bfloat16 g_wq3[(size_t)HIDN * HIDN];
__device__ __nv_bfloat16 g_wlk_h[(size_t)HIDN * HIDN];
__device__ __nv_bfloat16 g_wlk_l[(size_t)HIDN * HIDN];
__device__ __nv_bfloat16 g_wlv_h[(size_t)HIDN * HIDN];
__device__ __nv_bfloat16 g_wlv_l[(size_t)HIDN * HIDN];
__device__ __nv_bfloat16 g_wo_h[(size_t)HIDN * HIDN];
__device__ __nv_bfloat16 g_wo_l[(size_t)HIDN * HIDN];

__device__ __forceinline__ float warp_sum(float v) {
#pragma unroll
    for (int o = 16; o; o >>= 1) v += __shfl_xor_sync(0xffffffffu, v, o);
    return v;
}
__device__ __forceinline__ float warp_max(float v) {
#pragma unroll
    for (int o = 16; o; o >>= 1) v = fmaxf(v, __shfl_xor_sync(0xffffffffu, v, o));
    return v;
}

// ======================= mma.sync helpers (base PTX, sm_80+) =======================
__device__ __forceinline__ uint32_t smem_u32(const void* p) {
    uint32_t a;
    asm("{ .reg .u64 t; cvta.to.shared.u64 t, %1; cvt.u32.u64 %0, t; }" : "=r"(a) : "l"(p));
    return a;
}
__device__ __forceinline__ void ldsm4(uint32_t& r0, uint32_t& r1, uint32_t& r2, uint32_t& r3,
                                      uint32_t addr) {
    asm volatile("ldmatrix.sync.aligned.m8n8.x4.shared.b16 {%0,%1,%2,%3}, [%4];"
                 : "=r"(r0), "=r"(r1), "=r"(r2), "=r"(r3) : "r"(addr));
}
__device__ __forceinline__ void ldsm4t(uint32_t& r0, uint32_t& r1, uint32_t& r2, uint32_t& r3,
                                       uint32_t addr) {
    asm volatile("ldmatrix.sync.aligned.m8n8.x4.trans.shared.b16 {%0,%1,%2,%3}, [%4];"
                 : "=r"(r0), "=r"(r1), "=r"(r2), "=r"(r3) : "r"(addr));
}
__device__ __forceinline__ void mma16816(float* d, const uint32_t* a, const uint32_t* b) {
    asm volatile(
        "mma.sync.aligned.m16n8k16.row.col.f32.bf16.bf16.f32 "
        "{%0,%1,%2,%3}, {%4,%5,%6,%7}, {%8,%9}, {%0,%1,%2,%3};"
        : "+f"(d[0]), "+f"(d[1]), "+f"(d[2]), "+f"(d[3])
        : "r"(a[0]), "r"(a[1]), "r"(a[2]), "r"(a[3]), "r"(b[0]), "r"(b[1]));
}
__device__ __forceinline__ uint32_t swz(int row, int c) {
    int slot = (((row & 1) << 2) | c) ^ ((row >> 1) & 7);
    return (uint32_t)(((row >> 1) << 7) + (slot << 4));
}
__device__ __forceinline__ uint32_t vswz(int row, int c) {
    return (uint32_t)((row << 8) + ((c ^ (row & 7)) << 4));
}
// split helpers
__device__ __forceinline__ void split2(float x, __nv_bfloat16& h, __nv_bfloat16& l) {
    h = __float2bfloat16(x);
    l = __float2bfloat16(__fsub_rn(x, __bfloat162float(h)));
}
__device__ __forceinline__ void split3v(float x, __nv_bfloat16& a, __nv_bfloat16& b,
                                        __nv_bfloat16& c) {
    a = __float2bfloat16(x);
    float r1 = __fsub_rn(x, __bfloat162float(a));
    b = __float2bfloat16(r1);
    c = __float2bfloat16(__fsub_rn(r1, __bfloat162float(b)));
}

// ------------------------------------------------------------------
// Selection-grade TC GEMM: bf16 tri-split 6-pass + per-K-tile Kahan fold.
// Block 128(m) x 64(n), 8 warps (2m x 4n), warp tile 64x16, K-step 32.
// ------------------------------------------------------------------
__global__ void __launch_bounds__(256)
gemm_tc6k(const __nv_bfloat16* __restrict__ A1, const __nv_bfloat16* __restrict__ A2,
          const __nv_bfloat16* __restrict__ A3,
          const __nv_bfloat16* __restrict__ B1, const __nv_bfloat16* __restrict__ B2,
          const __nv_bfloat16* __restrict__ B3,
          const float* __restrict__ bias, float* __restrict__ C,
          int lda, int ldb, int ldc, int K,
          size_t a_zoff, size_t c_zoff, float scale, int causal)
{
    const int row0 = blockIdx.y << 7;
    const int n0 = blockIdx.x << 6;
    if (causal && n0 >= (row0 >> 2) + 32) return;
    A1 += blockIdx.z * a_zoff; A2 += blockIdx.z * a_zoff; A3 += blockIdx.z * a_zoff;
    C += blockIdx.z * c_zoff;

    __shared__ char smem[3 * 8192 + 3 * 4096];
    const uint32_t sb = smem_u32(smem);
    const uint32_t OB1 = 24576, OB2 = 28672, OB3 = 32768;
    const int tid = threadIdx.x;
    const int lane = tid & 31, wid = tid >> 5;
    const int wm = wid >> 2, wn = wid & 3;

    float acc[4][2][4], cmp[4][2][4];
#pragma unroll
    for (int mi = 0; mi < 4; mi++)
#pragma unroll
        for (int ni = 0; ni < 2; ni++)
#pragma unroll
            for (int t = 0; t < 4; t++) { acc[mi][ni][t] = 0.f; cmp[mi][ni][t] = 0.f; }

    const int lr = lane & 15, lc = lane >> 4;

    for (int k0 = 0; k0 < K; k0 += 32) {
#pragma unroll
        for (int i = 0; i < 2; i++) {
            const int idx = tid + (i << 8);
            const int row = idx >> 2, c = idx & 3;
            const uint32_t off = swz(row, c);
            const size_t ga = (size_t)(row0 + row) * lda + k0 + (c << 3);
            *(uint4*)(smem + 0     + off) = *(const uint4*)(A1 + ga);
            *(uint4*)(smem + 8192  + off) = *(const uint4*)(A2 + ga);
            *(uint4*)(smem + 16384 + off) = *(const uint4*)(A3 + ga);
        }
        {
            const int row = tid >> 2, c = tid & 3;
            const uint32_t off = swz(row, c);
            const size_t gb = (size_t)(n0 + row) * ldb + k0 + (c << 3);
            *(uint4*)(smem + OB1 + off) = *(const uint4*)(B1 + gb);
            *(uint4*)(smem + OB2 + off) = *(const uint4*)(B2 + gb);
            *(uint4*)(smem + OB3 + off) = *(const uint4*)(B3 + gb);
        }
        __syncthreads();

        float tmp[4][2][4];
#pragma unroll
        for (int mi = 0; mi < 4; mi++)
#pragma unroll
            for (int ni = 0; ni < 2; ni++)
#pragma unroll
                for (int t = 0; t < 4; t++) tmp[mi][ni][t] = 0.f;

#pragma unroll
        for (int kh = 0; kh < 2; kh++) {
            const int kc = kh * 2 + lc;
            uint32_t a1[4][4], a2[4][4], a3[4][4];
#pragma unroll
            for (int mi = 0; mi < 4; mi++) {
                const int r = wm * 64 + mi * 16 + lr;
                const uint32_t o = swz(r, kc);
                ldsm4(a1[mi][0], a1[mi][1], a1[mi][2], a1[mi][3], sb + 0 + o);
                ldsm4(a2[mi][0], a2[mi][1], a2[mi][2], a2[mi][3], sb + 8192 + o);
                ldsm4(a3[mi][0], a3[mi][1], a3[mi][2], a3[mi][3], sb + 16384 + o);
            }
            uint32_t b1[2][2], b2[2][2], b3[2][2];
            {
                const int r = wn * 16 + lr;
                const uint32_t o = swz(r, kc);
                uint32_t r0, r1, r2, r3;
                ldsm4(r0, r1, r2, r3, sb + OB1 + o);
                b1[0][0] = r0; b1[1][0] = r1; b1[0][1] = r2; b1[1][1] = r3;
                ldsm4(r0, r1, r2, r3, sb + OB2 + o);
                b2[0][0] = r0; b2[1][0] = r1; b2[0][1] = r2; b2[1][1] = r3;
                ldsm4(r0, r1, r2, r3, sb + OB3 + o);
                b3[0][0] = r0; b3[1][0] = r1; b3[0][1] = r2; b3[1][1] = r3;
            }
#pragma unroll
            for (int mi = 0; mi < 4; mi++)
#pragma unroll
                for (int ni = 0; ni < 2; ni++) {
                    mma16816(tmp[mi][ni], a1[mi], b1[ni]);
                    mma16816(tmp[mi][ni], a1[mi], b2[ni]);
                    mma16816(tmp[mi][ni], a2[mi], b1[ni]);
                    mma16816(tmp[mi][ni], a2[mi], b2[ni]);
                    mma16816(tmp[mi][ni], a1[mi], b3[ni]);
                    mma16816(tmp[mi][ni], a3[mi], b1[ni]);
                }
        }
#pragma unroll
        for (int mi = 0; mi < 4; mi++)
#pragma unroll
            for (int ni = 0; ni < 2; ni++)
#pragma unroll
                for (int t = 0; t < 4; t++) {
                    float y = __fsub_rn(tmp[mi][ni][t], cmp[mi][ni][t]);
                    float t2 = __fadd_rn(acc[mi][ni][t], y);
                    cmp[mi][ni][t] = __fsub_rn(__fsub_rn(t2, acc[mi][ni][t]), y);
                    acc[mi][ni][t] = t2;
                }
        __syncthreads();
    }
#pragma unroll
    for (int mi = 0; mi < 4; mi++) {
        const int r = row0 + wm * 64 + mi * 16 + (lane >> 2);
#pragma unroll
        for (int ni = 0; ni < 2; ni++) {
            const int cc = n0 + wn * 16 + ni * 8 + ((lane & 3) << 1);
            if (bias) {
                const float b0 = bias[cc], b1v = bias[cc + 1];
                C[(size_t)r * ldc + cc]           = __fadd_rn(acc[mi][ni][0], b0);
                C[(size_t)r * ldc + cc + 1]       = __fadd_rn(acc[mi][ni][1], b1v);
                C[(size_t)(r + 8) * ldc + cc]     = __fadd_rn(acc[mi][ni][2], b0);
                C[(size_t)(r + 8) * ldc + cc + 1] = __fadd_rn(acc[mi][ni][3], b1v);
            } else {
                C[(size_t)r * ldc + cc]           = __fmul_rn(acc[mi][ni][0], scale);
                C[(size_t)r * ldc + cc + 1]       = __fmul_rn(acc[mi][ni][1], scale);
                C[(size_t)(r + 8) * ldc + cc]     = __fmul_rn(acc[mi][ni][2], scale);
                C[(size_t)(r + 8) * ldc + cc + 1] = __fmul_rn(acc[mi][ni][3], scale);
            }
        }
    }
}

// ------------------------------------------------------------------
// Smooth tensor GEMM bf16x3: C = A @ W + bias. Block 128x128.
// Optional bf16 2-split outputs (Sh/Sl) fused into the epilogue.
// ------------------------------------------------------------------
__global__ void __launch_bounds__(256)
gemm_tc(const __nv_bfloat16* __restrict__ Ah, const __nv_bfloat16* __restrict__ Al,
        const __nv_bfloat16* __restrict__ Bh, const __nv_bfloat16* __restrict__ Bl,
        const float* __restrict__ bias, float* __restrict__ C,
        __nv_bfloat16* __restrict__ Sh, __nv_bfloat16* __restrict__ Sl)
{
    __shared__ char smem[4 * 8192];
    const uint32_t sb = smem_u32(smem);
    const uint32_t SA_H = 0, SA_L = 8192, SB_H = 16384, SB_L = 24576;
    const int tid = threadIdx.x;
    const int lane = tid & 31, wid = tid >> 5;
    const int wm = wid >> 2, wn = wid & 3;
    const int row0 = blockIdx.y << 7;
    const int n0 = blockIdx.x << 7;

    float acc[4][4][4];
#pragma unroll
    for (int mi = 0; mi < 4; mi++)
#pragma unroll
        for (int ni = 0; ni < 4; ni++)
#pragma unroll
            for (int t = 0; t < 4; t++) acc[mi][ni][t] = 0.f;

    const int lr = lane & 15, lc = lane >> 4;

    for (int k0 = 0; k0 < HIDN; k0 += 32) {
#pragma unroll
        for (int i = 0; i < 2; i++) {
            const int idx = tid + (i << 8);
            const int row = idx >> 2, c = idx & 3;
            const uint32_t off = swz(row, c);
            const size_t ga = (size_t)(row0 + row) * HIDN + k0 + (c << 3);
            const size_t gb = (size_t)(n0 + row) * HIDN + k0 + (c << 3);
            *(uint4*)(smem + SA_H + off) = *(const uint4*)(Ah + ga);
            *(uint4*)(smem + SA_L + off) = *(const uint4*)(Al + ga);
            *(uint4*)(smem + SB_H + off) = *(const uint4*)(Bh + gb);
            *(uint4*)(smem + SB_L + off) = *(const uint4*)(Bl + gb);
        }
        __syncthreads();
#pragma unroll
        for (int kh = 0; kh < 2; kh++) {
            const int kc = kh * 2 + lc;
            uint32_t a_h[4][4], a_l[4][4];
#pragma unroll
            for (int mi = 0; mi < 4; mi++) {
                const int r = wm * 64 + mi * 16 + lr;
                const uint32_t o = swz(r, kc);
                ldsm4(a_h[mi][0], a_h[mi][1], a_h[mi][2], a_h[mi][3], sb + SA_H + o);
                ldsm4(a_l[mi][0], a_l[mi][1], a_l[mi][2], a_l[mi][3], sb + SA_L + o);
            }
            uint32_t b_h[4][2], b_l[4][2];
#pragma unroll
            for (int np = 0; np < 2; np++) {
                const int r = wn * 32 + np * 16 + lr;
                const uint32_t o = swz(r, kc);
                uint32_t r0, r1, r2, r3;
                ldsm4(r0, r1, r2, r3, sb + SB_H + o);
                b_h[np * 2][0] = r0; b_h[np * 2 + 1][0] = r1;
                b_h[np * 2][1] = r2; b_h[np * 2 + 1][1] = r3;
                ldsm4(r0, r1, r2, r3, sb + SB_L + o);
                b_l[np * 2][0] = r0; b_l[np * 2 + 1][0] = r1;
                b_l[np * 2][1] = r2; b_l[np * 2 + 1][1] = r3;
            }
#pragma unroll
            for (int mi = 0; mi < 4; mi++)
#pragma unroll
                for (int ni = 0; ni < 4; ni++) {
                    mma16816(acc[mi][ni], a_h[mi], b_h[ni]);
                    mma16816(acc[mi][ni], a_h[mi], b_l[ni]);
                    mma16816(acc[mi][ni], a_l[mi], b_h[ni]);
                }
        }
        __syncthreads();
    }
#pragma unroll
    for (int mi = 0; mi < 4; mi++) {
        const int r = row0 + wm * 64 + mi * 16 + (lane >> 2);
#pragma unroll
        for (int ni = 0; ni < 4; ni++) {
            const int cc = n0 + wn * 32 + ni * 8 + ((lane & 3) << 1);
            const float b0 = bias[cc], b1 = bias[cc + 1];
            float v00 = __fadd_rn(acc[mi][ni][0], b0);
            float v01 = __fadd_rn(acc[mi][ni][1], b1);
            float v10 = __fadd_rn(acc[mi][ni][2], b0);
            float v11 = __fadd_rn(acc[mi][ni][3], b1);
            size_t o0 = (size_t)r * HIDN + cc;
            size_t o1 = (size_t)(r + 8) * HIDN + cc;
            C[o0] = v00; C[o0 + 1] = v01;
            C[o1] = v10; C[o1 + 1] = v11;
            if (Sh) {
                split2(v00, Sh[o0], Sl[o0]);
                split2(v01, Sh[o0 + 1], Sl[o0 + 1]);
                split2(v10, Sh[o1], Sl[o1]);
                split2(v11, Sh[o1 + 1], Sl[o1 + 1]);
            }
        }
    }
}

// ------------------------------------------------------------------
// Local QK^T: per (h, ch), scores[128 q][256 keys].
// ------------------------------------------------------------------
__global__ void __launch_bounds__(256)
gemm_tc_qk()
{
    __shared__ char smem[4 * 8192];
    const uint32_t sb = smem_u32(smem);
    const uint32_t SA_H = 0, SA_L = 8192, SB_H = 16384, SB_L = 24576;
    const int tid = threadIdx.x;
    const int lane = tid & 31, wid = tid >> 5;
    const int wm = wid >> 2, wn = wid & 3;
    const int z = blockIdx.y;
    const int h = z >> 5, ch = z & 31;
    const int n0 = blockIdx.x << 7;
    const int b_base = (ch << 7) - 128 + n0;
    const int colA = h * DH;

    float acc[4][4][4];
#pragma unroll
    for (int mi = 0; mi < 4; mi++)
#pragma unroll
        for (int ni = 0; ni < 4; ni++)
#pragma unroll
            for (int t = 0; t < 4; t++) acc[mi][ni][t] = 0.f;

    const int lr = lane & 15, lc = lane >> 4;

    for (int k0 = 0; k0 < DH; k0 += 32) {
#pragma unroll
        for (int i = 0; i < 2; i++) {
            const int idx = tid + (i << 8);
            const int row = idx >> 2, c = idx & 3;
            const uint32_t off = swz(row, c);
            const size_t ga = (size_t)((ch << 7) + row) * HIDN + colA + k0 + (c << 3);
            int br = b_base + row; if (br < 0) br = 0;
            const size_t gb = (size_t)br * HIDN + colA + k0 + (c << 3);
            *(uint4*)(smem + SA_H + off) = *(const uint4*)(g_qh + ga);
            *(uint4*)(smem + SA_L + off) = *(const uint4*)(g_ql + ga);
            *(uint4*)(smem + SB_H + off) = *(const uint4*)(g_lkh + gb);
            *(uint4*)(smem + SB_L + off) = *(const uint4*)(g_lkl + gb);
        }
        __syncthreads();
#pragma unroll
        for (int kh = 0; kh < 2; kh++) {
            const int kc = kh * 2 + lc;
            uint32_t a_h[4][4], a_l[4][4];
#pragma unroll
            for (int mi = 0; mi < 4; mi++) {
                const int r = wm * 64 + mi * 16 + lr;
                const uint32_t o = swz(r, kc);
                ldsm4(a_h[mi][0], a_h[mi][1], a_h[mi][2], a_h[mi][3], sb + SA_H + o);
                ldsm4(a_l[mi][0], a_l[mi][1], a_l[mi][2], a_l[mi][3], sb + SA_L + o);
            }
            uint32_t b_h[4][2], b_l[4][2];
#pragma unroll
            for (int np = 0; np < 2; np++) {
                const int r = wn * 32 + np * 16 + lr;
                const uint32_t o = swz(r, kc);
                uint32_t r0, r1, r2, r3;
                ldsm4(r0, r1, r2, r3, sb + SB_H + o);
                b_h[np * 2][0] = r0; b_h[np * 2 + 1][0] = r1;
                b_h[np * 2][1] = r2; b_h[np * 2 + 1][1] = r3;
                ldsm4(r0, r1, r2, r3, sb + SB_L + o);
                b_l[np * 2][0] = r0; b_l[np * 2 + 1][0] = r1;
                b_l[np * 2][1] = r2; b_l[np * 2 + 1][1] = r3;
            }
#pragma unroll
            for (int mi = 0; mi < 4; mi++)
#pragma unroll
                for (int ni = 0; ni < 4; ni++) {
                    mma16816(acc[mi][ni], a_h[mi], b_h[ni]);
                    mma16816(acc[mi][ni], a_h[mi], b_l[ni]);
                    mma16816(acc[mi][ni], a_l[mi], b_h[ni]);
                }
        }
        __syncthreads();
    }
    float* C = g_scl + (size_t)z * 128 * 256;
#pragma unroll
    for (int mi = 0; mi < 4; mi++) {
        const int r = wm * 64 + mi * 16 + (lane >> 2);
#pragma unroll
        for (int ni = 0; ni < 4; ni++) {
            const int cc = n0 + wn * 32 + ni * 8 + ((lane & 3) << 1);
            C[(size_t)r * 256 + cc]           = __fmul_rn(acc[mi][ni][0], ATT_SCALE);
            C[(size_t)r * 256 + cc + 1]       = __fmul_rn(acc[mi][ni][1], ATT_SCALE);
            C[(size_t)(r + 8) * 256 + cc]     = __fmul_rn(acc[mi][ni][2], ATT_SCALE);
            C[(size_t)(r + 8) * 256 + cc + 1] = __fmul_rn(acc[mi][ni][3], ATT_SCALE);
        }
    }
}

// ------------------------------------------------------------------
// Local PV: ctx = P[128x256]@V[256x128]; epilogue merges and emits
// merged fp32 + bf16 splits (removes a separate split pass).
// ------------------------------------------------------------------
__global__ void __launch_bounds__(256)
gemm_tc_pv()
{
    __shared__ char smem[4 * 8192];
    const uint32_t sb = smem_u32(smem);
    const uint32_t SP_H = 0, SP_L = 8192, SV_H = 16384, SV_L = 24576;
    const int tid = threadIdx.x;
    const int lane = tid & 31, wid = tid >> 5;
    const int wm = wid >> 2, wn = wid & 3;
    const int z = blockIdx.x;
    const int h = z >> 5, ch = z & 31;
    const int vbase = (ch << 7) - 128;
    const int colV = h * DH;
    const __nv_bfloat16* Ph = g_sph + (size_t)z * 128 * 256;
    const __nv_bfloat16* Pl = g_spl + (size_t)z * 128 * 256;

    float acc[4][4][4];
#pragma unroll
    for (int mi = 0; mi < 4; mi++)
#pragma unroll
        for (int ni = 0; ni < 4; ni++)
#pragma unroll
            for (int t = 0; t < 4; t++) acc[mi][ni][t] = 0.f;

    const int lr = lane & 15, lc = lane >> 4;

    for (int k0 = 0; k0 < 256; k0 += 32) {
#pragma unroll
        for (int i = 0; i < 2; i++) {
            const int idx = tid + (i << 8);
            const int row = idx >> 2, c = idx & 3;
            const uint32_t off = swz(row, c);
            const size_t gp = (size_t)row * 256 + k0 + (c << 3);
            *(uint4*)(smem + SP_H + off) = *(const uint4*)(Ph + gp);
            *(uint4*)(smem + SP_L + off) = *(const uint4*)(Pl + gp);
        }
#pragma unroll
        for (int i = 0; i < 2; i++) {
            const int idx = tid + (i << 8);
            const int row = idx >> 4, c = idx & 15;
            const uint32_t off = vswz(row, c);
            int vr = vbase + k0 + row; if (vr < 0) vr = 0;
            const size_t gv = (size_t)vr * HIDN + colV + (c << 3);
            *(uint4*)(smem + SV_H + off) = *(const uint4*)(g_lvh + gv);
            *(uint4*)(smem + SV_L + off) = *(const uint4*)(g_lvl + gv);
        }
        __syncthreads();
#pragma unroll
        for (int kh = 0; kh < 2; kh++) {
            const int kc = kh * 2 + lc;
            uint32_t a_h[4][4], a_l[4][4];
#pragma unroll
            for (int mi = 0; mi < 4; mi++) {
                const int r = wm * 64 + mi * 16 + lr;
                const uint32_t o = swz(r, kc);
                ldsm4(a_h[mi][0], a_h[mi][1], a_h[mi][2], a_h[mi][3], sb + SP_H + o);
                ldsm4(a_l[mi][0], a_l[mi][1], a_l[mi][2], a_l[mi][3], sb + SP_L + o);
            }
            uint32_t b_h[4][2], b_l[4][2];
#pragma unroll
            for (int j = 0; j < 2; j++) {
                const int krow = kh * 16 + lr;
                const int dchunk = wn * 4 + j * 2 + lc;
                const uint32_t o = vswz(krow, dchunk);
                uint32_t r0, r1, r2, r3;
                ldsm4t(r0, r1, r2, r3, sb + SV_H + o);
                b_h[j * 2][0] = r0; b_h[j * 2][1] = r1;
                b_h[j * 2 + 1][0] = r2; b_h[j * 2 + 1][1] = r3;
                ldsm4t(r0, r1, r2, r3, sb + SV_L + o);
                b_l[j * 2][0] = r0; b_l[j * 2][1] = r1;
                b_l[j * 2 + 1][0] = r2; b_l[j * 2 + 1][1] = r3;
            }
#pragma unroll
            for (int mi = 0; mi < 4; mi++)
#pragma unroll
                for (int ni = 0; ni < 4; ni++) {
                    mma16816(acc[mi][ni], a_h[mi], b_h[ni]);
                    mma16816(acc[mi][ni], a_h[mi], b_l[ni]);
                    mma16816(acc[mi][ni], a_l[mi], b_h[ni]);
                }
        }
        __syncthreads();
    }
#pragma unroll
    for (int mi = 0; mi < 4; mi++) {
        const int r = (ch << 7) + wm * 64 + mi * 16 + (lane >> 2);
#pragma unroll
        for (int ni = 0; ni < 4; ni++) {
            const int cc = colV + wn * 32 + ni * 8 + ((lane & 3) << 1);
            size_t o0 = (size_t)r * HIDN + cc;
            size_t o1 = (size_t)(r + 8) * HIDN + cc;
            float m00 = __fmul_rn(__fadd_rn(g_merged[o0], acc[mi][ni][0]), 0.5f);
            float m01 = __fmul_rn(__fadd_rn(g_merged[o0 + 1], acc[mi][ni][1]), 0.5f);
            float m10 = __fmul_rn(__fadd_rn(g_merged[o1], acc[mi][ni][2]), 0.5f);
            float m11 = __fmul_rn(__fadd_rn(g_merged[o1 + 1], acc[mi][ni][3]), 0.5f);
            g_merged[o0] = m00; g_merged[o0 + 1] = m01;
            g_merged[o1] = m10; g_merged[o1 + 1] = m11;
            split2(m00, g_mrg_h[o0], g_mrg_l[o0]);
            split2(m01, g_mrg_h[o0 + 1], g_mrg_l[o0 + 1]);
            split2(m10, g_mrg_h[o1], g_mrg_l[o1]);
            split2(m11, g_mrg_h[o1 + 1], g_mrg_l[o1 + 1]);
        }
    }
}

// tri-split fp32 -> 3 bf16 components
__global__ void split3_plain(const float* __restrict__ src,
                             __nv_bfloat16* __restrict__ b1, __nv_bfloat16* __restrict__ b2,
                             __nv_bfloat16* __restrict__ b3, int n)
{
    int i = blockIdx.x * blockDim.x + threadIdx.x;
    if (i >= n) return;
    split3v(src[i], b1[i], b2[i], b3[i]);
}

// transpose + split: W [K][N] -> T{h,l} [n][k]
__global__ void tsplit(const float* __restrict__ W,
                       __nv_bfloat16* __restrict__ Th, __nv_bfloat16* __restrict__ Tl)
{
    __shared__ float tile[32][33];
    const int n0 = blockIdx.x << 5, k0 = blockIdx.y << 5;
    const int tx = threadIdx.x & 31, ty = threadIdx.x >> 5;
#pragma unroll
    for (int i = 0; i < 32; i += 8)
        tile[ty + i][tx] = W[(size_t)(k0 + ty + i) * HIDN + n0 + tx];
    __syncthreads();
#pragma unroll
    for (int i = 0; i < 32; i += 8) {
        float x = tile[tx][ty + i];
        size_t o = (size_t)(n0 + ty + i) * HIDN + k0 + tx;
        split2(x, Th[o], Tl[o]);
    }
}

// transpose + tri-split
__global__ void tsplit3(const float* __restrict__ W,
                        __nv_bfloat16* __restrict__ T1, __nv_bfloat16* __restrict__ T2,
                        __nv_bfloat16* __restrict__ T3)
{
    __shared__ float tile[32][33];
    const int n0 = blockIdx.x << 5, k0 = blockIdx.y << 5;
    const int tx = threadIdx.x & 31, ty = threadIdx.x >> 5;
#pragma unroll
    for (int i = 0; i < 32; i += 8)
        tile[ty + i][tx] = W[(size_t)(k0 + ty + i) * HIDN + n0 + tx];
    __syncthreads();
#pragma unroll
    for (int i = 0; i < 32; i += 8) {
        float x = tile[tx][ty + i];
        size_t o = (size_t)(n0 + ty + i) * HIDN + k0 + tx;
        split3v(x, T1[o], T2[o], T3[o]);
    }
}

// ------------------------------------------------------------------
// entries GEMMs (Wk, Wv fused): C[1024][128] = entries @ W + bias.
// Tile 64x64, chunked-Kahan, grid (2, 16, 2) = 64 CTAs (vs 8 before).
// ------------------------------------------------------------------
__global__ __launch_bounds__(256)
void entries_gemm64(const float* __restrict__ Wk, const float* __restrict__ bk,
                    const float* __restrict__ Wv, const float* __restrict__ bv)
{
    const float* W = blockIdx.z ? Wv : Wk;
    const float* bias = blockIdx.z ? bv : bk;
    float* C = blockIdx.z ? g_cv : g_ck;
    const int row0 = blockIdx.y << 6;
    const int col0 = blockIdx.x << 6;

    __shared__ float As[16][64];
    __shared__ float Bs[16][64];
    const int tid = threadIdx.x;
    const int ty = tid >> 4, tx = tid & 15;

    float acc[4][4], cmp[4][4];
#pragma unroll
    for (int i = 0; i < 4; i++)
#pragma unroll
        for (int j = 0; j < 4; j++) { acc[i][j] = 0.f; cmp[i][j] = 0.f; }

    for (int k0 = 0; k0 < HIDN; k0 += 16) {
        {
            int m = tid >> 2, k4 = (tid & 3) << 2;
            float4 v = *(const float4*)(g_entries + (size_t)(row0 + m) * HIDN + k0 + k4);
            As[k4 + 0][m] = v.x; As[k4 + 1][m] = v.y;
            As[k4 + 2][m] = v.z; As[k4 + 3][m] = v.w;
        }
        {
            int kk = tid >> 4, n4 = (tid & 15) << 2;
            *(float4*)&Bs[kk][n4] = *(const float4*)(W + (size_t)(k0 + kk) * DH + col0 + n4);
        }
        __syncthreads();
        float tmp[4][4];
#pragma unroll
        for (int i = 0; i < 4; i++)
#pragma unroll
            for (int j = 0; j < 4; j++) tmp[i][j] = 0.f;
#pragma unroll
        for (int kk = 0; kk < 16; kk++) {
            float ra[4], rb[4];
            *(float4*)&ra[0] = *(const float4*)&As[kk][ty << 2];
            *(float4*)&rb[0] = *(const float4*)&Bs[kk][tx << 2];
#pragma unroll
            for (int i = 0; i < 4; i++)
#pragma unroll
                for (int j = 0; j < 4; j++)
                    tmp[i][j] = __fmaf_rn(ra[i], rb[j], tmp[i][j]);
        }
#pragma unroll
        for (int i = 0; i < 4; i++)
#pragma unroll
            for (int j = 0; j < 4; j++) {
                float y = __fsub_rn(tmp[i][j], cmp[i][j]);
                float t2 = __fadd_rn(acc[i][j], y);
                cmp[i][j] = __fsub_rn(__fsub_rn(t2, acc[i][j]), y);
                acc[i][j] = t2;
            }
        __syncthreads();
    }
#pragma unroll
    for (int i = 0; i < 4; i++) {
        size_t r = row0 + (ty << 2) + i;
#pragma unroll
        for (int j = 0; j < 4; j++) {
            int c = col0 + (tx << 2) + j;
            C[r * DH + c] = __fadd_rn(acc[i][j], bias[c]);
        }
    }
}

// ------------------------------------------------------------------
// rmsnorm + rope, one warp per (row, head) 128-slice, in place,
// with fused bf16 split emission (s3 != null -> tri-split).
// ------------------------------------------------------------------
__global__ void norm_rope(int mode, const float* __restrict__ w,
                          __nv_bfloat16* __restrict__ s1, __nv_bfloat16* __restrict__ s2,
                          __nv_bfloat16* __restrict__ s3)
{
    int gw = (blockIdx.x * blockDim.x + threadIdx.x) >> 5;
    int lane = threadIdx.x & 31;
    float* buf; int rows, heads, rstride, pmul, padd;
    if (mode == 0)      { buf = g_q;  rows = SQ; heads = NHEAD; rstride = HIDN; pmul = 1; padd = 0; }
    else if (mode == 1) { buf = g_lk; rows = SQ; heads = NHEAD; rstride = HIDN; pmul = 1; padd = 0; }
    else                { buf = g_ck; rows = CB; heads = 1;     rstride = DH;   pmul = 4; padd = 3; }
    if (gw >= rows * heads) return;
    int row = gw / heads, h = gw - row * heads;
    size_t base = (size_t)row * rstride + h * DH;
    float* p = buf + base;
    float x0 = p[lane], x1 = p[lane + 32], x2 = p[lane + 64], x3 = p[lane + 96];
    float ss = warp_sum(x0 * x0 + x1 * x1 + x2 * x2 + x3 * x3);
    float mean = __fadd_rn(__fmul_rn(ss, 0.0078125f), 1e-6f);
    float rs = __fdiv_rn(1.0f, __fsqrt_rn(mean));
    x0 = __fmul_rn(__fmul_rn(x0, rs), w[lane]);
    x1 = __fmul_rn(__fmul_rn(x1, rs), w[lane + 32]);
    x2 = __fmul_rn(__fmul_rn(x2, rs), w[lane + 64]);
    x3 = __fmul_rn(__fmul_rn(x3, rs), w[lane + 96]);
    float pf = (float)pow(10000.0, (double)lane * (1.0 / 32.0));
    float invf = __fdiv_rn(1.0f, pf);
    float ang = __fmul_rn((float)(row * pmul + padd), invf);
    float c = (float)cos((double)ang);
    float s = (float)sin((double)ang);
    float n0 = __fsub_rn(__fmul_rn(x0, c), __fmul_rn(x1, s));
    float n1 = __fadd_rn(__fmul_rn(x0, s), __fmul_rn(x1, c));
    p[lane] = n0; p[lane + 32] = n1; p[lane + 64] = x2; p[lane + 96] = x3;
    if (s1) {
        float vals[4] = {n0, n1, x2, x3};
        int offs[4] = {lane, lane + 32, lane + 64, lane + 96};
#pragma unroll
        for (int i = 0; i < 4; i++) {
            size_t o = base + offs[i];
            if (s3) split3v(vals[i], s1[o], s2[o], s3[o]);
            else    split2(vals[i], s1[o], s2[o]);
        }
    }
}

__global__ void cmp_logits(const float* __restrict__ hidden, const float* __restrict__ Wc,
                           const float* __restrict__ bc)
{
    int gw = (blockIdx.x * blockDim.x + threadIdx.x) >> 5;
    int lane = threadIdx.x & 31;
    if (gw >= SQ) return;
    const float* hr = hidden + (size_t)gw * HIDN;
    float acc = 0.f, cmp = 0.f;
    for (int k = lane; k < HIDN; k += 32) {
        float y = __fmaf_rn(hr[k], Wc[k], -cmp);
        float t = __fadd_rn(acc, y);
        cmp = __fsub_rn(__fsub_rn(t, acc), y);
        acc = t;
    }
    acc = warp_sum(acc);
    if (lane == 0) g_wlog[gw] = __fadd_rn(acc, bc[0]);
}

__global__ void entries_kernel(const float* __restrict__ hidden)
{
    int c = blockIdx.x;
    float w0 = g_wlog[c * 4 + 0], w1 = g_wlog[c * 4 + 1];
    float w2 = g_wlog[c * 4 + 2], w3 = g_wlog[c * 4 + 3];
    float m = fmaxf(fmaxf(w0, w1), fmaxf(w2, w3));
    float e0 = (float)exp((double)__fsub_rn(w0, m));
    float e1 = (float)exp((double)__fsub_rn(w1, m));
    float e2 = (float)exp((double)__fsub_rn(w2, m));
    float e3 = (float)exp((double)__fsub_rn(w3, m));
    float sum = __fadd_rn(__fadd_rn(e0, e1), __fadd_rn(e2, e3));
    e0 = __fdiv_rn(e0, sum); e1 = __fdiv_rn(e1, sum);
    e2 = __fdiv_rn(e2, sum); e3 = __fdiv_rn(e3, sum);
    const float* h0 = hidden + (size_t)c * 4 * HIDN;
    float* dst = g_entries + (size_t)c * HIDN;
    for (int j = threadIdx.x; j < HIDN; j += blockDim.x)
        dst[j] = e0 * h0[j] + e1 * h0[HIDN + j] + e2 * h0[2 * HIDN + j] + e3 * h0[3 * HIDN + j];
}

// ------------------------------------------------------------------
// top-8 over causal prefix + softmax + gather cv; writes 1.0*ctx_sparse
// ------------------------------------------------------------------
__global__ void topk_sparse()
{
    int gw = (blockIdx.x * blockDim.x + threadIdx.x) >> 5;
    int lane = threadIdx.x & 31;
    if (gw >= NHEAD * SQ) return;
    int h = gw >> 12;
    int s = gw & (SQ - 1);
    int nc = (s + 1) >> 2;
    const float* row = g_sc + ((size_t)h * SQ + s) * CB;

    float bv[8]; int bi[8];
#pragma unroll
    for (int i = 0; i < 8; i++) { bv[i] = NEGV; bi[i] = -1; }
    for (int c = lane; c < nc; c += 32) {
        float v = row[c];
        if (v > bv[7]) {
            bv[7] = v; bi[7] = c;
#pragma unroll
            for (int j = 7; j > 0; j--) {
                if (bv[j] > bv[j - 1]) {
                    float tv = bv[j]; bv[j] = bv[j - 1]; bv[j - 1] = tv;
                    int txx = bi[j]; bi[j] = bi[j - 1]; bi[j - 1] = txx;
                }
            }
        }
    }
    int ptr = 0;
    float tvv[8]; int tii[8];
#pragma unroll
    for (int t = 0; t < 8; t++) {
        float m = (ptr < 8) ? bv[ptr] : NEGV;
        int mi = (ptr < 8) ? bi[ptr] : 0x7fffffff;
#pragma unroll
        for (int o = 16; o; o >>= 1) {
            float om = __shfl_xor_sync(0xffffffffu, m, o);
            int oi = __shfl_xor_sync(0xffffffffu, mi, o);
            if (om > m || (om == m && oi < mi)) { m = om; mi = oi; }
        }
        tvv[t] = m; tii[t] = mi;
        if (ptr < 8 && bv[ptr] == m && bi[ptr] == mi) ptr++;
    }
    float m0 = tvv[0];
    float e[8]; float sum = 0.f;
#pragma unroll
    for (int t = 0; t < 8; t++) {
        e[t] = (tvv[t] > NEGH) ? (float)exp((double)__fsub_rn(tvv[t], m0)) : 0.f;
        sum += e[t];
    }
    float den = fmaxf(sum, 1e-9f);
    float c0 = 0.f, c1 = 0.f, c2 = 0.f, c3 = 0.f;
#pragma unroll
    for (int t = 0; t < 8; t++) {
        float wgt = __fdiv_rn(e[t], den);
        if (wgt > 0.f) {
            const float* vr = g_cv + (size_t)tii[t] * DH;
            c0 += wgt * vr[lane];      c1 += wgt * vr[lane + 32];
            c2 += wgt * vr[lane + 64]; c3 += wgt * vr[lane + 96];
        }
    }
    float* dst = g_merged + (size_t)s * HIDN + h * DH;
    dst[lane] = c0;      dst[lane + 32] = c1;
    dst[lane + 64] = c2; dst[lane + 96] = c3;
}

// masked softmax over 256 local keys; writes bf16 split probs
__global__ void local_softmax()
{
    int gw = (blockIdx.x * blockDim.x + threadIdx.x) >> 5;
    int lane = threadIdx.x & 31;
    if (gw >= NHEAD * 32 * 128) return;
    int qi = gw & 127;
    int ch = (gw >> 7) & 31;
    const float* rowp = g_scl + (size_t)gw * 256;
    __nv_bfloat16* oh = g_sph + (size_t)gw * 256;
    __nv_bfloat16* ol = g_spl + (size_t)gw * 256;
    int lo = (ch == 0) ? 128 : qi;
    int hi = qi + 128;
    float v[8];
    float m = NEGV;
#pragma unroll
    for (int t = 0; t < 8; t++) {
        int j = lane + (t << 5);
        bool ok = (j >= lo) && (j <= hi);
        v[t] = ok ? rowp[j] : NEGV;
        m = fmaxf(m, v[t]);
    }
    m = warp_max(m);
    float e[8]; float sum = 0.f;
#pragma unroll
    for (int t = 0; t < 8; t++) {
        int j = lane + (t << 5);
        bool ok = (j >= lo) && (j <= hi);
        e[t] = ok ? (float)exp((double)__fsub_rn(v[t], m)) : 0.f;
        sum += e[t];
    }
    sum = warp_sum(sum);
#pragma unroll
    for (int t = 0; t < 8; t++) {
        float p = __fdiv_rn(e[t], sum);
        split2(p, oh[lane + (t << 5)], ol[lane + (t << 5)]);
    }
}

// ------------------------------------------------------------------
extern "C" void kernel_launch(void* const* d_in, const int* in_sizes, int n_in,
                              void* d_out, int out_size)
{
    const float* hidden = (const float*)d_in[0];
    const float* Wq   = (const float*)d_in[1];
    const float* bq   = (const float*)d_in[2];
    const float* Wcmp = (const float*)d_in[3];
    const float* bcmp = (const float*)d_in[4];
    const float* Wk   = (const float*)d_in[5];
    const float* bk   = (const float*)d_in[6];
    const float* Wv   = (const float*)d_in[7];
    const float* bvv  = (const float*)d_in[8];
    const float* Wlk  = (const float*)d_in[9];
    const float* blkb = (const float*)d_in[10];
    const float* Wlv  = (const float*)d_in[11];
    const float* blvb = (const float*)d_in[12];
    const float* qnw  = (const float*)d_in[13];
    const float* knw  = (const float*)d_in[14];
    const float* Wo   = (const float*)d_in[15];
    const float* bo   = (const float*)d_in[16];
    float* out = (float*)d_out;

    static __nv_bfloat16 *hid_h = nullptr, *hid_l, *hid_m, *mrg_h, *mrg_l,
                         *wlk_h, *wlk_l, *wlv_h, *wlv_l, *wo_h, *wo_l,
                         *qh, *ql, *qm, *lkh, *lkl, *lvh, *lvl,
                         *wq1, *wq2, *wq3, *ck1, *ck2, *ck3;
    static float *p_q = nullptr, *p_lk, *p_lv, *p_merged, *p_ck, *p_sc;
    if (!hid_h) {
        cudaGetSymbolAddress((void**)&hid_h, g_hid_h);
        cudaGetSymbolAddress((void**)&hid_l, g_hid_l);
        cudaGetSymbolAddress((void**)&hid_m, g_hid_m);
        cudaGetSymbolAddress((void**)&mrg_h, g_mrg_h);
        cudaGetSymbolAddress((void**)&mrg_l, g_mrg_l);
        cudaGetSymbolAddress((void**)&wlk_h, g_wlk_h);
        cudaGetSymbolAddress((void**)&wlk_l, g_wlk_l);
        cudaGetSymbolAddress((void**)&wlv_h, g_wlv_h);
        cudaGetSymbolAddress((void**)&wlv_l, g_wlv_l);
        cudaGetSymbolAddress((void**)&wo_h, g_wo_h);
        cudaGetSymbolAddress((void**)&wo_l, g_wo_l);
        cudaGetSymbolAddress((void**)&qh, g_qh);
        cudaGetSymbolAddress((void**)&ql, g_ql);
        cudaGetSymbolAddress((void**)&qm, g_qm);
        cudaGetSymbolAddress((void**)&lkh, g_lkh);
        cudaGetSymbolAddress((void**)&lkl, g_lkl);
        cudaGetSymbolAddress((void**)&lvh, g_lvh);
        cudaGetSymbolAddress((void**)&lvl, g_lvl);
        cudaGetSymbolAddress((void**)&wq1, g_wq1);
        cudaGetSymbolAddress((void**)&wq2, g_wq2);
        cudaGetSymbolAddress((void**)&wq3, g_wq3);
        cudaGetSymbolAddress((void**)&ck1, g_ck1);
        cudaGetSymbolAddress((void**)&ck2, g_ck2);
        cudaGetSymbolAddress((void**)&ck3, g_ck3);
        cudaGetSymbolAddress((void**)&p_q, g_q);
        cudaGetSymbolAddress((void**)&p_lk, g_lk);
        cudaGetSymbolAddress((void**)&p_lv, g_lv);
        cudaGetSymbolAddress((void**)&p_merged, g_merged);
        cudaGetSymbolAddress((void**)&p_ck, g_ck);
        cudaGetSymbolAddress((void**)&p_sc, g_sc);
    }

    const int NELT = SQ * HIDN;

    // splits of inputs/weights
    split3_plain<<<(NELT + 255) / 256, 256>>>(hidden, hid_h, hid_m, hid_l, NELT);
    tsplit3<<<dim3(64, 64), 256>>>(Wq, wq1, wq2, wq3);
    tsplit<<<dim3(64, 64), 256>>>(Wlk, wlk_h, wlk_l);
    tsplit<<<dim3(64, 64), 256>>>(Wlv, wlv_h, wlv_l);
    tsplit<<<dim3(64, 64), 256>>>(Wo,  wo_h,  wo_l);

    // Wq: tri-split 6-pass TC with per-K-tile Kahan fold (selection-grade)
    gemm_tc6k<<<dim3(HIDN / 64, SQ / 128, 1), 256>>>(
        hid_h, hid_m, hid_l, wq1, wq2, wq3, bq, p_q,
        HIDN, HIDN, HIDN, HIDN, 0, 0, 1.0f, 0);

    // smooth projections (bf16x3); lv emits bf16 splits fused
    gemm_tc<<<dim3(HIDN / 128, SQ / 128), 256>>>(hid_h, hid_m, wlk_h, wlk_l, blkb, p_lk,
                                                 nullptr, nullptr);
    gemm_tc<<<dim3(HIDN / 128, SQ / 128), 256>>>(hid_h, hid_m, wlv_h, wlv_l, blvb, p_lv,
                                                 lvh, lvl);

    cmp_logits<<<SQ / 8, 256>>>(hidden, Wcmp, bcmp);
    entries_kernel<<<CB, 256>>>(hidden);

    // entries GEMMs: fused Wk+Wv, 64x64 tiles, 64 CTAs (was 2 kernels x 8 CTAs)
    entries_gemm64<<<dim3(2, 16, 2), 256>>>(Wk, bk, Wv, bvv);

    // norm+rope with fused split emission
    norm_rope<<<(SQ * NHEAD) / 8, 256>>>(0, qnw, qh, ql, qm);        // tri-split q
    norm_rope<<<(SQ * NHEAD) / 8, 256>>>(1, knw, lkh, lkl, nullptr); // 2-split lk
    norm_rope<<<CB / 8, 256>>>(2, knw, nullptr, nullptr, nullptr);
    split3_plain<<<(CB * DH + 255) / 256, 256>>>(p_ck, ck1, ck2, ck3, CB * DH);

    // compressed scores: tri-split 6-pass TC + Kahan fold, causal tile skip
    gemm_tc6k<<<dim3(CB / 64, SQ / 128, NHEAD), 256>>>(
        qh, ql, qm, ck1, ck2, ck3, nullptr, p_sc,
        HIDN, DH, CB, DH, (size_t)DH, (size_t)SQ * CB, ATT_SCALE, 1);

    topk_sparse<<<(NHEAD * SQ) / 8, 256>>>();

    // local attention on tensor cores
    gemm_tc_qk<<<dim3(2, NHEAD * 32), 256>>>();
    local_softmax<<<(NHEAD * 32 * 128) / 8, 256>>>();
    gemm_tc_pv<<<NHEAD * 32, 256>>>();   // merges + emits mrg splits

    // output projection on tensor cores
    gemm_tc<<<dim3(HIDN / 128, SQ / 128), 256>>>(mrg_h, mrg_l, wo_h, wo_l, bo, out,
                                                 nullptr, nullptr);
}

// round 13
// speedup vs baseline: 2.1001x; 1.0736x over previous
#include <cuda_runtime.h>
#include <cuda_fp16.h>
#include <math.h>
#include <stdint.h>

#define SQ 4096
#define HIDN 2048
#define NHEAD 16
#define DH 128
#define CB 1024
#define NEGV -1e30f
#define NEGH -5e29f
#define ATT_SCALE 0.08838834764831845f

// ------------- scratch (static __device__ globals; allocation-free) -------------
__device__ float g_q[(size_t)SQ * HIDN];
__device__ float g_lk[(size_t)SQ * HIDN];
__device__ float g_lv[(size_t)SQ * HIDN];
__device__ float g_wlog[SQ];
__device__ float g_entries[(size_t)CB * HIDN];
__device__ float g_ck[CB * DH];
__device__ float g_cv[CB * DH];
__device__ float g_merged[(size_t)SQ * HIDN];
__device__ float g_sc[(size_t)NHEAD * SQ * CB];
__device__ float g_scl[(size_t)NHEAD * 32 * 128 * 256];

// fp16 2-split buffers
__device__ __half g_hid_h[(size_t)SQ * HIDN];
__device__ __half g_hid_l[(size_t)SQ * HIDN];
__device__ __half g_mrg_h[(size_t)SQ * HIDN];
__device__ __half g_mrg_l[(size_t)SQ * HIDN];
__device__ __half g_qh[(size_t)SQ * HIDN];
__device__ __half g_ql[(size_t)SQ * HIDN];
__device__ __half g_lkh[(size_t)SQ * HIDN];
__device__ __half g_lkl[(size_t)SQ * HIDN];
__device__ __half g_lvh[(size_t)SQ * HIDN];
__device__ __half g_lvl[(size_t)SQ * HIDN];
__device__ __half g_ck1[CB * DH];
__device__ __half g_ck2[CB * DH];
__device__ __half g_sph[(size_t)NHEAD * 32 * 128 * 256];
__device__ __half g_spl[(size_t)NHEAD * 32 * 128 * 256];
__device__ __half g_wq1[(size_t)HIDN * HIDN];
__device__ __half g_wq2[(size_t)HIDN * HIDN];
__device__ __half g_wlk_h[(size_t)HIDN * HIDN];
__device__ __half g_wlk_l[(size_t)HIDN * HIDN];
__device__ __half g_wlv_h[(size_t)HIDN * HIDN];
__device__ __half g_wlv_l[(size_t)HIDN * HIDN];
__device__ __half g_wo_h[(size_t)HIDN * HIDN];
__device__ __half g_wo_l[(size_t)HIDN * HIDN];

__device__ __forceinline__ float warp_sum(float v) {
#pragma unroll
    for (int o = 16; o; o >>= 1) v += __shfl_xor_sync(0xffffffffu, v, o);
    return v;
}
__device__ __forceinline__ float warp_max(float v) {
#pragma unroll
    for (int o = 16; o; o >>= 1) v = fmaxf(v, __shfl_xor_sync(0xffffffffu, v, o));
    return v;
}

// ======================= mma.sync helpers (base PTX, sm_80+) =======================
__device__ __forceinline__ uint32_t smem_u32(const void* p) {
    uint32_t a;
    asm("{ .reg .u64 t; cvta.to.shared.u64 t, %1; cvt.u32.u64 %0, t; }" : "=r"(a) : "l"(p));
    return a;
}
__device__ __forceinline__ void ldsm4(uint32_t& r0, uint32_t& r1, uint32_t& r2, uint32_t& r3,
                                      uint32_t addr) {
    asm volatile("ldmatrix.sync.aligned.m8n8.x4.shared.b16 {%0,%1,%2,%3}, [%4];"
                 : "=r"(r0), "=r"(r1), "=r"(r2), "=r"(r3) : "r"(addr));
}
__device__ __forceinline__ void ldsm4t(uint32_t& r0, uint32_t& r1, uint32_t& r2, uint32_t& r3,
                                       uint32_t addr) {
    asm volatile("ldmatrix.sync.aligned.m8n8.x4.trans.shared.b16 {%0,%1,%2,%3}, [%4];"
                 : "=r"(r0), "=r"(r1), "=r"(r2), "=r"(r3) : "r"(addr));
}
// fp16 inputs, fp32 accumulate
__device__ __forceinline__ void mma16816(float* d, const uint32_t* a, const uint32_t* b) {
    asm volatile(
        "mma.sync.aligned.m16n8k16.row.col.f32.f16.f16.f32 "
        "{%0,%1,%2,%3}, {%4,%5,%6,%7}, {%8,%9}, {%0,%1,%2,%3};"
        : "+f"(d[0]), "+f"(d[1]), "+f"(d[2]), "+f"(d[3])
        : "r"(a[0]), "r"(a[1]), "r"(a[2]), "r"(a[3]), "r"(b[0]), "r"(b[1]));
}
__device__ __forceinline__ uint32_t swz(int row, int c) {
    int slot = (((row & 1) << 2) | c) ^ ((row >> 1) & 7);
    return (uint32_t)(((row >> 1) << 7) + (slot << 4));
}
__device__ __forceinline__ uint32_t vswz(int row, int c) {
    return (uint32_t)((row << 8) + ((c ^ (row & 7)) << 4));
}
// fp16 2-split: x = h + l + e, |e| <= 2^-22 |x|
__device__ __forceinline__ void split2(float x, __half& h, __half& l) {
    h = __float2half_rn(x);
    l = __float2half_rn(__fsub_rn(x, __half2float(h)));
}

// ------------------------------------------------------------------
// Selection-grade TC GEMM: fp16 2-split, 4 passes (hh,hl,lh,ll — all
// products exact; residual ~2^-23), Kahan fold of the fp32 accumulator
// every 2 K-tiles (chain noise 2^-24*sqrt(16) ~ 2.4e-7).
// Block 128(m) x 64(n), 8 warps (2m x 4n), warp tile 64x16, K-step 32.
// ------------------------------------------------------------------
__global__ void __launch_bounds__(256)
gemm_tc4k(const __half* __restrict__ A1, const __half* __restrict__ A2,
          const __half* __restrict__ B1, const __half* __restrict__ B2,
          const float* __restrict__ bias, float* __restrict__ C,
          int lda, int ldb, int ldc, int K,
          size_t a_zoff, size_t c_zoff, float scale, int causal)
{
    const int row0 = blockIdx.y << 7;
    const int n0 = blockIdx.x << 6;
    if (causal && n0 >= (row0 >> 2) + 32) return;
    A1 += blockIdx.z * a_zoff; A2 += blockIdx.z * a_zoff;
    C += blockIdx.z * c_zoff;

    __shared__ char smem[2 * 8192 + 2 * 4096];   // A1|A2 [128][32], B1|B2 [64][32]
    const uint32_t sb = smem_u32(smem);
    const uint32_t OB1 = 16384, OB2 = 20480;
    const int tid = threadIdx.x;
    const int lane = tid & 31, wid = tid >> 5;
    const int wm = wid >> 2, wn = wid & 3;

    float acc[4][2][4], cmp[4][2][4], tmp[4][2][4];
#pragma unroll
    for (int mi = 0; mi < 4; mi++)
#pragma unroll
        for (int ni = 0; ni < 2; ni++)
#pragma unroll
            for (int t = 0; t < 4; t++) {
                acc[mi][ni][t] = 0.f; cmp[mi][ni][t] = 0.f; tmp[mi][ni][t] = 0.f;
            }

    const int lr = lane & 15, lc = lane >> 4;

    for (int k0 = 0; k0 < K; k0 += 32) {
#pragma unroll
        for (int i = 0; i < 2; i++) {
            const int idx = tid + (i << 8);
            const int row = idx >> 2, c = idx & 3;
            const uint32_t off = swz(row, c);
            const size_t ga = (size_t)(row0 + row) * lda + k0 + (c << 3);
            *(uint4*)(smem + 0    + off) = *(const uint4*)(A1 + ga);
            *(uint4*)(smem + 8192 + off) = *(const uint4*)(A2 + ga);
        }
        {
            const int row = tid >> 2, c = tid & 3;
            const uint32_t off = swz(row, c);
            const size_t gb = (size_t)(n0 + row) * ldb + k0 + (c << 3);
            *(uint4*)(smem + OB1 + off) = *(const uint4*)(B1 + gb);
            *(uint4*)(smem + OB2 + off) = *(const uint4*)(B2 + gb);
        }
        __syncthreads();

#pragma unroll
        for (int kh = 0; kh < 2; kh++) {
            const int kc = kh * 2 + lc;
            uint32_t a1[4][4], a2[4][4];
#pragma unroll
            for (int mi = 0; mi < 4; mi++) {
                const int r = wm * 64 + mi * 16 + lr;
                const uint32_t o = swz(r, kc);
                ldsm4(a1[mi][0], a1[mi][1], a1[mi][2], a1[mi][3], sb + 0 + o);
                ldsm4(a2[mi][0], a2[mi][1], a2[mi][2], a2[mi][3], sb + 8192 + o);
            }
            uint32_t b1[2][2], b2[2][2];
            {
                const int r = wn * 16 + lr;
                const uint32_t o = swz(r, kc);
                uint32_t r0, r1, r2, r3;
                ldsm4(r0, r1, r2, r3, sb + OB1 + o);
                b1[0][0] = r0; b1[1][0] = r1; b1[0][1] = r2; b1[1][1] = r3;
                ldsm4(r0, r1, r2, r3, sb + OB2 + o);
                b2[0][0] = r0; b2[1][0] = r1; b2[0][1] = r2; b2[1][1] = r3;
            }
#pragma unroll
            for (int mi = 0; mi < 4; mi++)
#pragma unroll
                for (int ni = 0; ni < 2; ni++) {
                    mma16816(tmp[mi][ni], a1[mi], b1[ni]);
                    mma16816(tmp[mi][ni], a1[mi], b2[ni]);
                    mma16816(tmp[mi][ni], a2[mi], b1[ni]);
                    mma16816(tmp[mi][ni], a2[mi], b2[ni]);
                }
        }
        // Kahan fold every 2 K-tiles (and at the end)
        if (((k0 >> 5) & 1) || (k0 + 32 >= K)) {
#pragma unroll
            for (int mi = 0; mi < 4; mi++)
#pragma unroll
                for (int ni = 0; ni < 2; ni++)
#pragma unroll
                    for (int t = 0; t < 4; t++) {
                        float y = __fsub_rn(tmp[mi][ni][t], cmp[mi][ni][t]);
                        float t2 = __fadd_rn(acc[mi][ni][t], y);
                        cmp[mi][ni][t] = __fsub_rn(__fsub_rn(t2, acc[mi][ni][t]), y);
                        acc[mi][ni][t] = t2;
                        tmp[mi][ni][t] = 0.f;
                    }
        }
        __syncthreads();
    }
#pragma unroll
    for (int mi = 0; mi < 4; mi++) {
        const int r = row0 + wm * 64 + mi * 16 + (lane >> 2);
#pragma unroll
        for (int ni = 0; ni < 2; ni++) {
            const int cc = n0 + wn * 16 + ni * 8 + ((lane & 3) << 1);
            if (bias) {
                const float b0 = bias[cc], b1v = bias[cc + 1];
                C[(size_t)r * ldc + cc]           = __fadd_rn(acc[mi][ni][0], b0);
                C[(size_t)r * ldc + cc + 1]       = __fadd_rn(acc[mi][ni][1], b1v);
                C[(size_t)(r + 8) * ldc + cc]     = __fadd_rn(acc[mi][ni][2], b0);
                C[(size_t)(r + 8) * ldc + cc + 1] = __fadd_rn(acc[mi][ni][3], b1v);
            } else {
                C[(size_t)r * ldc + cc]           = __fmul_rn(acc[mi][ni][0], scale);
                C[(size_t)r * ldc + cc + 1]       = __fmul_rn(acc[mi][ni][1], scale);
                C[(size_t)(r + 8) * ldc + cc]     = __fmul_rn(acc[mi][ni][2], scale);
                C[(size_t)(r + 8) * ldc + cc + 1] = __fmul_rn(acc[mi][ni][3], scale);
            }
        }
    }
}

// ------------------------------------------------------------------
// Smooth tensor GEMM fp16 2-split, 3 passes (hh,hl,lh; drop ll~2^-24).
// Block 128x128. Optional fp16 2-split outputs fused into epilogue.
// ------------------------------------------------------------------
__global__ void __launch_bounds__(256)
gemm_tc(const __half* __restrict__ Ah, const __half* __restrict__ Al,
        const __half* __restrict__ Bh, const __half* __restrict__ Bl,
        const float* __restrict__ bias, float* __restrict__ C,
        __half* __restrict__ Sh, __half* __restrict__ Sl)
{
    __shared__ char smem[4 * 8192];
    const uint32_t sb = smem_u32(smem);
    const uint32_t SA_H = 0, SA_L = 8192, SB_H = 16384, SB_L = 24576;
    const int tid = threadIdx.x;
    const int lane = tid & 31, wid = tid >> 5;
    const int wm = wid >> 2, wn = wid & 3;
    const int row0 = blockIdx.y << 7;
    const int n0 = blockIdx.x << 7;

    float acc[4][4][4];
#pragma unroll
    for (int mi = 0; mi < 4; mi++)
#pragma unroll
        for (int ni = 0; ni < 4; ni++)
#pragma unroll
            for (int t = 0; t < 4; t++) acc[mi][ni][t] = 0.f;

    const int lr = lane & 15, lc = lane >> 4;

    for (int k0 = 0; k0 < HIDN; k0 += 32) {
#pragma unroll
        for (int i = 0; i < 2; i++) {
            const int idx = tid + (i << 8);
            const int row = idx >> 2, c = idx & 3;
            const uint32_t off = swz(row, c);
            const size_t ga = (size_t)(row0 + row) * HIDN + k0 + (c << 3);
            const size_t gb = (size_t)(n0 + row) * HIDN + k0 + (c << 3);
            *(uint4*)(smem + SA_H + off) = *(const uint4*)(Ah + ga);
            *(uint4*)(smem + SA_L + off) = *(const uint4*)(Al + ga);
            *(uint4*)(smem + SB_H + off) = *(const uint4*)(Bh + gb);
            *(uint4*)(smem + SB_L + off) = *(const uint4*)(Bl + gb);
        }
        __syncthreads();
#pragma unroll
        for (int kh = 0; kh < 2; kh++) {
            const int kc = kh * 2 + lc;
            uint32_t a_h[4][4], a_l[4][4];
#pragma unroll
            for (int mi = 0; mi < 4; mi++) {
                const int r = wm * 64 + mi * 16 + lr;
                const uint32_t o = swz(r, kc);
                ldsm4(a_h[mi][0], a_h[mi][1], a_h[mi][2], a_h[mi][3], sb + SA_H + o);
                ldsm4(a_l[mi][0], a_l[mi][1], a_l[mi][2], a_l[mi][3], sb + SA_L + o);
            }
            uint32_t b_h[4][2], b_l[4][2];
#pragma unroll
            for (int np = 0; np < 2; np++) {
                const int r = wn * 32 + np * 16 + lr;
                const uint32_t o = swz(r, kc);
                uint32_t r0, r1, r2, r3;
                ldsm4(r0, r1, r2, r3, sb + SB_H + o);
                b_h[np * 2][0] = r0; b_h[np * 2 + 1][0] = r1;
                b_h[np * 2][1] = r2; b_h[np * 2 + 1][1] = r3;
                ldsm4(r0, r1, r2, r3, sb + SB_L + o);
                b_l[np * 2][0] = r0; b_l[np * 2 + 1][0] = r1;
                b_l[np * 2][1] = r2; b_l[np * 2 + 1][1] = r3;
            }
#pragma unroll
            for (int mi = 0; mi < 4; mi++)
#pragma unroll
                for (int ni = 0; ni < 4; ni++) {
                    mma16816(acc[mi][ni], a_h[mi], b_h[ni]);
                    mma16816(acc[mi][ni], a_h[mi], b_l[ni]);
                    mma16816(acc[mi][ni], a_l[mi], b_h[ni]);
                }
        }
        __syncthreads();
    }
#pragma unroll
    for (int mi = 0; mi < 4; mi++) {
        const int r = row0 + wm * 64 + mi * 16 + (lane >> 2);
#pragma unroll
        for (int ni = 0; ni < 4; ni++) {
            const int cc = n0 + wn * 32 + ni * 8 + ((lane & 3) << 1);
            const float b0 = bias[cc], b1 = bias[cc + 1];
            float v00 = __fadd_rn(acc[mi][ni][0], b0);
            float v01 = __fadd_rn(acc[mi][ni][1], b1);
            float v10 = __fadd_rn(acc[mi][ni][2], b0);
            float v11 = __fadd_rn(acc[mi][ni][3], b1);
            size_t o0 = (size_t)r * HIDN + cc;
            size_t o1 = (size_t)(r + 8) * HIDN + cc;
            C[o0] = v00; C[o0 + 1] = v01;
            C[o1] = v10; C[o1 + 1] = v11;
            if (Sh) {
                split2(v00, Sh[o0], Sl[o0]);
                split2(v01, Sh[o0 + 1], Sl[o0 + 1]);
                split2(v10, Sh[o1], Sl[o1]);
                split2(v11, Sh[o1 + 1], Sl[o1 + 1]);
            }
        }
    }
}

// ------------------------------------------------------------------
// Local QK^T: per (h, ch), scores[128 q][256 keys]. fp16 3-pass.
// ------------------------------------------------------------------
__global__ void __launch_bounds__(256)
gemm_tc_qk()
{
    __shared__ char smem[4 * 8192];
    const uint32_t sb = smem_u32(smem);
    const uint32_t SA_H = 0, SA_L = 8192, SB_H = 16384, SB_L = 24576;
    const int tid = threadIdx.x;
    const int lane = tid & 31, wid = tid >> 5;
    const int wm = wid >> 2, wn = wid & 3;
    const int z = blockIdx.y;
    const int h = z >> 5, ch = z & 31;
    const int n0 = blockIdx.x << 7;
    const int b_base = (ch << 7) - 128 + n0;
    const int colA = h * DH;

    float acc[4][4][4];
#pragma unroll
    for (int mi = 0; mi < 4; mi++)
#pragma unroll
        for (int ni = 0; ni < 4; ni++)
#pragma unroll
            for (int t = 0; t < 4; t++) acc[mi][ni][t] = 0.f;

    const int lr = lane & 15, lc = lane >> 4;

    for (int k0 = 0; k0 < DH; k0 += 32) {
#pragma unroll
        for (int i = 0; i < 2; i++) {
            const int idx = tid + (i << 8);
            const int row = idx >> 2, c = idx & 3;
            const uint32_t off = swz(row, c);
            const size_t ga = (size_t)((ch << 7) + row) * HIDN + colA + k0 + (c << 3);
            int br = b_base + row; if (br < 0) br = 0;
            const size_t gb = (size_t)br * HIDN + colA + k0 + (c << 3);
            *(uint4*)(smem + SA_H + off) = *(const uint4*)(g_qh + ga);
            *(uint4*)(smem + SA_L + off) = *(const uint4*)(g_ql + ga);
            *(uint4*)(smem + SB_H + off) = *(const uint4*)(g_lkh + gb);
            *(uint4*)(smem + SB_L + off) = *(const uint4*)(g_lkl + gb);
        }
        __syncthreads();
#pragma unroll
        for (int kh = 0; kh < 2; kh++) {
            const int kc = kh * 2 + lc;
            uint32_t a_h[4][4], a_l[4][4];
#pragma unroll
            for (int mi = 0; mi < 4; mi++) {
                const int r = wm * 64 + mi * 16 + lr;
                const uint32_t o = swz(r, kc);
                ldsm4(a_h[mi][0], a_h[mi][1], a_h[mi][2], a_h[mi][3], sb + SA_H + o);
                ldsm4(a_l[mi][0], a_l[mi][1], a_l[mi][2], a_l[mi][3], sb + SA_L + o);
            }
            uint32_t b_h[4][2], b_l[4][2];
#pragma unroll
            for (int np = 0; np < 2; np++) {
                const int r = wn * 32 + np * 16 + lr;
                const uint32_t o = swz(r, kc);
                uint32_t r0, r1, r2, r3;
                ldsm4(r0, r1, r2, r3, sb + SB_H + o);
                b_h[np * 2][0] = r0; b_h[np * 2 + 1][0] = r1;
                b_h[np * 2][1] = r2; b_h[np * 2 + 1][1] = r3;
                ldsm4(r0, r1, r2, r3, sb + SB_L + o);
                b_l[np * 2][0] = r0; b_l[np * 2 + 1][0] = r1;
                b_l[np * 2][1] = r2; b_l[np * 2 + 1][1] = r3;
            }
#pragma unroll
            for (int mi = 0; mi < 4; mi++)
#pragma unroll
                for (int ni = 0; ni < 4; ni++) {
                    mma16816(acc[mi][ni], a_h[mi], b_h[ni]);
                    mma16816(acc[mi][ni], a_h[mi], b_l[ni]);
                    mma16816(acc[mi][ni], a_l[mi], b_h[ni]);
                }
        }
        __syncthreads();
    }
    float* C = g_scl + (size_t)z * 128 * 256;
#pragma unroll
    for (int mi = 0; mi < 4; mi++) {
        const int r = wm * 64 + mi * 16 + (lane >> 2);
#pragma unroll
        for (int ni = 0; ni < 4; ni++) {
            const int cc = n0 + wn * 32 + ni * 8 + ((lane & 3) << 1);
            C[(size_t)r * 256 + cc]           = __fmul_rn(acc[mi][ni][0], ATT_SCALE);
            C[(size_t)r * 256 + cc + 1]       = __fmul_rn(acc[mi][ni][1], ATT_SCALE);
            C[(size_t)(r + 8) * 256 + cc]     = __fmul_rn(acc[mi][ni][2], ATT_SCALE);
            C[(size_t)(r + 8) * 256 + cc + 1] = __fmul_rn(acc[mi][ni][3], ATT_SCALE);
        }
    }
}

// ------------------------------------------------------------------
// Local PV: ctx = P[128x256]@V[256x128]; merge + emit merged fp16 splits.
// ------------------------------------------------------------------
__global__ void __launch_bounds__(256)
gemm_tc_pv()
{
    __shared__ char smem[4 * 8192];
    const uint32_t sb = smem_u32(smem);
    const uint32_t SP_H = 0, SP_L = 8192, SV_H = 16384, SV_L = 24576;
    const int tid = threadIdx.x;
    const int lane = tid & 31, wid = tid >> 5;
    const int wm = wid >> 2, wn = wid & 3;
    const int z = blockIdx.x;
    const int h = z >> 5, ch = z & 31;
    const int vbase = (ch << 7) - 128;
    const int colV = h * DH;
    const __half* Ph = g_sph + (size_t)z * 128 * 256;
    const __half* Pl = g_spl + (size_t)z * 128 * 256;

    float acc[4][4][4];
#pragma unroll
    for (int mi = 0; mi < 4; mi++)
#pragma unroll
        for (int ni = 0; ni < 4; ni++)
#pragma unroll
            for (int t = 0; t < 4; t++) acc[mi][ni][t] = 0.f;

    const int lr = lane & 15, lc = lane >> 4;

    for (int k0 = 0; k0 < 256; k0 += 32) {
#pragma unroll
        for (int i = 0; i < 2; i++) {
            const int idx = tid + (i << 8);
            const int row = idx >> 2, c = idx & 3;
            const uint32_t off = swz(row, c);
            const size_t gp = (size_t)row * 256 + k0 + (c << 3);
            *(uint4*)(smem + SP_H + off) = *(const uint4*)(Ph + gp);
            *(uint4*)(smem + SP_L + off) = *(const uint4*)(Pl + gp);
        }
#pragma unroll
        for (int i = 0; i < 2; i++) {
            const int idx = tid + (i << 8);
            const int row = idx >> 4, c = idx & 15;
            const uint32_t off = vswz(row, c);
            int vr = vbase + k0 + row; if (vr < 0) vr = 0;
            const size_t gv = (size_t)vr * HIDN + colV + (c << 3);
            *(uint4*)(smem + SV_H + off) = *(const uint4*)(g_lvh + gv);
            *(uint4*)(smem + SV_L + off) = *(const uint4*)(g_lvl + gv);
        }
        __syncthreads();
#pragma unroll
        for (int kh = 0; kh < 2; kh++) {
            const int kc = kh * 2 + lc;
            uint32_t a_h[4][4], a_l[4][4];
#pragma unroll
            for (int mi = 0; mi < 4; mi++) {
                const int r = wm * 64 + mi * 16 + lr;
                const uint32_t o = swz(r, kc);
                ldsm4(a_h[mi][0], a_h[mi][1], a_h[mi][2], a_h[mi][3], sb + SP_H + o);
                ldsm4(a_l[mi][0], a_l[mi][1], a_l[mi][2], a_l[mi][3], sb + SP_L + o);
            }
            uint32_t b_h[4][2], b_l[4][2];
#pragma unroll
            for (int j = 0; j < 2; j++) {
                const int krow = kh * 16 + lr;
                const int dchunk = wn * 4 + j * 2 + lc;
                const uint32_t o = vswz(krow, dchunk);
                uint32_t r0, r1, r2, r3;
                ldsm4t(r0, r1, r2, r3, sb + SV_H + o);
                b_h[j * 2][0] = r0; b_h[j * 2][1] = r1;
                b_h[j * 2 + 1][0] = r2; b_h[j * 2 + 1][1] = r3;
                ldsm4t(r0, r1, r2, r3, sb + SV_L + o);
                b_l[j * 2][0] = r0; b_l[j * 2][1] = r1;
                b_l[j * 2 + 1][0] = r2; b_l[j * 2 + 1][1] = r3;
            }
#pragma unroll
            for (int mi = 0; mi < 4; mi++)
#pragma unroll
                for (int ni = 0; ni < 4; ni++) {
                    mma16816(acc[mi][ni], a_h[mi], b_h[ni]);
                    mma16816(acc[mi][ni], a_h[mi], b_l[ni]);
                    mma16816(acc[mi][ni], a_l[mi], b_h[ni]);
                }
        }
        __syncthreads();
    }
#pragma unroll
    for (int mi = 0; mi < 4; mi++) {
        const int r = (ch << 7) + wm * 64 + mi * 16 + (lane >> 2);
#pragma unroll
        for (int ni = 0; ni < 4; ni++) {
            const int cc = colV + wn * 32 + ni * 8 + ((lane & 3) << 1);
            size_t o0 = (size_t)r * HIDN + cc;
            size_t o1 = (size_t)(r + 8) * HIDN + cc;
            float m00 = __fmul_rn(__fadd_rn(g_merged[o0], acc[mi][ni][0]), 0.5f);
            float m01 = __fmul_rn(__fadd_rn(g_merged[o0 + 1], acc[mi][ni][1]), 0.5f);
            float m10 = __fmul_rn(__fadd_rn(g_merged[o1], acc[mi][ni][2]), 0.5f);
            float m11 = __fmul_rn(__fadd_rn(g_merged[o1 + 1], acc[mi][ni][3]), 0.5f);
            g_merged[o0] = m00; g_merged[o0 + 1] = m01;
            g_merged[o1] = m10; g_merged[o1 + 1] = m11;
            split2(m00, g_mrg_h[o0], g_mrg_l[o0]);
            split2(m01, g_mrg_h[o0 + 1], g_mrg_l[o0 + 1]);
            split2(m10, g_mrg_h[o1], g_mrg_l[o1]);
            split2(m11, g_mrg_h[o1 + 1], g_mrg_l[o1 + 1]);
        }
    }
}

// plain 2-split
__global__ void split2_plain(const float* __restrict__ src,
                             __half* __restrict__ h, __half* __restrict__ l, int n)
{
    int i = blockIdx.x * blockDim.x + threadIdx.x;
    if (i >= n) return;
    split2(src[i], h[i], l[i]);
}

// transpose + 2-split: W [K][N] -> T{h,l} [n][k]
__global__ void tsplit(const float* __restrict__ W,
                       __half* __restrict__ Th, __half* __restrict__ Tl)
{
    __shared__ float tile[32][33];
    const int n0 = blockIdx.x << 5, k0 = blockIdx.y << 5;
    const int tx = threadIdx.x & 31, ty = threadIdx.x >> 5;
#pragma unroll
    for (int i = 0; i < 32; i += 8)
        tile[ty + i][tx] = W[(size_t)(k0 + ty + i) * HIDN + n0 + tx];
    __syncthreads();
#pragma unroll
    for (int i = 0; i < 32; i += 8) {
        float x = tile[tx][ty + i];
        size_t o = (size_t)(n0 + ty + i) * HIDN + k0 + tx;
        split2(x, Th[o], Tl[o]);
    }
}

// ------------------------------------------------------------------
// entries GEMMs (Wk, Wv fused): tile 64x64, chunked-Kahan, 64 CTAs.
// ------------------------------------------------------------------
__global__ __launch_bounds__(256)
void entries_gemm64(const float* __restrict__ Wk, const float* __restrict__ bk,
                    const float* __restrict__ Wv, const float* __restrict__ bv)
{
    const float* W = blockIdx.z ? Wv : Wk;
    const float* bias = blockIdx.z ? bv : bk;
    float* C = blockIdx.z ? g_cv : g_ck;
    const int row0 = blockIdx.y << 6;
    const int col0 = blockIdx.x << 6;

    __shared__ float As[16][64];
    __shared__ float Bs[16][64];
    const int tid = threadIdx.x;
    const int ty = tid >> 4, tx = tid & 15;

    float acc[4][4], cmp[4][4];
#pragma unroll
    for (int i = 0; i < 4; i++)
#pragma unroll
        for (int j = 0; j < 4; j++) { acc[i][j] = 0.f; cmp[i][j] = 0.f; }

    for (int k0 = 0; k0 < HIDN; k0 += 16) {
        {
            int m = tid >> 2, k4 = (tid & 3) << 2;
            float4 v = *(const float4*)(g_entries + (size_t)(row0 + m) * HIDN + k0 + k4);
            As[k4 + 0][m] = v.x; As[k4 + 1][m] = v.y;
            As[k4 + 2][m] = v.z; As[k4 + 3][m] = v.w;
        }
        {
            int kk = tid >> 4, n4 = (tid & 15) << 2;
            *(float4*)&Bs[kk][n4] = *(const float4*)(W + (size_t)(k0 + kk) * DH + col0 + n4);
        }
        __syncthreads();
        float tmp[4][4];
#pragma unroll
        for (int i = 0; i < 4; i++)
#pragma unroll
            for (int j = 0; j < 4; j++) tmp[i][j] = 0.f;
#pragma unroll
        for (int kk = 0; kk < 16; kk++) {
            float ra[4], rb[4];
            *(float4*)&ra[0] = *(const float4*)&As[kk][ty << 2];
            *(float4*)&rb[0] = *(const float4*)&Bs[kk][tx << 2];
#pragma unroll
            for (int i = 0; i < 4; i++)
#pragma unroll
                for (int j = 0; j < 4; j++)
                    tmp[i][j] = __fmaf_rn(ra[i], rb[j], tmp[i][j]);
        }
#pragma unroll
        for (int i = 0; i < 4; i++)
#pragma unroll
            for (int j = 0; j < 4; j++) {
                float y = __fsub_rn(tmp[i][j], cmp[i][j]);
                float t2 = __fadd_rn(acc[i][j], y);
                cmp[i][j] = __fsub_rn(__fsub_rn(t2, acc[i][j]), y);
                acc[i][j] = t2;
            }
        __syncthreads();
    }
#pragma unroll
    for (int i = 0; i < 4; i++) {
        size_t r = row0 + (ty << 2) + i;
#pragma unroll
        for (int j = 0; j < 4; j++) {
            int c = col0 + (tx << 2) + j;
            C[r * DH + c] = __fadd_rn(acc[i][j], bias[c]);
        }
    }
}

// ------------------------------------------------------------------
// rmsnorm + rope with fused fp16 2-split emission.
// ------------------------------------------------------------------
__global__ void norm_rope(int mode, const float* __restrict__ w,
                          __half* __restrict__ s1, __half* __restrict__ s2)
{
    int gw = (blockIdx.x * blockDim.x + threadIdx.x) >> 5;
    int lane = threadIdx.x & 31;
    float* buf; int rows, heads, rstride, pmul, padd;
    if (mode == 0)      { buf = g_q;  rows = SQ; heads = NHEAD; rstride = HIDN; pmul = 1; padd = 0; }
    else if (mode == 1) { buf = g_lk; rows = SQ; heads = NHEAD; rstride = HIDN; pmul = 1; padd = 0; }
    else                { buf = g_ck; rows = CB; heads = 1;     rstride = DH;   pmul = 4; padd = 3; }
    if (gw >= rows * heads) return;
    int row = gw / heads, h = gw - row * heads;
    size_t base = (size_t)row * rstride + h * DH;
    float* p = buf + base;
    float x0 = p[lane], x1 = p[lane + 32], x2 = p[lane + 64], x3 = p[lane + 96];
    float ss = warp_sum(x0 * x0 + x1 * x1 + x2 * x2 + x3 * x3);
    float mean = __fadd_rn(__fmul_rn(ss, 0.0078125f), 1e-6f);
    float rs = __fdiv_rn(1.0f, __fsqrt_rn(mean));
    x0 = __fmul_rn(__fmul_rn(x0, rs), w[lane]);
    x1 = __fmul_rn(__fmul_rn(x1, rs), w[lane + 32]);
    x2 = __fmul_rn(__fmul_rn(x2, rs), w[lane + 64]);
    x3 = __fmul_rn(__fmul_rn(x3, rs), w[lane + 96]);
    float pf = (float)pow(10000.0, (double)lane * (1.0 / 32.0));
    float invf = __fdiv_rn(1.0f, pf);
    float ang = __fmul_rn((float)(row * pmul + padd), invf);
    float c = (float)cos((double)ang);
    float s = (float)sin((double)ang);
    float n0 = __fsub_rn(__fmul_rn(x0, c), __fmul_rn(x1, s));
    float n1 = __fadd_rn(__fmul_rn(x0, s), __fmul_rn(x1, c));
    p[lane] = n0; p[lane + 32] = n1; p[lane + 64] = x2; p[lane + 96] = x3;
    if (s1) {
        float vals[4] = {n0, n1, x2, x3};
        int offs[4] = {lane, lane + 32, lane + 64, lane + 96};
#pragma unroll
        for (int i = 0; i < 4; i++) {
            size_t o = base + offs[i];
            split2(vals[i], s1[o], s2[o]);
        }
    }
}

__global__ void cmp_logits(const float* __restrict__ hidden, const float* __restrict__ Wc,
                           const float* __restrict__ bc)
{
    int gw = (blockIdx.x * blockDim.x + threadIdx.x) >> 5;
    int lane = threadIdx.x & 31;
    if (gw >= SQ) return;
    const float* hr = hidden + (size_t)gw * HIDN;
    float acc = 0.f, cmp = 0.f;
    for (int k = lane; k < HIDN; k += 32) {
        float y = __fmaf_rn(hr[k], Wc[k], -cmp);
        float t = __fadd_rn(acc, y);
        cmp = __fsub_rn(__fsub_rn(t, acc), y);
        acc = t;
    }
    acc = warp_sum(acc);
    if (lane == 0) g_wlog[gw] = __fadd_rn(acc, bc[0]);
}

__global__ void entries_kernel(const float* __restrict__ hidden)
{
    int c = blockIdx.x;
    float w0 = g_wlog[c * 4 + 0], w1 = g_wlog[c * 4 + 1];
    float w2 = g_wlog[c * 4 + 2], w3 = g_wlog[c * 4 + 3];
    float m = fmaxf(fmaxf(w0, w1), fmaxf(w2, w3));
    float e0 = (float)exp((double)__fsub_rn(w0, m));
    float e1 = (float)exp((double)__fsub_rn(w1, m));
    float e2 = (float)exp((double)__fsub_rn(w2, m));
    float e3 = (float)exp((double)__fsub_rn(w3, m));
    float sum = __fadd_rn(__fadd_rn(e0, e1), __fadd_rn(e2, e3));
    e0 = __fdiv_rn(e0, sum); e1 = __fdiv_rn(e1, sum);
    e2 = __fdiv_rn(e2, sum); e3 = __fdiv_rn(e3, sum);
    const float* h0 = hidden + (size_t)c * 4 * HIDN;
    float* dst = g_entries + (size_t)c * HIDN;
    for (int j = threadIdx.x; j < HIDN; j += blockDim.x)
        dst[j] = e0 * h0[j] + e1 * h0[HIDN + j] + e2 * h0[2 * HIDN + j] + e3 * h0[3 * HIDN + j];
}

// ------------------------------------------------------------------
// top-8 over causal prefix + softmax + gather cv; writes 1.0*ctx_sparse
// ------------------------------------------------------------------
__global__ void topk_sparse()
{
    int gw = (blockIdx.x * blockDim.x + threadIdx.x) >> 5;
    int lane = threadIdx.x & 31;
    if (gw >= NHEAD * SQ) return;
    int h = gw >> 12;
    int s = gw & (SQ - 1);
    int nc = (s + 1) >> 2;
    const float* row = g_sc + ((size_t)h * SQ + s) * CB;

    float bv[8]; int bi[8];
#pragma unroll
    for (int i = 0; i < 8; i++) { bv[i] = NEGV; bi[i] = -1; }
    for (int c = lane; c < nc; c += 32) {
        float v = row[c];
        if (v > bv[7]) {
            bv[7] = v; bi[7] = c;
#pragma unroll
            for (int j = 7; j > 0; j--) {
                if (bv[j] > bv[j - 1]) {
                    float tv = bv[j]; bv[j] = bv[j - 1]; bv[j - 1] = tv;
                    int txx = bi[j]; bi[j] = bi[j - 1]; bi[j - 1] = txx;
                }
            }
        }
    }
    int ptr = 0;
    float tvv[8]; int tii[8];
#pragma unroll
    for (int t = 0; t < 8; t++) {
        float m = (ptr < 8) ? bv[ptr] : NEGV;
        int mi = (ptr < 8) ? bi[ptr] : 0x7fffffff;
#pragma unroll
        for (int o = 16; o; o >>= 1) {
            float om = __shfl_xor_sync(0xffffffffu, m, o);
            int oi = __shfl_xor_sync(0xffffffffu, mi, o);
            if (om > m || (om == m && oi < mi)) { m = om; mi = oi; }
        }
        tvv[t] = m; tii[t] = mi;
        if (ptr < 8 && bv[ptr] == m && bi[ptr] == mi) ptr++;
    }
    float m0 = tvv[0];
    float e[8]; float sum = 0.f;
#pragma unroll
    for (int t = 0; t < 8; t++) {
        e[t] = (tvv[t] > NEGH) ? (float)exp((double)__fsub_rn(tvv[t], m0)) : 0.f;
        sum += e[t];
    }
    float den = fmaxf(sum, 1e-9f);
    float c0 = 0.f, c1 = 0.f, c2 = 0.f, c3 = 0.f;
#pragma unroll
    for (int t = 0; t < 8; t++) {
        float wgt = __fdiv_rn(e[t], den);
        if (wgt > 0.f) {
            const float* vr = g_cv + (size_t)tii[t] * DH;
            c0 += wgt * vr[lane];      c1 += wgt * vr[lane + 32];
            c2 += wgt * vr[lane + 64]; c3 += wgt * vr[lane + 96];
        }
    }
    float* dst = g_merged + (size_t)s * HIDN + h * DH;
    dst[lane] = c0;      dst[lane + 32] = c1;
    dst[lane + 64] = c2; dst[lane + 96] = c3;
}

// masked softmax over 256 local keys; writes fp16 split probs
__global__ void local_softmax()
{
    int gw = (blockIdx.x * blockDim.x + threadIdx.x) >> 5;
    int lane = threadIdx.x & 31;
    if (gw >= NHEAD * 32 * 128) return;
    int qi = gw & 127;
    int ch = (gw >> 7) & 31;
    const float* rowp = g_scl + (size_t)gw * 256;
    __half* oh = g_sph + (size_t)gw * 256;
    __half* ol = g_spl + (size_t)gw * 256;
    int lo = (ch == 0) ? 128 : qi;
    int hi = qi + 128;
    float v[8];
    float m = NEGV;
#pragma unroll
    for (int t = 0; t < 8; t++) {
        int j = lane + (t << 5);
        bool ok = (j >= lo) && (j <= hi);
        v[t] = ok ? rowp[j] : NEGV;
        m = fmaxf(m, v[t]);
    }
    m = warp_max(m);
    float e[8]; float sum = 0.f;
#pragma unroll
    for (int t = 0; t < 8; t++) {
        int j = lane + (t << 5);
        bool ok = (j >= lo) && (j <= hi);
        e[t] = ok ? (float)exp((double)__fsub_rn(v[t], m)) : 0.f;
        sum += e[t];
    }
    sum = warp_sum(sum);
#pragma unroll
    for (int t = 0; t < 8; t++) {
        float p = __fdiv_rn(e[t], sum);
        split2(p, oh[lane + (t << 5)], ol[lane + (t << 5)]);
    }
}

// ------------------------------------------------------------------
extern "C" void kernel_launch(void* const* d_in, const int* in_sizes, int n_in,
                              void* d_out, int out_size)
{
    const float* hidden = (const float*)d_in[0];
    const float* Wq   = (const float*)d_in[1];
    const float* bq   = (const float*)d_in[2];
    const float* Wcmp = (const float*)d_in[3];
    const float* bcmp = (const float*)d_in[4];
    const float* Wk   = (const float*)d_in[5];
    const float* bk   = (const float*)d_in[6];
    const float* Wv   = (const float*)d_in[7];
    const float* bvv  = (const float*)d_in[8];
    const float* Wlk  = (const float*)d_in[9];
    const float* blkb = (const float*)d_in[10];
    const float* Wlv  = (const float*)d_in[11];
    const float* blvb = (const float*)d_in[12];
    const float* qnw  = (const float*)d_in[13];
    const float* knw  = (const float*)d_in[14];
    const float* Wo   = (const float*)d_in[15];
    const float* bo   = (const float*)d_in[16];
    float* out = (float*)d_out;

    static __half *hid_h = nullptr, *hid_l, *mrg_h, *mrg_l,
                  *wlk_h, *wlk_l, *wlv_h, *wlv_l, *wo_h, *wo_l,
                  *qh, *ql, *lkh, *lkl, *lvh, *lvl,
                  *wq1, *wq2, *ck1, *ck2;
    static float *p_q = nullptr, *p_lk, *p_lv, *p_merged, *p_ck, *p_sc;
    if (!hid_h) {
        cudaGetSymbolAddress((void**)&hid_h, g_hid_h);
        cudaGetSymbolAddress((void**)&hid_l, g_hid_l);
        cudaGetSymbolAddress((void**)&mrg_h, g_mrg_h);
        cudaGetSymbolAddress((void**)&mrg_l, g_mrg_l);
        cudaGetSymbolAddress((void**)&wlk_h, g_wlk_h);
        cudaGetSymbolAddress((void**)&wlk_l, g_wlk_l);
        cudaGetSymbolAddress((void**)&wlv_h, g_wlv_h);
        cudaGetSymbolAddress((void**)&wlv_l, g_wlv_l);
        cudaGetSymbolAddress((void**)&wo_h, g_wo_h);
        cudaGetSymbolAddress((void**)&wo_l, g_wo_l);
        cudaGetSymbolAddress((void**)&qh, g_qh);
        cudaGetSymbolAddress((void**)&ql, g_ql);
        cudaGetSymbolAddress((void**)&lkh, g_lkh);
        cudaGetSymbolAddress((void**)&lkl, g_lkl);
        cudaGetSymbolAddress((void**)&lvh, g_lvh);
        cudaGetSymbolAddress((void**)&lvl, g_lvl);
        cudaGetSymbolAddress((void**)&wq1, g_wq1);
        cudaGetSymbolAddress((void**)&wq2, g_wq2);
        cudaGetSymbolAddress((void**)&ck1, g_ck1);
        cudaGetSymbolAddress((void**)&ck2, g_ck2);
        cudaGetSymbolAddress((void**)&p_q, g_q);
        cudaGetSymbolAddress((void**)&p_lk, g_lk);
        cudaGetSymbolAddress((void**)&p_lv, g_lv);
        cudaGetSymbolAddress((void**)&p_merged, g_merged);
        cudaGetSymbolAddress((void**)&p_ck, g_ck);
        cudaGetSymbolAddress((void**)&p_sc, g_sc);
    }

    const int NELT = SQ * HIDN;

    // splits of inputs/weights (all fp16 2-split)
    split2_plain<<<(NELT + 255) / 256, 256>>>(hidden, hid_h, hid_l, NELT);
    tsplit<<<dim3(64, 64), 256>>>(Wq,  wq1,  wq2);
    tsplit<<<dim3(64, 64), 256>>>(Wlk, wlk_h, wlk_l);
    tsplit<<<dim3(64, 64), 256>>>(Wlv, wlv_h, wlv_l);
    tsplit<<<dim3(64, 64), 256>>>(Wo,  wo_h,  wo_l);

    // Wq: fp16 2-split 4-pass TC + Kahan fold (selection-grade)
    gemm_tc4k<<<dim3(HIDN / 64, SQ / 128, 1), 256>>>(
        hid_h, hid_l, wq1, wq2, bq, p_q,
        HIDN, HIDN, HIDN, HIDN, 0, 0, 1.0f, 0);

    // smooth projections (fp16 3-pass); lv emits fp16 splits fused
    gemm_tc<<<dim3(HIDN / 128, SQ / 128), 256>>>(hid_h, hid_l, wlk_h, wlk_l, blkb, p_lk,
                                                 nullptr, nullptr);
    gemm_tc<<<dim3(HIDN / 128, SQ / 128), 256>>>(hid_h, hid_l, wlv_h, wlv_l, blvb, p_lv,
                                                 lvh, lvl);

    cmp_logits<<<SQ / 8, 256>>>(hidden, Wcmp, bcmp);
    entries_kernel<<<CB, 256>>>(hidden);

    // entries GEMMs: fused Wk+Wv, 64x64 tiles, 64 CTAs
    entries_gemm64<<<dim3(2, 16, 2), 256>>>(Wk, bk, Wv, bvv);

    // norm+rope with fused split emission
    norm_rope<<<(SQ * NHEAD) / 8, 256>>>(0, qnw, qh, ql);
    norm_rope<<<(SQ * NHEAD) / 8, 256>>>(1, knw, lkh, lkl);
    norm_rope<<<CB / 8, 256>>>(2, knw, ck1, ck2);

    // compressed scores: fp16 4-pass TC + Kahan fold, causal tile skip
    gemm_tc4k<<<dim3(CB / 64, SQ / 128, NHEAD), 256>>>(
        qh, ql, ck1, ck2, nullptr, p_sc,
        HIDN, DH, CB, DH, (size_t)DH, (size_t)SQ * CB, ATT_SCALE, 1);

    topk_sparse<<<(NHEAD * SQ) / 8, 256>>>();

    // local attention on tensor cores
    gemm_tc_qk<<<dim3(2, NHEAD * 32), 256>>>();
    local_softmax<<<(NHEAD * 32 * 128) / 8, 256>>>();
    gemm_tc_pv<<<NHEAD * 32, 256>>>();   // merges + emits mrg splits

    // output projection on tensor cores
    gemm_tc<<<dim3(HIDN / 128, SQ / 128), 256>>>(mrg_h, mrg_l, wo_h, wo_l, bo, out,
                                                 nullptr, nullptr);
}

// round 14
// speedup vs baseline: 2.2989x; 1.0947x over previous
#include <cuda_runtime.h>
#include <cuda_fp16.h>
#include <math.h>
#include <stdint.h>

#define SQ 4096
#define HIDN 2048
#define NHEAD 16
#define DH 128
#define CB 1024
#define NEGV -1e30f
#define NEGH -5e29f
#define ATT_SCALE 0.08838834764831845f

// ------------- scratch (static __device__ globals; allocation-free) -------------
__device__ float g_q[(size_t)SQ * HIDN];
__device__ float g_lk[(size_t)SQ * HIDN];
__device__ float g_lv[(size_t)SQ * HIDN];
__device__ float g_wlog[SQ];
__device__ float g_entries[(size_t)CB * HIDN];
__device__ float g_ck[CB * DH];
__device__ float g_cv[CB * DH];
__device__ float g_merged[(size_t)SQ * HIDN];
__device__ float g_sc[(size_t)NHEAD * SQ * CB];
__device__ float g_scl[(size_t)NHEAD * 32 * 128 * 256];

// fp16 2-split buffers
__device__ __half g_hid_h[(size_t)SQ * HIDN];
__device__ __half g_hid_l[(size_t)SQ * HIDN];
__device__ __half g_mrg_h[(size_t)SQ * HIDN];
__device__ __half g_mrg_l[(size_t)SQ * HIDN];
__device__ __half g_qh[(size_t)SQ * HIDN];
__device__ __half g_ql[(size_t)SQ * HIDN];
__device__ __half g_lkh[(size_t)SQ * HIDN];
__device__ __half g_lkl[(size_t)SQ * HIDN];
__device__ __half g_lvh[(size_t)SQ * HIDN];
__device__ __half g_lvl[(size_t)SQ * HIDN];
__device__ __half g_ck1[CB * DH];
__device__ __half g_ck2[CB * DH];
__device__ __half g_sph[(size_t)NHEAD * 32 * 128 * 256];
__device__ __half g_spl[(size_t)NHEAD * 32 * 128 * 256];
__device__ __half g_wq1[(size_t)HIDN * HIDN];
__device__ __half g_wq2[(size_t)HIDN * HIDN];
__device__ __half g_wlk_h[(size_t)HIDN * HIDN];
__device__ __half g_wlk_l[(size_t)HIDN * HIDN];
__device__ __half g_wlv_h[(size_t)HIDN * HIDN];
__device__ __half g_wlv_l[(size_t)HIDN * HIDN];
__device__ __half g_wo_h[(size_t)HIDN * HIDN];
__device__ __half g_wo_l[(size_t)HIDN * HIDN];

__device__ __forceinline__ float warp_sum(float v) {
#pragma unroll
    for (int o = 16; o; o >>= 1) v += __shfl_xor_sync(0xffffffffu, v, o);
    return v;
}
__device__ __forceinline__ float warp_max(float v) {
#pragma unroll
    for (int o = 16; o; o >>= 1) v = fmaxf(v, __shfl_xor_sync(0xffffffffu, v, o));
    return v;
}

// ======================= mma.sync helpers (base PTX, sm_80+) =======================
__device__ __forceinline__ uint32_t smem_u32(const void* p) {
    uint32_t a;
    asm("{ .reg .u64 t; cvta.to.shared.u64 t, %1; cvt.u32.u64 %0, t; }" : "=r"(a) : "l"(p));
    return a;
}
__device__ __forceinline__ void ldsm4(uint32_t& r0, uint32_t& r1, uint32_t& r2, uint32_t& r3,
                                      uint32_t addr) {
    asm volatile("ldmatrix.sync.aligned.m8n8.x4.shared.b16 {%0,%1,%2,%3}, [%4];"
                 : "=r"(r0), "=r"(r1), "=r"(r2), "=r"(r3) : "r"(addr));
}
__device__ __forceinline__ void ldsm4t(uint32_t& r0, uint32_t& r1, uint32_t& r2, uint32_t& r3,
                                       uint32_t addr) {
    asm volatile("ldmatrix.sync.aligned.m8n8.x4.trans.shared.b16 {%0,%1,%2,%3}, [%4];"
                 : "=r"(r0), "=r"(r1), "=r"(r2), "=r"(r3) : "r"(addr));
}
__device__ __forceinline__ void mma16816(float* d, const uint32_t* a, const uint32_t* b) {
    asm volatile(
        "mma.sync.aligned.m16n8k16.row.col.f32.f16.f16.f32 "
        "{%0,%1,%2,%3}, {%4,%5,%6,%7}, {%8,%9}, {%0,%1,%2,%3};"
        : "+f"(d[0]), "+f"(d[1]), "+f"(d[2]), "+f"(d[3])
        : "r"(a[0]), "r"(a[1]), "r"(a[2]), "r"(a[3]), "r"(b[0]), "r"(b[1]));
}
// cp.async (Ampere+ base PTX)
__device__ __forceinline__ void cp16(uint32_t dst, const void* src) {
    asm volatile("cp.async.cg.shared.global [%0], [%1], 16;" :: "r"(dst), "l"(src) : "memory");
}
#define CP_COMMIT() asm volatile("cp.async.commit_group;" ::: "memory")
#define CP_WAIT1() asm volatile("cp.async.wait_group 1;" ::: "memory")
#define CP_WAIT0() asm volatile("cp.async.wait_group 0;" ::: "memory")

__device__ __forceinline__ uint32_t swz(int row, int c) {
    int slot = (((row & 1) << 2) | c) ^ ((row >> 1) & 7);
    return (uint32_t)(((row >> 1) << 7) + (slot << 4));
}
__device__ __forceinline__ uint32_t vswz(int row, int c) {
    return (uint32_t)((row << 8) + ((c ^ (row & 7)) << 4));
}
// fp16 2-split: x = h + l + e, |e| <= 2^-22 |x|
__device__ __forceinline__ void split2(float x, __half& h, __half& l) {
    h = __float2half_rn(x);
    l = __float2half_rn(__fsub_rn(x, __half2float(h)));
}

extern __shared__ char dynsmem[];

// ------------------------------------------------------------------
// Selection-grade TC GEMM: fp16 2-split, 4 passes + Kahan fold every
// 2 K-tiles. Block 128x64, 8 warps, K-step 32.
// cp.async double-buffered (2 stages x 24 KB dynamic smem).
// ------------------------------------------------------------------
__global__ void __launch_bounds__(256)
gemm_tc4k(const __half* __restrict__ A1, const __half* __restrict__ A2,
          const __half* __restrict__ B1, const __half* __restrict__ B2,
          const float* __restrict__ bias, float* __restrict__ C,
          int lda, int ldb, int ldc, int K,
          size_t a_zoff, size_t c_zoff, float scale, int causal)
{
    const int row0 = blockIdx.y << 7;
    const int n0 = blockIdx.x << 6;
    if (causal && n0 >= (row0 >> 2) + 32) return;
    A1 += blockIdx.z * a_zoff; A2 += blockIdx.z * a_zoff;
    C += blockIdx.z * c_zoff;

    const uint32_t sb = smem_u32(dynsmem);
    const int tid = threadIdx.x;
    const int lane = tid & 31, wid = tid >> 5;
    const int wm = wid >> 2, wn = wid & 3;
    const int nt = K >> 5;

    // stage layout (24576 B): A1 0 | A2 8192 | B1 16384 | B2 20480
    auto stage_load = [&](int t) {
        const int k0 = t << 5;
        const uint32_t st = (uint32_t)(t & 1) * 24576u;
#pragma unroll
        for (int i = 0; i < 2; i++) {
            const int idx = tid + (i << 8);
            const int row = idx >> 2, c = idx & 3;
            const uint32_t off = st + swz(row, c);
            const size_t ga = (size_t)(row0 + row) * lda + k0 + (c << 3);
            cp16(sb + off, A1 + ga);
            cp16(sb + off + 8192, A2 + ga);
        }
        {
            const int row = tid >> 2, c = tid & 3;
            const uint32_t off = st + swz(row, c);
            const size_t gb = (size_t)(n0 + row) * ldb + k0 + (c << 3);
            cp16(sb + off + 16384, B1 + gb);
            cp16(sb + off + 20480, B2 + gb);
        }
        CP_COMMIT();
    };

    float acc[4][2][4], cmp[4][2][4], tmp[4][2][4];
#pragma unroll
    for (int mi = 0; mi < 4; mi++)
#pragma unroll
        for (int ni = 0; ni < 2; ni++)
#pragma unroll
            for (int t = 0; t < 4; t++) {
                acc[mi][ni][t] = 0.f; cmp[mi][ni][t] = 0.f; tmp[mi][ni][t] = 0.f;
            }

    const int lr = lane & 15, lc = lane >> 4;

    stage_load(0);
    for (int t = 0; t < nt; t++) {
        if (t + 1 < nt) { stage_load(t + 1); CP_WAIT1(); }
        else CP_WAIT0();
        __syncthreads();
        const uint32_t st = (uint32_t)(t & 1) * 24576u;
#pragma unroll
        for (int kh = 0; kh < 2; kh++) {
            const int kc = kh * 2 + lc;
            uint32_t a1[4][4], a2[4][4];
#pragma unroll
            for (int mi = 0; mi < 4; mi++) {
                const int r = wm * 64 + mi * 16 + lr;
                const uint32_t o = st + swz(r, kc);
                ldsm4(a1[mi][0], a1[mi][1], a1[mi][2], a1[mi][3], sb + o);
                ldsm4(a2[mi][0], a2[mi][1], a2[mi][2], a2[mi][3], sb + o + 8192);
            }
            uint32_t b1[2][2], b2[2][2];
            {
                const int r = wn * 16 + lr;
                const uint32_t o = st + swz(r, kc);
                uint32_t r0, r1, r2, r3;
                ldsm4(r0, r1, r2, r3, sb + o + 16384);
                b1[0][0] = r0; b1[1][0] = r1; b1[0][1] = r2; b1[1][1] = r3;
                ldsm4(r0, r1, r2, r3, sb + o + 20480);
                b2[0][0] = r0; b2[1][0] = r1; b2[0][1] = r2; b2[1][1] = r3;
            }
#pragma unroll
            for (int mi = 0; mi < 4; mi++)
#pragma unroll
                for (int ni = 0; ni < 2; ni++) {
                    mma16816(tmp[mi][ni], a1[mi], b1[ni]);
                    mma16816(tmp[mi][ni], a1[mi], b2[ni]);
                    mma16816(tmp[mi][ni], a2[mi], b1[ni]);
                    mma16816(tmp[mi][ni], a2[mi], b2[ni]);
                }
        }
        if ((t & 1) || (t == nt - 1)) {
#pragma unroll
            for (int mi = 0; mi < 4; mi++)
#pragma unroll
                for (int ni = 0; ni < 2; ni++)
#pragma unroll
                    for (int q = 0; q < 4; q++) {
                        float y = __fsub_rn(tmp[mi][ni][q], cmp[mi][ni][q]);
                        float t2 = __fadd_rn(acc[mi][ni][q], y);
                        cmp[mi][ni][q] = __fsub_rn(__fsub_rn(t2, acc[mi][ni][q]), y);
                        acc[mi][ni][q] = t2;
                        tmp[mi][ni][q] = 0.f;
                    }
        }
        __syncthreads();
    }
#pragma unroll
    for (int mi = 0; mi < 4; mi++) {
        const int r = row0 + wm * 64 + mi * 16 + (lane >> 2);
#pragma unroll
        for (int ni = 0; ni < 2; ni++) {
            const int cc = n0 + wn * 16 + ni * 8 + ((lane & 3) << 1);
            if (bias) {
                const float b0 = bias[cc], b1v = bias[cc + 1];
                C[(size_t)r * ldc + cc]           = __fadd_rn(acc[mi][ni][0], b0);
                C[(size_t)r * ldc + cc + 1]       = __fadd_rn(acc[mi][ni][1], b1v);
                C[(size_t)(r + 8) * ldc + cc]     = __fadd_rn(acc[mi][ni][2], b0);
                C[(size_t)(r + 8) * ldc + cc + 1] = __fadd_rn(acc[mi][ni][3], b1v);
            } else {
                C[(size_t)r * ldc + cc]           = __fmul_rn(acc[mi][ni][0], scale);
                C[(size_t)r * ldc + cc + 1]       = __fmul_rn(acc[mi][ni][1], scale);
                C[(size_t)(r + 8) * ldc + cc]     = __fmul_rn(acc[mi][ni][2], scale);
                C[(size_t)(r + 8) * ldc + cc + 1] = __fmul_rn(acc[mi][ni][3], scale);
            }
        }
    }
}

// ------------------------------------------------------------------
// Smooth tensor GEMM fp16 3-pass, block 128x128.
// cp.async double-buffered (2 stages x 32 KB dynamic smem).
// Optional fp16 2-split outputs fused into epilogue.
// ------------------------------------------------------------------
__global__ void __launch_bounds__(256)
gemm_tc(const __half* __restrict__ Ah, const __half* __restrict__ Al,
        const __half* __restrict__ Bh, const __half* __restrict__ Bl,
        const float* __restrict__ bias, float* __restrict__ C,
        __half* __restrict__ Sh, __half* __restrict__ Sl)
{
    const uint32_t sb = smem_u32(dynsmem);
    const int tid = threadIdx.x;
    const int lane = tid & 31, wid = tid >> 5;
    const int wm = wid >> 2, wn = wid & 3;
    const int row0 = blockIdx.y << 7;
    const int n0 = blockIdx.x << 7;

    // stage layout (32768 B): AH 0 | AL 8192 | BH 16384 | BL 24576
    auto stage_load = [&](int t) {
        const int k0 = t << 5;
        const uint32_t st = (uint32_t)(t & 1) * 32768u;
#pragma unroll
        for (int i = 0; i < 2; i++) {
            const int idx = tid + (i << 8);
            const int row = idx >> 2, c = idx & 3;
            const uint32_t off = st + swz(row, c);
            const size_t ga = (size_t)(row0 + row) * HIDN + k0 + (c << 3);
            const size_t gb = (size_t)(n0 + row) * HIDN + k0 + (c << 3);
            cp16(sb + off, Ah + ga);
            cp16(sb + off + 8192, Al + ga);
            cp16(sb + off + 16384, Bh + gb);
            cp16(sb + off + 24576, Bl + gb);
        }
        CP_COMMIT();
    };

    float acc[4][4][4];
#pragma unroll
    for (int mi = 0; mi < 4; mi++)
#pragma unroll
        for (int ni = 0; ni < 4; ni++)
#pragma unroll
            for (int t = 0; t < 4; t++) acc[mi][ni][t] = 0.f;

    const int lr = lane & 15, lc = lane >> 4;
    const int nt = HIDN / 32;

    stage_load(0);
    for (int t = 0; t < nt; t++) {
        if (t + 1 < nt) { stage_load(t + 1); CP_WAIT1(); }
        else CP_WAIT0();
        __syncthreads();
        const uint32_t st = (uint32_t)(t & 1) * 32768u;
#pragma unroll
        for (int kh = 0; kh < 2; kh++) {
            const int kc = kh * 2 + lc;
            uint32_t a_h[4][4], a_l[4][4];
#pragma unroll
            for (int mi = 0; mi < 4; mi++) {
                const int r = wm * 64 + mi * 16 + lr;
                const uint32_t o = st + swz(r, kc);
                ldsm4(a_h[mi][0], a_h[mi][1], a_h[mi][2], a_h[mi][3], sb + o);
                ldsm4(a_l[mi][0], a_l[mi][1], a_l[mi][2], a_l[mi][3], sb + o + 8192);
            }
            uint32_t b_h[4][2], b_l[4][2];
#pragma unroll
            for (int np = 0; np < 2; np++) {
                const int r = wn * 32 + np * 16 + lr;
                const uint32_t o = st + swz(r, kc);
                uint32_t r0, r1, r2, r3;
                ldsm4(r0, r1, r2, r3, sb + o + 16384);
                b_h[np * 2][0] = r0; b_h[np * 2 + 1][0] = r1;
                b_h[np * 2][1] = r2; b_h[np * 2 + 1][1] = r3;
                ldsm4(r0, r1, r2, r3, sb + o + 24576);
                b_l[np * 2][0] = r0; b_l[np * 2 + 1][0] = r1;
                b_l[np * 2][1] = r2; b_l[np * 2 + 1][1] = r3;
            }
#pragma unroll
            for (int mi = 0; mi < 4; mi++)
#pragma unroll
                for (int ni = 0; ni < 4; ni++) {
                    mma16816(acc[mi][ni], a_h[mi], b_h[ni]);
                    mma16816(acc[mi][ni], a_h[mi], b_l[ni]);
                    mma16816(acc[mi][ni], a_l[mi], b_h[ni]);
                }
        }
        __syncthreads();
    }
#pragma unroll
    for (int mi = 0; mi < 4; mi++) {
        const int r = row0 + wm * 64 + mi * 16 + (lane >> 2);
#pragma unroll
        for (int ni = 0; ni < 4; ni++) {
            const int cc = n0 + wn * 32 + ni * 8 + ((lane & 3) << 1);
            const float b0 = bias[cc], b1 = bias[cc + 1];
            float v00 = __fadd_rn(acc[mi][ni][0], b0);
            float v01 = __fadd_rn(acc[mi][ni][1], b1);
            float v10 = __fadd_rn(acc[mi][ni][2], b0);
            float v11 = __fadd_rn(acc[mi][ni][3], b1);
            size_t o0 = (size_t)r * HIDN + cc;
            size_t o1 = (size_t)(r + 8) * HIDN + cc;
            C[o0] = v00; C[o0 + 1] = v01;
            C[o1] = v10; C[o1 + 1] = v11;
            if (Sh) {
                split2(v00, Sh[o0], Sl[o0]);
                split2(v01, Sh[o0 + 1], Sl[o0 + 1]);
                split2(v10, Sh[o1], Sl[o1]);
                split2(v11, Sh[o1 + 1], Sl[o1 + 1]);
            }
        }
    }
}

// ------------------------------------------------------------------
// Local QK^T: per (h, ch), scores[128 q][256 keys]. fp16 3-pass.
// ------------------------------------------------------------------
__global__ void __launch_bounds__(256)
gemm_tc_qk()
{
    __shared__ char smem[4 * 8192];
    const uint32_t sb = smem_u32(smem);
    const uint32_t SA_H = 0, SA_L = 8192, SB_H = 16384, SB_L = 24576;
    const int tid = threadIdx.x;
    const int lane = tid & 31, wid = tid >> 5;
    const int wm = wid >> 2, wn = wid & 3;
    const int z = blockIdx.y;
    const int h = z >> 5, ch = z & 31;
    const int n0 = blockIdx.x << 7;
    const int b_base = (ch << 7) - 128 + n0;
    const int colA = h * DH;

    float acc[4][4][4];
#pragma unroll
    for (int mi = 0; mi < 4; mi++)
#pragma unroll
        for (int ni = 0; ni < 4; ni++)
#pragma unroll
            for (int t = 0; t < 4; t++) acc[mi][ni][t] = 0.f;

    const int lr = lane & 15, lc = lane >> 4;

    for (int k0 = 0; k0 < DH; k0 += 32) {
#pragma unroll
        for (int i = 0; i < 2; i++) {
            const int idx = tid + (i << 8);
            const int row = idx >> 2, c = idx & 3;
            const uint32_t off = swz(row, c);
            const size_t ga = (size_t)((ch << 7) + row) * HIDN + colA + k0 + (c << 3);
            int br = b_base + row; if (br < 0) br = 0;
            const size_t gb = (size_t)br * HIDN + colA + k0 + (c << 3);
            *(uint4*)(smem + SA_H + off) = *(const uint4*)(g_qh + ga);
            *(uint4*)(smem + SA_L + off) = *(const uint4*)(g_ql + ga);
            *(uint4*)(smem + SB_H + off) = *(const uint4*)(g_lkh + gb);
            *(uint4*)(smem + SB_L + off) = *(const uint4*)(g_lkl + gb);
        }
        __syncthreads();
#pragma unroll
        for (int kh = 0; kh < 2; kh++) {
            const int kc = kh * 2 + lc;
            uint32_t a_h[4][4], a_l[4][4];
#pragma unroll
            for (int mi = 0; mi < 4; mi++) {
                const int r = wm * 64 + mi * 16 + lr;
                const uint32_t o = swz(r, kc);
                ldsm4(a_h[mi][0], a_h[mi][1], a_h[mi][2], a_h[mi][3], sb + SA_H + o);
                ldsm4(a_l[mi][0], a_l[mi][1], a_l[mi][2], a_l[mi][3], sb + SA_L + o);
            }
            uint32_t b_h[4][2], b_l[4][2];
#pragma unroll
            for (int np = 0; np < 2; np++) {
                const int r = wn * 32 + np * 16 + lr;
                const uint32_t o = swz(r, kc);
                uint32_t r0, r1, r2, r3;
                ldsm4(r0, r1, r2, r3, sb + SB_H + o);
                b_h[np * 2][0] = r0; b_h[np * 2 + 1][0] = r1;
                b_h[np * 2][1] = r2; b_h[np * 2 + 1][1] = r3;
                ldsm4(r0, r1, r2, r3, sb + SB_L + o);
                b_l[np * 2][0] = r0; b_l[np * 2 + 1][0] = r1;
                b_l[np * 2][1] = r2; b_l[np * 2 + 1][1] = r3;
            }
#pragma unroll
            for (int mi = 0; mi < 4; mi++)
#pragma unroll
                for (int ni = 0; ni < 4; ni++) {
                    mma16816(acc[mi][ni], a_h[mi], b_h[ni]);
                    mma16816(acc[mi][ni], a_h[mi], b_l[ni]);
                    mma16816(acc[mi][ni], a_l[mi], b_h[ni]);
                }
        }
        __syncthreads();
    }
    float* C = g_scl + (size_t)z * 128 * 256;
#pragma unroll
    for (int mi = 0; mi < 4; mi++) {
        const int r = wm * 64 + mi * 16 + (lane >> 2);
#pragma unroll
        for (int ni = 0; ni < 4; ni++) {
            const int cc = n0 + wn * 32 + ni * 8 + ((lane & 3) << 1);
            C[(size_t)r * 256 + cc]           = __fmul_rn(acc[mi][ni][0], ATT_SCALE);
            C[(size_t)r * 256 + cc + 1]       = __fmul_rn(acc[mi][ni][1], ATT_SCALE);
            C[(size_t)(r + 8) * 256 + cc]     = __fmul_rn(acc[mi][ni][2], ATT_SCALE);
            C[(size_t)(r + 8) * 256 + cc + 1] = __fmul_rn(acc[mi][ni][3], ATT_SCALE);
        }
    }
}

// ------------------------------------------------------------------
// Local PV: ctx = P[128x256]@V[256x128]; merge + emit merged fp16 splits.
// ------------------------------------------------------------------
__global__ void __launch_bounds__(256)
gemm_tc_pv()
{
    __shared__ char smem[4 * 8192];
    const uint32_t sb = smem_u32(smem);
    const uint32_t SP_H = 0, SP_L = 8192, SV_H = 16384, SV_L = 24576;
    const int tid = threadIdx.x;
    const int lane = tid & 31, wid = tid >> 5;
    const int wm = wid >> 2, wn = wid & 3;
    const int z = blockIdx.x;
    const int h = z >> 5, ch = z & 31;
    const int vbase = (ch << 7) - 128;
    const int colV = h * DH;
    const __half* Ph = g_sph + (size_t)z * 128 * 256;
    const __half* Pl = g_spl + (size_t)z * 128 * 256;

    float acc[4][4][4];
#pragma unroll
    for (int mi = 0; mi < 4; mi++)
#pragma unroll
        for (int ni = 0; ni < 4; ni++)
#pragma unroll
            for (int t = 0; t < 4; t++) acc[mi][ni][t] = 0.f;

    const int lr = lane & 15, lc = lane >> 4;

    for (int k0 = 0; k0 < 256; k0 += 32) {
#pragma unroll
        for (int i = 0; i < 2; i++) {
            const int idx = tid + (i << 8);
            const int row = idx >> 2, c = idx & 3;
            const uint32_t off = swz(row, c);
            const size_t gp = (size_t)row * 256 + k0 + (c << 3);
            *(uint4*)(smem + SP_H + off) = *(const uint4*)(Ph + gp);
            *(uint4*)(smem + SP_L + off) = *(const uint4*)(Pl + gp);
        }
#pragma unroll
        for (int i = 0; i < 2; i++) {
            const int idx = tid + (i << 8);
            const int row = idx >> 4, c = idx & 15;
            const uint32_t off = vswz(row, c);
            int vr = vbase + k0 + row; if (vr < 0) vr = 0;
            const size_t gv = (size_t)vr * HIDN + colV + (c << 3);
            *(uint4*)(smem + SV_H + off) = *(const uint4*)(g_lvh + gv);
            *(uint4*)(smem + SV_L + off) = *(const uint4*)(g_lvl + gv);
        }
        __syncthreads();
#pragma unroll
        for (int kh = 0; kh < 2; kh++) {
            const int kc = kh * 2 + lc;
            uint32_t a_h[4][4], a_l[4][4];
#pragma unroll
            for (int mi = 0; mi < 4; mi++) {
                const int r = wm * 64 + mi * 16 + lr;
                const uint32_t o = swz(r, kc);
                ldsm4(a_h[mi][0], a_h[mi][1], a_h[mi][2], a_h[mi][3], sb + SP_H + o);
                ldsm4(a_l[mi][0], a_l[mi][1], a_l[mi][2], a_l[mi][3], sb + SP_L + o);
            }
            uint32_t b_h[4][2], b_l[4][2];
#pragma unroll
            for (int j = 0; j < 2; j++) {
                const int krow = kh * 16 + lr;
                const int dchunk = wn * 4 + j * 2 + lc;
                const uint32_t o = vswz(krow, dchunk);
                uint32_t r0, r1, r2, r3;
                ldsm4t(r0, r1, r2, r3, sb + SV_H + o);
                b_h[j * 2][0] = r0; b_h[j * 2][1] = r1;
                b_h[j * 2 + 1][0] = r2; b_h[j * 2 + 1][1] = r3;
                ldsm4t(r0, r1, r2, r3, sb + SV_L + o);
                b_l[j * 2][0] = r0; b_l[j * 2][1] = r1;
                b_l[j * 2 + 1][0] = r2; b_l[j * 2 + 1][1] = r3;
            }
#pragma unroll
            for (int mi = 0; mi < 4; mi++)
#pragma unroll
                for (int ni = 0; ni < 4; ni++) {
                    mma16816(acc[mi][ni], a_h[mi], b_h[ni]);
                    mma16816(acc[mi][ni], a_h[mi], b_l[ni]);
                    mma16816(acc[mi][ni], a_l[mi], b_h[ni]);
                }
        }
        __syncthreads();
    }
#pragma unroll
    for (int mi = 0; mi < 4; mi++) {
        const int r = (ch << 7) + wm * 64 + mi * 16 + (lane >> 2);
#pragma unroll
        for (int ni = 0; ni < 4; ni++) {
            const int cc = colV + wn * 32 + ni * 8 + ((lane & 3) << 1);
            size_t o0 = (size_t)r * HIDN + cc;
            size_t o1 = (size_t)(r + 8) * HIDN + cc;
            float m00 = __fmul_rn(__fadd_rn(g_merged[o0], acc[mi][ni][0]), 0.5f);
            float m01 = __fmul_rn(__fadd_rn(g_merged[o0 + 1], acc[mi][ni][1]), 0.5f);
            float m10 = __fmul_rn(__fadd_rn(g_merged[o1], acc[mi][ni][2]), 0.5f);
            float m11 = __fmul_rn(__fadd_rn(g_merged[o1 + 1], acc[mi][ni][3]), 0.5f);
            g_merged[o0] = m00; g_merged[o0 + 1] = m01;
            g_merged[o1] = m10; g_merged[o1 + 1] = m11;
            split2(m00, g_mrg_h[o0], g_mrg_l[o0]);
            split2(m01, g_mrg_h[o0 + 1], g_mrg_l[o0 + 1]);
            split2(m10, g_mrg_h[o1], g_mrg_l[o1]);
            split2(m11, g_mrg_h[o1 + 1], g_mrg_l[o1 + 1]);
        }
    }
}

// plain 2-split
__global__ void split2_plain(const float* __restrict__ src,
                             __half* __restrict__ h, __half* __restrict__ l, int n)
{
    int i = blockIdx.x * blockDim.x + threadIdx.x;
    if (i >= n) return;
    split2(src[i], h[i], l[i]);
}

// transpose + 2-split: W [K][N] -> T{h,l} [n][k]
__global__ void tsplit(const float* __restrict__ W,
                       __half* __restrict__ Th, __half* __restrict__ Tl)
{
    __shared__ float tile[32][33];
    const int n0 = blockIdx.x << 5, k0 = blockIdx.y << 5;
    const int tx = threadIdx.x & 31, ty = threadIdx.x >> 5;
#pragma unroll
    for (int i = 0; i < 32; i += 8)
        tile[ty + i][tx] = W[(size_t)(k0 + ty + i) * HIDN + n0 + tx];
    __syncthreads();
#pragma unroll
    for (int i = 0; i < 32; i += 8) {
        float x = tile[tx][ty + i];
        size_t o = (size_t)(n0 + ty + i) * HIDN + k0 + tx;
        split2(x, Th[o], Tl[o]);
    }
}

// ------------------------------------------------------------------
// entries GEMMs (Wk, Wv fused): tile 64x64, chunked-Kahan, 64 CTAs.
// ------------------------------------------------------------------
__global__ __launch_bounds__(256)
void entries_gemm64(const float* __restrict__ Wk, const float* __restrict__ bk,
                    const float* __restrict__ Wv, const float* __restrict__ bv)
{
    const float* W = blockIdx.z ? Wv : Wk;
    const float* bias = blockIdx.z ? bv : bk;
    float* C = blockIdx.z ? g_cv : g_ck;
    const int row0 = blockIdx.y << 6;
    const int col0 = blockIdx.x << 6;

    __shared__ float As[16][64];
    __shared__ float Bs[16][64];
    const int tid = threadIdx.x;
    const int ty = tid >> 4, tx = tid & 15;

    float acc[4][4], cmp[4][4];
#pragma unroll
    for (int i = 0; i < 4; i++)
#pragma unroll
        for (int j = 0; j < 4; j++) { acc[i][j] = 0.f; cmp[i][j] = 0.f; }

    for (int k0 = 0; k0 < HIDN; k0 += 16) {
        {
            int m = tid >> 2, k4 = (tid & 3) << 2;
            float4 v = *(const float4*)(g_entries + (size_t)(row0 + m) * HIDN + k0 + k4);
            As[k4 + 0][m] = v.x; As[k4 + 1][m] = v.y;
            As[k4 + 2][m] = v.z; As[k4 + 3][m] = v.w;
        }
        {
            int kk = tid >> 4, n4 = (tid & 15) << 2;
            *(float4*)&Bs[kk][n4] = *(const float4*)(W + (size_t)(k0 + kk) * DH + col0 + n4);
        }
        __syncthreads();
        float tmp[4][4];
#pragma unroll
        for (int i = 0; i < 4; i++)
#pragma unroll
            for (int j = 0; j < 4; j++) tmp[i][j] = 0.f;
#pragma unroll
        for (int kk = 0; kk < 16; kk++) {
            float ra[4], rb[4];
            *(float4*)&ra[0] = *(const float4*)&As[kk][ty << 2];
            *(float4*)&rb[0] = *(const float4*)&Bs[kk][tx << 2];
#pragma unroll
            for (int i = 0; i < 4; i++)
#pragma unroll
                for (int j = 0; j < 4; j++)
                    tmp[i][j] = __fmaf_rn(ra[i], rb[j], tmp[i][j]);
        }
#pragma unroll
        for (int i = 0; i < 4; i++)
#pragma unroll
            for (int j = 0; j < 4; j++) {
                float y = __fsub_rn(tmp[i][j], cmp[i][j]);
                float t2 = __fadd_rn(acc[i][j], y);
                cmp[i][j] = __fsub_rn(__fsub_rn(t2, acc[i][j]), y);
                acc[i][j] = t2;
            }
        __syncthreads();
    }
#pragma unroll
    for (int i = 0; i < 4; i++) {
        size_t r = row0 + (ty << 2) + i;
#pragma unroll
        for (int j = 0; j < 4; j++) {
            int c = col0 + (tx << 2) + j;
            C[r * DH + c] = __fadd_rn(acc[i][j], bias[c]);
        }
    }
}

// ------------------------------------------------------------------
// rmsnorm + rope with fused fp16 2-split emission.
// ------------------------------------------------------------------
__global__ void norm_rope(int mode, const float* __restrict__ w,
                          __half* __restrict__ s1, __half* __restrict__ s2)
{
    int gw = (blockIdx.x * blockDim.x + threadIdx.x) >> 5;
    int lane = threadIdx.x & 31;
    float* buf; int rows, heads, rstride, pmul, padd;
    if (mode == 0)      { buf = g_q;  rows = SQ; heads = NHEAD; rstride = HIDN; pmul = 1; padd = 0; }
    else if (mode == 1) { buf = g_lk; rows = SQ; heads = NHEAD; rstride = HIDN; pmul = 1; padd = 0; }
    else                { buf = g_ck; rows = CB; heads = 1;     rstride = DH;   pmul = 4; padd = 3; }
    if (gw >= rows * heads) return;
    int row = gw / heads, h = gw - row * heads;
    size_t base = (size_t)row * rstride + h * DH;
    float* p = buf + base;
    float x0 = p[lane], x1 = p[lane + 32], x2 = p[lane + 64], x3 = p[lane + 96];
    float ss = warp_sum(x0 * x0 + x1 * x1 + x2 * x2 + x3 * x3);
    float mean = __fadd_rn(__fmul_rn(ss, 0.0078125f), 1e-6f);
    float rs = __fdiv_rn(1.0f, __fsqrt_rn(mean));
    x0 = __fmul_rn(__fmul_rn(x0, rs), w[lane]);
    x1 = __fmul_rn(__fmul_rn(x1, rs), w[lane + 32]);
    x2 = __fmul_rn(__fmul_rn(x2, rs), w[lane + 64]);
    x3 = __fmul_rn(__fmul_rn(x3, rs), w[lane + 96]);
    float pf = (float)pow(10000.0, (double)lane * (1.0 / 32.0));
    float invf = __fdiv_rn(1.0f, pf);
    float ang = __fmul_rn((float)(row * pmul + padd), invf);
    float c = (float)cos((double)ang);
    float s = (float)sin((double)ang);
    float n0 = __fsub_rn(__fmul_rn(x0, c), __fmul_rn(x1, s));
    float n1 = __fadd_rn(__fmul_rn(x0, s), __fmul_rn(x1, c));
    p[lane] = n0; p[lane + 32] = n1; p[lane + 64] = x2; p[lane + 96] = x3;
    if (s1) {
        float vals[4] = {n0, n1, x2, x3};
        int offs[4] = {lane, lane + 32, lane + 64, lane + 96};
#pragma unroll
        for (int i = 0; i < 4; i++) {
            size_t o = base + offs[i];
            split2(vals[i], s1[o], s2[o]);
        }
    }
}

__global__ void cmp_logits(const float* __restrict__ hidden, const float* __restrict__ Wc,
                           const float* __restrict__ bc)
{
    int gw = (blockIdx.x * blockDim.x + threadIdx.x) >> 5;
    int lane = threadIdx.x & 31;
    if (gw >= SQ) return;
    const float* hr = hidden + (size_t)gw * HIDN;
    float acc = 0.f, cmp = 0.f;
    for (int k = lane; k < HIDN; k += 32) {
        float y = __fmaf_rn(hr[k], Wc[k], -cmp);
        float t = __fadd_rn(acc, y);
        cmp = __fsub_rn(__fsub_rn(t, acc), y);
        acc = t;
    }
    acc = warp_sum(acc);
    if (lane == 0) g_wlog[gw] = __fadd_rn(acc, bc[0]);
}

__global__ void entries_kernel(const float* __restrict__ hidden)
{
    int c = blockIdx.x;
    float w0 = g_wlog[c * 4 + 0], w1 = g_wlog[c * 4 + 1];
    float w2 = g_wlog[c * 4 + 2], w3 = g_wlog[c * 4 + 3];
    float m = fmaxf(fmaxf(w0, w1), fmaxf(w2, w3));
    float e0 = (float)exp((double)__fsub_rn(w0, m));
    float e1 = (float)exp((double)__fsub_rn(w1, m));
    float e2 = (float)exp((double)__fsub_rn(w2, m));
    float e3 = (float)exp((double)__fsub_rn(w3, m));
    float sum = __fadd_rn(__fadd_rn(e0, e1), __fadd_rn(e2, e3));
    e0 = __fdiv_rn(e0, sum); e1 = __fdiv_rn(e1, sum);
    e2 = __fdiv_rn(e2, sum); e3 = __fdiv_rn(e3, sum);
    const float* h0 = hidden + (size_t)c * 4 * HIDN;
    float* dst = g_entries + (size_t)c * HIDN;
    for (int j = threadIdx.x; j < HIDN; j += blockDim.x)
        dst[j] = e0 * h0[j] + e1 * h0[HIDN + j] + e2 * h0[2 * HIDN + j] + e3 * h0[3 * HIDN + j];
}

// ------------------------------------------------------------------
// top-8 over causal prefix + softmax + gather cv; writes 1.0*ctx_sparse
// ------------------------------------------------------------------
__global__ void topk_sparse()
{
    int gw = (blockIdx.x * blockDim.x + threadIdx.x) >> 5;
    int lane = threadIdx.x & 31;
    if (gw >= NHEAD * SQ) return;
    int h = gw >> 12;
    int s = gw & (SQ - 1);
    int nc = (s + 1) >> 2;
    const float* row = g_sc + ((size_t)h * SQ + s) * CB;

    float bv[8]; int bi[8];
#pragma unroll
    for (int i = 0; i < 8; i++) { bv[i] = NEGV; bi[i] = -1; }
    for (int c = lane; c < nc; c += 32) {
        float v = row[c];
        if (v > bv[7]) {
            bv[7] = v; bi[7] = c;
#pragma unroll
            for (int j = 7; j > 0; j--) {
                if (bv[j] > bv[j - 1]) {
                    float tv = bv[j]; bv[j] = bv[j - 1]; bv[j - 1] = tv;
                    int txx = bi[j]; bi[j] = bi[j - 1]; bi[j - 1] = txx;
                }
            }
        }
    }
    int ptr = 0;
    float tvv[8]; int tii[8];
#pragma unroll
    for (int t = 0; t < 8; t++) {
        float m = (ptr < 8) ? bv[ptr] : NEGV;
        int mi = (ptr < 8) ? bi[ptr] : 0x7fffffff;
#pragma unroll
        for (int o = 16; o; o >>= 1) {
            float om = __shfl_xor_sync(0xffffffffu, m, o);
            int oi = __shfl_xor_sync(0xffffffffu, mi, o);
            if (om > m || (om == m && oi < mi)) { m = om; mi = oi; }
        }
        tvv[t] = m; tii[t] = mi;
        if (ptr < 8 && bv[ptr] == m && bi[ptr] == mi) ptr++;
    }
    float m0 = tvv[0];
    float e[8]; float sum = 0.f;
#pragma unroll
    for (int t = 0; t < 8; t++) {
        e[t] = (tvv[t] > NEGH) ? (float)exp((double)__fsub_rn(tvv[t], m0)) : 0.f;
        sum += e[t];
    }
    float den = fmaxf(sum, 1e-9f);
    float c0 = 0.f, c1 = 0.f, c2 = 0.f, c3 = 0.f;
#pragma unroll
    for (int t = 0; t < 8; t++) {
        float wgt = __fdiv_rn(e[t], den);
        if (wgt > 0.f) {
            const float* vr = g_cv + (size_t)tii[t] * DH;
            c0 += wgt * vr[lane];      c1 += wgt * vr[lane + 32];
            c2 += wgt * vr[lane + 64]; c3 += wgt * vr[lane + 96];
        }
    }
    float* dst = g_merged + (size_t)s * HIDN + h * DH;
    dst[lane] = c0;      dst[lane + 32] = c1;
    dst[lane + 64] = c2; dst[lane + 96] = c3;
}

// masked softmax over 256 local keys; writes fp16 split probs
__global__ void local_softmax()
{
    int gw = (blockIdx.x * blockDim.x + threadIdx.x) >> 5;
    int lane = threadIdx.x & 31;
    if (gw >= NHEAD * 32 * 128) return;
    int qi = gw & 127;
    int ch = (gw >> 7) & 31;
    const float* rowp = g_scl + (size_t)gw * 256;
    __half* oh = g_sph + (size_t)gw * 256;
    __half* ol = g_spl + (size_t)gw * 256;
    int lo = (ch == 0) ? 128 : qi;
    int hi = qi + 128;
    float v[8];
    float m = NEGV;
#pragma unroll
    for (int t = 0; t < 8; t++) {
        int j = lane + (t << 5);
        bool ok = (j >= lo) && (j <= hi);
        v[t] = ok ? rowp[j] : NEGV;
        m = fmaxf(m, v[t]);
    }
    m = warp_max(m);
    float e[8]; float sum = 0.f;
#pragma unroll
    for (int t = 0; t < 8; t++) {
        int j = lane + (t << 5);
        bool ok = (j >= lo) && (j <= hi);
        e[t] = ok ? (float)exp((double)__fsub_rn(v[t], m)) : 0.f;
        sum += e[t];
    }
    sum = warp_sum(sum);
#pragma unroll
    for (int t = 0; t < 8; t++) {
        float p = __fdiv_rn(e[t], sum);
        split2(p, oh[lane + (t << 5)], ol[lane + (t << 5)]);
    }
}

// ------------------------------------------------------------------
extern "C" void kernel_launch(void* const* d_in, const int* in_sizes, int n_in,
                              void* d_out, int out_size)
{
    const float* hidden = (const float*)d_in[0];
    const float* Wq   = (const float*)d_in[1];
    const float* bq   = (const float*)d_in[2];
    const float* Wcmp = (const float*)d_in[3];
    const float* bcmp = (const float*)d_in[4];
    const float* Wk   = (const float*)d_in[5];
    const float* bk   = (const float*)d_in[6];
    const float* Wv   = (const float*)d_in[7];
    const float* bvv  = (const float*)d_in[8];
    const float* Wlk  = (const float*)d_in[9];
    const float* blkb = (const float*)d_in[10];
    const float* Wlv  = (const float*)d_in[11];
    const float* blvb = (const float*)d_in[12];
    const float* qnw  = (const float*)d_in[13];
    const float* knw  = (const float*)d_in[14];
    const float* Wo   = (const float*)d_in[15];
    const float* bo   = (const float*)d_in[16];
    float* out = (float*)d_out;

    static __half *hid_h = nullptr, *hid_l, *mrg_h, *mrg_l,
                  *wlk_h, *wlk_l, *wlv_h, *wlv_l, *wo_h, *wo_l,
                  *qh, *ql, *lkh, *lkl, *lvh, *lvl,
                  *wq1, *wq2, *ck1, *ck2;
    static float *p_q = nullptr, *p_lk, *p_lv, *p_merged, *p_ck, *p_sc;
    static bool attr_done = false;
    if (!attr_done) {
        cudaFuncSetAttribute(gemm_tc, cudaFuncAttributeMaxDynamicSharedMemorySize, 65536);
        cudaFuncSetAttribute(gemm_tc4k, cudaFuncAttributeMaxDynamicSharedMemorySize, 49152);
        attr_done = true;
    }
    if (!hid_h) {
        cudaGetSymbolAddress((void**)&hid_h, g_hid_h);
        cudaGetSymbolAddress((void**)&hid_l, g_hid_l);
        cudaGetSymbolAddress((void**)&mrg_h, g_mrg_h);
        cudaGetSymbolAddress((void**)&mrg_l, g_mrg_l);
        cudaGetSymbolAddress((void**)&wlk_h, g_wlk_h);
        cudaGetSymbolAddress((void**)&wlk_l, g_wlk_l);
        cudaGetSymbolAddress((void**)&wlv_h, g_wlv_h);
        cudaGetSymbolAddress((void**)&wlv_l, g_wlv_l);
        cudaGetSymbolAddress((void**)&wo_h, g_wo_h);
        cudaGetSymbolAddress((void**)&wo_l, g_wo_l);
        cudaGetSymbolAddress((void**)&qh, g_qh);
        cudaGetSymbolAddress((void**)&ql, g_ql);
        cudaGetSymbolAddress((void**)&lkh, g_lkh);
        cudaGetSymbolAddress((void**)&lkl, g_lkl);
        cudaGetSymbolAddress((void**)&lvh, g_lvh);
        cudaGetSymbolAddress((void**)&lvl, g_lvl);
        cudaGetSymbolAddress((void**)&wq1, g_wq1);
        cudaGetSymbolAddress((void**)&wq2, g_wq2);
        cudaGetSymbolAddress((void**)&ck1, g_ck1);
        cudaGetSymbolAddress((void**)&ck2, g_ck2);
        cudaGetSymbolAddress((void**)&p_q, g_q);
        cudaGetSymbolAddress((void**)&p_lk, g_lk);
        cudaGetSymbolAddress((void**)&p_lv, g_lv);
        cudaGetSymbolAddress((void**)&p_merged, g_merged);
        cudaGetSymbolAddress((void**)&p_ck, g_ck);
        cudaGetSymbolAddress((void**)&p_sc, g_sc);
    }

    const int NELT = SQ * HIDN;

    // splits of inputs/weights (all fp16 2-split)
    split2_plain<<<(NELT + 255) / 256, 256>>>(hidden, hid_h, hid_l, NELT);
    tsplit<<<dim3(64, 64), 256>>>(Wq,  wq1,  wq2);
    tsplit<<<dim3(64, 64), 256>>>(Wlk, wlk_h, wlk_l);
    tsplit<<<dim3(64, 64), 256>>>(Wlv, wlv_h, wlv_l);
    tsplit<<<dim3(64, 64), 256>>>(Wo,  wo_h,  wo_l);

    // Wq: fp16 2-split 4-pass TC + Kahan fold (selection-grade), cp.async pipelined
    gemm_tc4k<<<dim3(HIDN / 64, SQ / 128, 1), 256, 49152>>>(
        hid_h, hid_l, wq1, wq2, bq, p_q,
        HIDN, HIDN, HIDN, HIDN, 0, 0, 1.0f, 0);

    // smooth projections (fp16 3-pass, cp.async pipelined); lv emits splits fused
    gemm_tc<<<dim3(HIDN / 128, SQ / 128), 256, 65536>>>(hid_h, hid_l, wlk_h, wlk_l,
                                                        blkb, p_lk, nullptr, nullptr);
    gemm_tc<<<dim3(HIDN / 128, SQ / 128), 256, 65536>>>(hid_h, hid_l, wlv_h, wlv_l,
                                                        blvb, p_lv, lvh, lvl);

    cmp_logits<<<SQ / 8, 256>>>(hidden, Wcmp, bcmp);
    entries_kernel<<<CB, 256>>>(hidden);

    // entries GEMMs: fused Wk+Wv, 64x64 tiles, 64 CTAs
    entries_gemm64<<<dim3(2, 16, 2), 256>>>(Wk, bk, Wv, bvv);

    // norm+rope with fused split emission
    norm_rope<<<(SQ * NHEAD) / 8, 256>>>(0, qnw, qh, ql);
    norm_rope<<<(SQ * NHEAD) / 8, 256>>>(1, knw, lkh, lkl);
    norm_rope<<<CB / 8, 256>>>(2, knw, ck1, ck2);

    // compressed scores: fp16 4-pass TC + Kahan fold, causal tile skip
    gemm_tc4k<<<dim3(CB / 64, SQ / 128, NHEAD), 256, 49152>>>(
        qh, ql, ck1, ck2, nullptr, p_sc,
        HIDN, DH, CB, DH, (size_t)DH, (size_t)SQ * CB, ATT_SCALE, 1);

    topk_sparse<<<(NHEAD * SQ) / 8, 256>>>();

    // local attention on tensor cores
    gemm_tc_qk<<<dim3(2, NHEAD * 32), 256>>>();
    local_softmax<<<(NHEAD * 32 * 128) / 8, 256>>>();
    gemm_tc_pv<<<NHEAD * 32, 256>>>();   // merges + emits mrg splits

    // output projection on tensor cores
    gemm_tc<<<dim3(HIDN / 128, SQ / 128), 256, 65536>>>(mrg_h, mrg_l, wo_h, wo_l,
                                                        bo, out, nullptr, nullptr);
}

// round 15
// speedup vs baseline: 2.3262x; 1.0119x over previous
#include <cuda_runtime.h>
#include <cuda_fp16.h>
#include <math.h>
#include <stdint.h>

#define SQ 4096
#define HIDN 2048
#define NHEAD 16
#define DH 128
#define CB 1024
#define NEGV -1e30f
#define NEGH -5e29f
#define ATT_SCALE 0.08838834764831845f

// ------------- scratch (static __device__ globals; allocation-free) -------------
__device__ float g_q[(size_t)SQ * HIDN];
__device__ float g_lk[(size_t)SQ * HIDN];
__device__ float g_lv[(size_t)SQ * HIDN];
__device__ float g_wlog[SQ];
__device__ float g_entries[(size_t)CB * HIDN];
__device__ float g_ck[CB * DH];
__device__ float g_cv[CB * DH];
__device__ float g_merged[(size_t)SQ * HIDN];
__device__ float g_sc[(size_t)NHEAD * SQ * CB];
__device__ float g_scl[(size_t)NHEAD * 32 * 128 * 256];

// fp16 2-split buffers
__device__ __half g_hid_h[(size_t)SQ * HIDN];
__device__ __half g_hid_l[(size_t)SQ * HIDN];
__device__ __half g_mrg_h[(size_t)SQ * HIDN];
__device__ __half g_mrg_l[(size_t)SQ * HIDN];
__device__ __half g_qh[(size_t)SQ * HIDN];
__device__ __half g_ql[(size_t)SQ * HIDN];
__device__ __half g_lkh[(size_t)SQ * HIDN];
__device__ __half g_lkl[(size_t)SQ * HIDN];
__device__ __half g_lvh[(size_t)SQ * HIDN];
__device__ __half g_lvl[(size_t)SQ * HIDN];
__device__ __half g_ck1[CB * DH];
__device__ __half g_ck2[CB * DH];
__device__ __half g_sph[(size_t)NHEAD * 32 * 128 * 256];
__device__ __half g_spl[(size_t)NHEAD * 32 * 128 * 256];
__device__ __half g_wq1[(size_t)HIDN * HIDN];
__device__ __half g_wq2[(size_t)HIDN * HIDN];
__device__ __half g_wlk_h[(size_t)HIDN * HIDN];
__device__ __half g_wlk_l[(size_t)HIDN * HIDN];
__device__ __half g_wlv_h[(size_t)HIDN * HIDN];
__device__ __half g_wlv_l[(size_t)HIDN * HIDN];
__device__ __half g_wo_h[(size_t)HIDN * HIDN];
__device__ __half g_wo_l[(size_t)HIDN * HIDN];

__device__ __forceinline__ float warp_sum(float v) {
#pragma unroll
    for (int o = 16; o; o >>= 1) v += __shfl_xor_sync(0xffffffffu, v, o);
    return v;
}
__device__ __forceinline__ float warp_max(float v) {
#pragma unroll
    for (int o = 16; o; o >>= 1) v = fmaxf(v, __shfl_xor_sync(0xffffffffu, v, o));
    return v;
}

// ======================= mma.sync helpers (base PTX, sm_80+) =======================
__device__ __forceinline__ uint32_t smem_u32(const void* p) {
    uint32_t a;
    asm("{ .reg .u64 t; cvta.to.shared.u64 t, %1; cvt.u32.u64 %0, t; }" : "=r"(a) : "l"(p));
    return a;
}
__device__ __forceinline__ void ldsm4(uint32_t& r0, uint32_t& r1, uint32_t& r2, uint32_t& r3,
                                      uint32_t addr) {
    asm volatile("ldmatrix.sync.aligned.m8n8.x4.shared.b16 {%0,%1,%2,%3}, [%4];"
                 : "=r"(r0), "=r"(r1), "=r"(r2), "=r"(r3) : "r"(addr));
}
__device__ __forceinline__ void ldsm4t(uint32_t& r0, uint32_t& r1, uint32_t& r2, uint32_t& r3,
                                       uint32_t addr) {
    asm volatile("ldmatrix.sync.aligned.m8n8.x4.trans.shared.b16 {%0,%1,%2,%3}, [%4];"
                 : "=r"(r0), "=r"(r1), "=r"(r2), "=r"(r3) : "r"(addr));
}
__device__ __forceinline__ void mma16816(float* d, const uint32_t* a, const uint32_t* b) {
    asm volatile(
        "mma.sync.aligned.m16n8k16.row.col.f32.f16.f16.f32 "
        "{%0,%1,%2,%3}, {%4,%5,%6,%7}, {%8,%9}, {%0,%1,%2,%3};"
        : "+f"(d[0]), "+f"(d[1]), "+f"(d[2]), "+f"(d[3])
        : "r"(a[0]), "r"(a[1]), "r"(a[2]), "r"(a[3]), "r"(b[0]), "r"(b[1]));
}
// cp.async (Ampere+ base PTX)
__device__ __forceinline__ void cp16(uint32_t dst, const void* src) {
    asm volatile("cp.async.cg.shared.global [%0], [%1], 16;" :: "r"(dst), "l"(src) : "memory");
}
#define CP_COMMIT() asm volatile("cp.async.commit_group;" ::: "memory")
#define CP_WAIT2() asm volatile("cp.async.wait_group 2;" ::: "memory")
#define CP_WAIT1() asm volatile("cp.async.wait_group 1;" ::: "memory")
#define CP_WAIT0() asm volatile("cp.async.wait_group 0;" ::: "memory")

__device__ __forceinline__ uint32_t swz(int row, int c) {
    int slot = (((row & 1) << 2) | c) ^ ((row >> 1) & 7);
    return (uint32_t)(((row >> 1) << 7) + (slot << 4));
}
__device__ __forceinline__ uint32_t vswz(int row, int c) {
    return (uint32_t)((row << 8) + ((c ^ (row & 7)) << 4));
}
// fp16 2-split: x = h + l + e, |e| <= 2^-22 |x|
__device__ __forceinline__ void split2(float x, __half& h, __half& l) {
    h = __float2half_rn(x);
    l = __float2half_rn(__fsub_rn(x, __half2float(h)));
}

extern __shared__ char dynsmem[];

// ------------------------------------------------------------------
// Selection-grade TC GEMM: fp16 2-split, 3 passes (hh,hl,lh; dropped
// ll ~2^-22) + Kahan fold every 2 K-tiles (total noise ~5e-7).
// Block 128x64, 8 warps, K-step 32. cp.async 3-stage (3 x 24 KB).
// ------------------------------------------------------------------
__global__ void __launch_bounds__(256)
gemm_tc4k(const __half* __restrict__ A1, const __half* __restrict__ A2,
          const __half* __restrict__ B1, const __half* __restrict__ B2,
          const float* __restrict__ bias, float* __restrict__ C,
          int lda, int ldb, int ldc, int K,
          size_t a_zoff, size_t c_zoff, float scale, int causal)
{
    const int row0 = blockIdx.y << 7;
    const int n0 = blockIdx.x << 6;
    if (causal && n0 >= (row0 >> 2) + 32) return;
    A1 += blockIdx.z * a_zoff; A2 += blockIdx.z * a_zoff;
    C += blockIdx.z * c_zoff;

    const uint32_t sb = smem_u32(dynsmem);
    const int tid = threadIdx.x;
    const int lane = tid & 31, wid = tid >> 5;
    const int wm = wid >> 2, wn = wid & 3;
    const int nt = K >> 5;

    // stage layout (24576 B): A1 0 | A2 8192 | B1 16384 | B2 20480
    auto stage_load = [&](int t) {
        const int k0 = t << 5;
        const uint32_t st = (uint32_t)(t % 3) * 24576u;
#pragma unroll
        for (int i = 0; i < 2; i++) {
            const int idx = tid + (i << 8);
            const int row = idx >> 2, c = idx & 3;
            const uint32_t off = st + swz(row, c);
            const size_t ga = (size_t)(row0 + row) * lda + k0 + (c << 3);
            cp16(sb + off, A1 + ga);
            cp16(sb + off + 8192, A2 + ga);
        }
        {
            const int row = tid >> 2, c = tid & 3;
            const uint32_t off = st + swz(row, c);
            const size_t gb = (size_t)(n0 + row) * ldb + k0 + (c << 3);
            cp16(sb + off + 16384, B1 + gb);
            cp16(sb + off + 20480, B2 + gb);
        }
        CP_COMMIT();
    };

    float acc[4][2][4], cmp[4][2][4], tmp[4][2][4];
#pragma unroll
    for (int mi = 0; mi < 4; mi++)
#pragma unroll
        for (int ni = 0; ni < 2; ni++)
#pragma unroll
            for (int t = 0; t < 4; t++) {
                acc[mi][ni][t] = 0.f; cmp[mi][ni][t] = 0.f; tmp[mi][ni][t] = 0.f;
            }

    const int lr = lane & 15, lc = lane >> 4;

    stage_load(0);
    if (nt > 1) stage_load(1);
    for (int t = 0; t < nt; t++) {
        if (t + 2 < nt) { stage_load(t + 2); CP_WAIT2(); }
        else if (t + 1 < nt) CP_WAIT1();
        else CP_WAIT0();
        __syncthreads();
        const uint32_t st = (uint32_t)(t % 3) * 24576u;
#pragma unroll
        for (int kh = 0; kh < 2; kh++) {
            const int kc = kh * 2 + lc;
            uint32_t a1[4][4], a2[4][4];
#pragma unroll
            for (int mi = 0; mi < 4; mi++) {
                const int r = wm * 64 + mi * 16 + lr;
                const uint32_t o = st + swz(r, kc);
                ldsm4(a1[mi][0], a1[mi][1], a1[mi][2], a1[mi][3], sb + o);
                ldsm4(a2[mi][0], a2[mi][1], a2[mi][2], a2[mi][3], sb + o + 8192);
            }
            uint32_t b1[2][2], b2[2][2];
            {
                const int r = wn * 16 + lr;
                const uint32_t o = st + swz(r, kc);
                uint32_t r0, r1, r2, r3;
                ldsm4(r0, r1, r2, r3, sb + o + 16384);
                b1[0][0] = r0; b1[1][0] = r1; b1[0][1] = r2; b1[1][1] = r3;
                ldsm4(r0, r1, r2, r3, sb + o + 20480);
                b2[0][0] = r0; b2[1][0] = r1; b2[0][1] = r2; b2[1][1] = r3;
            }
#pragma unroll
            for (int mi = 0; mi < 4; mi++)
#pragma unroll
                for (int ni = 0; ni < 2; ni++) {
                    mma16816(tmp[mi][ni], a1[mi], b1[ni]);
                    mma16816(tmp[mi][ni], a1[mi], b2[ni]);
                    mma16816(tmp[mi][ni], a2[mi], b1[ni]);
                }
        }
        if ((t & 1) || (t == nt - 1)) {
#pragma unroll
            for (int mi = 0; mi < 4; mi++)
#pragma unroll
                for (int ni = 0; ni < 2; ni++)
#pragma unroll
                    for (int q = 0; q < 4; q++) {
                        float y = __fsub_rn(tmp[mi][ni][q], cmp[mi][ni][q]);
                        float t2 = __fadd_rn(acc[mi][ni][q], y);
                        cmp[mi][ni][q] = __fsub_rn(__fsub_rn(t2, acc[mi][ni][q]), y);
                        acc[mi][ni][q] = t2;
                        tmp[mi][ni][q] = 0.f;
                    }
        }
        __syncthreads();
    }
#pragma unroll
    for (int mi = 0; mi < 4; mi++) {
        const int r = row0 + wm * 64 + mi * 16 + (lane >> 2);
#pragma unroll
        for (int ni = 0; ni < 2; ni++) {
            const int cc = n0 + wn * 16 + ni * 8 + ((lane & 3) << 1);
            if (bias) {
                const float b0 = bias[cc], b1v = bias[cc + 1];
                C[(size_t)r * ldc + cc]           = __fadd_rn(acc[mi][ni][0], b0);
                C[(size_t)r * ldc + cc + 1]       = __fadd_rn(acc[mi][ni][1], b1v);
                C[(size_t)(r + 8) * ldc + cc]     = __fadd_rn(acc[mi][ni][2], b0);
                C[(size_t)(r + 8) * ldc + cc + 1] = __fadd_rn(acc[mi][ni][3], b1v);
            } else {
                C[(size_t)r * ldc + cc]           = __fmul_rn(acc[mi][ni][0], scale);
                C[(size_t)r * ldc + cc + 1]       = __fmul_rn(acc[mi][ni][1], scale);
                C[(size_t)(r + 8) * ldc + cc]     = __fmul_rn(acc[mi][ni][2], scale);
                C[(size_t)(r + 8) * ldc + cc + 1] = __fmul_rn(acc[mi][ni][3], scale);
            }
        }
    }
}

// ------------------------------------------------------------------
// Smooth tensor GEMM fp16 3-pass, block 128x128.
// cp.async 3-stage (3 x 32 KB dynamic smem).
// Optional fp16 2-split outputs fused into epilogue.
// ------------------------------------------------------------------
__global__ void __launch_bounds__(256)
gemm_tc(const __half* __restrict__ Ah, const __half* __restrict__ Al,
        const __half* __restrict__ Bh, const __half* __restrict__ Bl,
        const float* __restrict__ bias, float* __restrict__ C,
        __half* __restrict__ Sh, __half* __restrict__ Sl)
{
    const uint32_t sb = smem_u32(dynsmem);
    const int tid = threadIdx.x;
    const int lane = tid & 31, wid = tid >> 5;
    const int wm = wid >> 2, wn = wid & 3;
    const int row0 = blockIdx.y << 7;
    const int n0 = blockIdx.x << 7;

    // stage layout (32768 B): AH 0 | AL 8192 | BH 16384 | BL 24576
    auto stage_load = [&](int t) {
        const int k0 = t << 5;
        const uint32_t st = (uint32_t)(t % 3) * 32768u;
#pragma unroll
        for (int i = 0; i < 2; i++) {
            const int idx = tid + (i << 8);
            const int row = idx >> 2, c = idx & 3;
            const uint32_t off = st + swz(row, c);
            const size_t ga = (size_t)(row0 + row) * HIDN + k0 + (c << 3);
            const size_t gb = (size_t)(n0 + row) * HIDN + k0 + (c << 3);
            cp16(sb + off, Ah + ga);
            cp16(sb + off + 8192, Al + ga);
            cp16(sb + off + 16384, Bh + gb);
            cp16(sb + off + 24576, Bl + gb);
        }
        CP_COMMIT();
    };

    float acc[4][4][4];
#pragma unroll
    for (int mi = 0; mi < 4; mi++)
#pragma unroll
        for (int ni = 0; ni < 4; ni++)
#pragma unroll
            for (int t = 0; t < 4; t++) acc[mi][ni][t] = 0.f;

    const int lr = lane & 15, lc = lane >> 4;
    const int nt = HIDN / 32;

    stage_load(0);
    stage_load(1);
    for (int t = 0; t < nt; t++) {
        if (t + 2 < nt) { stage_load(t + 2); CP_WAIT2(); }
        else if (t + 1 < nt) CP_WAIT1();
        else CP_WAIT0();
        __syncthreads();
        const uint32_t st = (uint32_t)(t % 3) * 32768u;
#pragma unroll
        for (int kh = 0; kh < 2; kh++) {
            const int kc = kh * 2 + lc;
            uint32_t a_h[4][4], a_l[4][4];
#pragma unroll
            for (int mi = 0; mi < 4; mi++) {
                const int r = wm * 64 + mi * 16 + lr;
                const uint32_t o = st + swz(r, kc);
                ldsm4(a_h[mi][0], a_h[mi][1], a_h[mi][2], a_h[mi][3], sb + o);
                ldsm4(a_l[mi][0], a_l[mi][1], a_l[mi][2], a_l[mi][3], sb + o + 8192);
            }
            uint32_t b_h[4][2], b_l[4][2];
#pragma unroll
            for (int np = 0; np < 2; np++) {
                const int r = wn * 32 + np * 16 + lr;
                const uint32_t o = st + swz(r, kc);
                uint32_t r0, r1, r2, r3;
                ldsm4(r0, r1, r2, r3, sb + o + 16384);
                b_h[np * 2][0] = r0; b_h[np * 2 + 1][0] = r1;
                b_h[np * 2][1] = r2; b_h[np * 2 + 1][1] = r3;
                ldsm4(r0, r1, r2, r3, sb + o + 24576);
                b_l[np * 2][0] = r0; b_l[np * 2 + 1][0] = r1;
                b_l[np * 2][1] = r2; b_l[np * 2 + 1][1] = r3;
            }
#pragma unroll
            for (int mi = 0; mi < 4; mi++)
#pragma unroll
                for (int ni = 0; ni < 4; ni++) {
                    mma16816(acc[mi][ni], a_h[mi], b_h[ni]);
                    mma16816(acc[mi][ni], a_h[mi], b_l[ni]);
                    mma16816(acc[mi][ni], a_l[mi], b_h[ni]);
                }
        }
        __syncthreads();
    }
#pragma unroll
    for (int mi = 0; mi < 4; mi++) {
        const int r = row0 + wm * 64 + mi * 16 + (lane >> 2);
#pragma unroll
        for (int ni = 0; ni < 4; ni++) {
            const int cc = n0 + wn * 32 + ni * 8 + ((lane & 3) << 1);
            const float b0 = bias[cc], b1 = bias[cc + 1];
            float v00 = __fadd_rn(acc[mi][ni][0], b0);
            float v01 = __fadd_rn(acc[mi][ni][1], b1);
            float v10 = __fadd_rn(acc[mi][ni][2], b0);
            float v11 = __fadd_rn(acc[mi][ni][3], b1);
            size_t o0 = (size_t)r * HIDN + cc;
            size_t o1 = (size_t)(r + 8) * HIDN + cc;
            C[o0] = v00; C[o0 + 1] = v01;
            C[o1] = v10; C[o1 + 1] = v11;
            if (Sh) {
                split2(v00, Sh[o0], Sl[o0]);
                split2(v01, Sh[o0 + 1], Sl[o0 + 1]);
                split2(v10, Sh[o1], Sl[o1]);
                split2(v11, Sh[o1 + 1], Sl[o1 + 1]);
            }
        }
    }
}

// ------------------------------------------------------------------
// Local QK^T: per (h, ch), scores[128 q][256 keys]. fp16 3-pass.
// ------------------------------------------------------------------
__global__ void __launch_bounds__(256)
gemm_tc_qk()
{
    __shared__ char smem[4 * 8192];
    const uint32_t sb = smem_u32(smem);
    const uint32_t SA_H = 0, SA_L = 8192, SB_H = 16384, SB_L = 24576;
    const int tid = threadIdx.x;
    const int lane = tid & 31, wid = tid >> 5;
    const int wm = wid >> 2, wn = wid & 3;
    const int z = blockIdx.y;
    const int h = z >> 5, ch = z & 31;
    const int n0 = blockIdx.x << 7;
    const int b_base = (ch << 7) - 128 + n0;
    const int colA = h * DH;

    float acc[4][4][4];
#pragma unroll
    for (int mi = 0; mi < 4; mi++)
#pragma unroll
        for (int ni = 0; ni < 4; ni++)
#pragma unroll
            for (int t = 0; t < 4; t++) acc[mi][ni][t] = 0.f;

    const int lr = lane & 15, lc = lane >> 4;

    for (int k0 = 0; k0 < DH; k0 += 32) {
#pragma unroll
        for (int i = 0; i < 2; i++) {
            const int idx = tid + (i << 8);
            const int row = idx >> 2, c = idx & 3;
            const uint32_t off = swz(row, c);
            const size_t ga = (size_t)((ch << 7) + row) * HIDN + colA + k0 + (c << 3);
            int br = b_base + row; if (br < 0) br = 0;
            const size_t gb = (size_t)br * HIDN + colA + k0 + (c << 3);
            *(uint4*)(smem + SA_H + off) = *(const uint4*)(g_qh + ga);
            *(uint4*)(smem + SA_L + off) = *(const uint4*)(g_ql + ga);
            *(uint4*)(smem + SB_H + off) = *(const uint4*)(g_lkh + gb);
            *(uint4*)(smem + SB_L + off) = *(const uint4*)(g_lkl + gb);
        }
        __syncthreads();
#pragma unroll
        for (int kh = 0; kh < 2; kh++) {
            const int kc = kh * 2 + lc;
            uint32_t a_h[4][4], a_l[4][4];
#pragma unroll
            for (int mi = 0; mi < 4; mi++) {
                const int r = wm * 64 + mi * 16 + lr;
                const uint32_t o = swz(r, kc);
                ldsm4(a_h[mi][0], a_h[mi][1], a_h[mi][2], a_h[mi][3], sb + SA_H + o);
                ldsm4(a_l[mi][0], a_l[mi][1], a_l[mi][2], a_l[mi][3], sb + SA_L + o);
            }
            uint32_t b_h[4][2], b_l[4][2];
#pragma unroll
            for (int np = 0; np < 2; np++) {
                const int r = wn * 32 + np * 16 + lr;
                const uint32_t o = swz(r, kc);
                uint32_t r0, r1, r2, r3;
                ldsm4(r0, r1, r2, r3, sb + SB_H + o);
                b_h[np * 2][0] = r0; b_h[np * 2 + 1][0] = r1;
                b_h[np * 2][1] = r2; b_h[np * 2 + 1][1] = r3;
                ldsm4(r0, r1, r2, r3, sb + SB_L + o);
                b_l[np * 2][0] = r0; b_l[np * 2 + 1][0] = r1;
                b_l[np * 2][1] = r2; b_l[np * 2 + 1][1] = r3;
            }
#pragma unroll
            for (int mi = 0; mi < 4; mi++)
#pragma unroll
                for (int ni = 0; ni < 4; ni++) {
                    mma16816(acc[mi][ni], a_h[mi], b_h[ni]);
                    mma16816(acc[mi][ni], a_h[mi], b_l[ni]);
                    mma16816(acc[mi][ni], a_l[mi], b_h[ni]);
                }
        }
        __syncthreads();
    }
    float* C = g_scl + (size_t)z * 128 * 256;
#pragma unroll
    for (int mi = 0; mi < 4; mi++) {
        const int r = wm * 64 + mi * 16 + (lane >> 2);
#pragma unroll
        for (int ni = 0; ni < 4; ni++) {
            const int cc = n0 + wn * 32 + ni * 8 + ((lane & 3) << 1);
            C[(size_t)r * 256 + cc]           = __fmul_rn(acc[mi][ni][0], ATT_SCALE);
            C[(size_t)r * 256 + cc + 1]       = __fmul_rn(acc[mi][ni][1], ATT_SCALE);
            C[(size_t)(r + 8) * 256 + cc]     = __fmul_rn(acc[mi][ni][2], ATT_SCALE);
            C[(size_t)(r + 8) * 256 + cc + 1] = __fmul_rn(acc[mi][ni][3], ATT_SCALE);
        }
    }
}

// ------------------------------------------------------------------
// Local PV: ctx = P[128x256]@V[256x128]; merge + emit merged fp16 splits.
// ------------------------------------------------------------------
__global__ void __launch_bounds__(256)
gemm_tc_pv()
{
    __shared__ char smem[4 * 8192];
    const uint32_t sb = smem_u32(smem);
    const uint32_t SP_H = 0, SP_L = 8192, SV_H = 16384, SV_L = 24576;
    const int tid = threadIdx.x;
    const int lane = tid & 31, wid = tid >> 5;
    const int wm = wid >> 2, wn = wid & 3;
    const int z = blockIdx.x;
    const int h = z >> 5, ch = z & 31;
    const int vbase = (ch << 7) - 128;
    const int colV = h * DH;
    const __half* Ph = g_sph + (size_t)z * 128 * 256;
    const __half* Pl = g_spl + (size_t)z * 128 * 256;

    float acc[4][4][4];
#pragma unroll
    for (int mi = 0; mi < 4; mi++)
#pragma unroll
        for (int ni = 0; ni < 4; ni++)
#pragma unroll
            for (int t = 0; t < 4; t++) acc[mi][ni][t] = 0.f;

    const int lr = lane & 15, lc = lane >> 4;

    for (int k0 = 0; k0 < 256; k0 += 32) {
#pragma unroll
        for (int i = 0; i < 2; i++) {
            const int idx = tid + (i << 8);
            const int row = idx >> 2, c = idx & 3;
            const uint32_t off = swz(row, c);
            const size_t gp = (size_t)row * 256 + k0 + (c << 3);
            *(uint4*)(smem + SP_H + off) = *(const uint4*)(Ph + gp);
            *(uint4*)(smem + SP_L + off) = *(const uint4*)(Pl + gp);
        }
#pragma unroll
        for (int i = 0; i < 2; i++) {
            const int idx = tid + (i << 8);
            const int row = idx >> 4, c = idx & 15;
            const uint32_t off = vswz(row, c);
            int vr = vbase + k0 + row; if (vr < 0) vr = 0;
            const size_t gv = (size_t)vr * HIDN + colV + (c << 3);
            *(uint4*)(smem + SV_H + off) = *(const uint4*)(g_lvh + gv);
            *(uint4*)(smem + SV_L + off) = *(const uint4*)(g_lvl + gv);
        }
        __syncthreads();
#pragma unroll
        for (int kh = 0; kh < 2; kh++) {
            const int kc = kh * 2 + lc;
            uint32_t a_h[4][4], a_l[4][4];
#pragma unroll
            for (int mi = 0; mi < 4; mi++) {
                const int r = wm * 64 + mi * 16 + lr;
                const uint32_t o = swz(r, kc);
                ldsm4(a_h[mi][0], a_h[mi][1], a_h[mi][2], a_h[mi][3], sb + SP_H + o);
                ldsm4(a_l[mi][0], a_l[mi][1], a_l[mi][2], a_l[mi][3], sb + SP_L + o);
            }
            uint32_t b_h[4][2], b_l[4][2];
#pragma unroll
            for (int j = 0; j < 2; j++) {
                const int krow = kh * 16 + lr;
                const int dchunk = wn * 4 + j * 2 + lc;
                const uint32_t o = vswz(krow, dchunk);
                uint32_t r0, r1, r2, r3;
                ldsm4t(r0, r1, r2, r3, sb + SV_H + o);
                b_h[j * 2][0] = r0; b_h[j * 2][1] = r1;
                b_h[j * 2 + 1][0] = r2; b_h[j * 2 + 1][1] = r3;
                ldsm4t(r0, r1, r2, r3, sb + SV_L + o);
                b_l[j * 2][0] = r0; b_l[j * 2][1] = r1;
                b_l[j * 2 + 1][0] = r2; b_l[j * 2 + 1][1] = r3;
            }
#pragma unroll
            for (int mi = 0; mi < 4; mi++)
#pragma unroll
                for (int ni = 0; ni < 4; ni++) {
                    mma16816(acc[mi][ni], a_h[mi], b_h[ni]);
                    mma16816(acc[mi][ni], a_h[mi], b_l[ni]);
                    mma16816(acc[mi][ni], a_l[mi], b_h[ni]);
                }
        }
        __syncthreads();
    }
#pragma unroll
    for (int mi = 0; mi < 4; mi++) {
        const int r = (ch << 7) + wm * 64 + mi * 16 + (lane >> 2);
#pragma unroll
        for (int ni = 0; ni < 4; ni++) {
            const int cc = colV + wn * 32 + ni * 8 + ((lane & 3) << 1);
            size_t o0 = (size_t)r * HIDN + cc;
            size_t o1 = (size_t)(r + 8) * HIDN + cc;
            float m00 = __fmul_rn(__fadd_rn(g_merged[o0], acc[mi][ni][0]), 0.5f);
            float m01 = __fmul_rn(__fadd_rn(g_merged[o0 + 1], acc[mi][ni][1]), 0.5f);
            float m10 = __fmul_rn(__fadd_rn(g_merged[o1], acc[mi][ni][2]), 0.5f);
            float m11 = __fmul_rn(__fadd_rn(g_merged[o1 + 1], acc[mi][ni][3]), 0.5f);
            g_merged[o0] = m00; g_merged[o0 + 1] = m01;
            g_merged[o1] = m10; g_merged[o1 + 1] = m11;
            split2(m00, g_mrg_h[o0], g_mrg_l[o0]);
            split2(m01, g_mrg_h[o0 + 1], g_mrg_l[o0 + 1]);
            split2(m10, g_mrg_h[o1], g_mrg_l[o1]);
            split2(m11, g_mrg_h[o1 + 1], g_mrg_l[o1 + 1]);
        }
    }
}

// plain 2-split
__global__ void split2_plain(const float* __restrict__ src,
                             __half* __restrict__ h, __half* __restrict__ l, int n)
{
    int i = blockIdx.x * blockDim.x + threadIdx.x;
    if (i >= n) return;
    split2(src[i], h[i], l[i]);
}

// transpose + 2-split: W [K][N] -> T{h,l} [n][k]
__global__ void tsplit(const float* __restrict__ W,
                       __half* __restrict__ Th, __half* __restrict__ Tl)
{
    __shared__ float tile[32][33];
    const int n0 = blockIdx.x << 5, k0 = blockIdx.y << 5;
    const int tx = threadIdx.x & 31, ty = threadIdx.x >> 5;
#pragma unroll
    for (int i = 0; i < 32; i += 8)
        tile[ty + i][tx] = W[(size_t)(k0 + ty + i) * HIDN + n0 + tx];
    __syncthreads();
#pragma unroll
    for (int i = 0; i < 32; i += 8) {
        float x = tile[tx][ty + i];
        size_t o = (size_t)(n0 + ty + i) * HIDN + k0 + tx;
        split2(x, Th[o], Tl[o]);
    }
}

// ------------------------------------------------------------------
// entries GEMMs (Wk, Wv fused): tile 64x64, chunked-Kahan, 64 CTAs.
// ------------------------------------------------------------------
__global__ __launch_bounds__(256)
void entries_gemm64(const float* __restrict__ Wk, const float* __restrict__ bk,
                    const float* __restrict__ Wv, const float* __restrict__ bv)
{
    const float* W = blockIdx.z ? Wv : Wk;
    const float* bias = blockIdx.z ? bv : bk;
    float* C = blockIdx.z ? g_cv : g_ck;
    const int row0 = blockIdx.y << 6;
    const int col0 = blockIdx.x << 6;

    __shared__ float As[16][64];
    __shared__ float Bs[16][64];
    const int tid = threadIdx.x;
    const int ty = tid >> 4, tx = tid & 15;

    float acc[4][4], cmp[4][4];
#pragma unroll
    for (int i = 0; i < 4; i++)
#pragma unroll
        for (int j = 0; j < 4; j++) { acc[i][j] = 0.f; cmp[i][j] = 0.f; }

    for (int k0 = 0; k0 < HIDN; k0 += 16) {
        {
            int m = tid >> 2, k4 = (tid & 3) << 2;
            float4 v = *(const float4*)(g_entries + (size_t)(row0 + m) * HIDN + k0 + k4);
            As[k4 + 0][m] = v.x; As[k4 + 1][m] = v.y;
            As[k4 + 2][m] = v.z; As[k4 + 3][m] = v.w;
        }
        {
            int kk = tid >> 4, n4 = (tid & 15) << 2;
            *(float4*)&Bs[kk][n4] = *(const float4*)(W + (size_t)(k0 + kk) * DH + col0 + n4);
        }
        __syncthreads();
        float tmp[4][4];
#pragma unroll
        for (int i = 0; i < 4; i++)
#pragma unroll
            for (int j = 0; j < 4; j++) tmp[i][j] = 0.f;
#pragma unroll
        for (int kk = 0; kk < 16; kk++) {
            float ra[4], rb[4];
            *(float4*)&ra[0] = *(const float4*)&As[kk][ty << 2];
            *(float4*)&rb[0] = *(const float4*)&Bs[kk][tx << 2];
#pragma unroll
            for (int i = 0; i < 4; i++)
#pragma unroll
                for (int j = 0; j < 4; j++)
                    tmp[i][j] = __fmaf_rn(ra[i], rb[j], tmp[i][j]);
        }
#pragma unroll
        for (int i = 0; i < 4; i++)
#pragma unroll
            for (int j = 0; j < 4; j++) {
                float y = __fsub_rn(tmp[i][j], cmp[i][j]);
                float t2 = __fadd_rn(acc[i][j], y);
                cmp[i][j] = __fsub_rn(__fsub_rn(t2, acc[i][j]), y);
                acc[i][j] = t2;
            }
        __syncthreads();
    }
#pragma unroll
    for (int i = 0; i < 4; i++) {
        size_t r = row0 + (ty << 2) + i;
#pragma unroll
        for (int j = 0; j < 4; j++) {
            int c = col0 + (tx << 2) + j;
            C[r * DH + c] = __fadd_rn(acc[i][j], bias[c]);
        }
    }
}

// ------------------------------------------------------------------
// rmsnorm + rope with fused fp16 2-split emission.
// ------------------------------------------------------------------
__global__ void norm_rope(int mode, const float* __restrict__ w,
                          __half* __restrict__ s1, __half* __restrict__ s2)
{
    int gw = (blockIdx.x * blockDim.x + threadIdx.x) >> 5;
    int lane = threadIdx.x & 31;
    float* buf; int rows, heads, rstride, pmul, padd;
    if (mode == 0)      { buf = g_q;  rows = SQ; heads = NHEAD; rstride = HIDN; pmul = 1; padd = 0; }
    else if (mode == 1) { buf = g_lk; rows = SQ; heads = NHEAD; rstride = HIDN; pmul = 1; padd = 0; }
    else                { buf = g_ck; rows = CB; heads = 1;     rstride = DH;   pmul = 4; padd = 3; }
    if (gw >= rows * heads) return;
    int row = gw / heads, h = gw - row * heads;
    size_t base = (size_t)row * rstride + h * DH;
    float* p = buf + base;
    float x0 = p[lane], x1 = p[lane + 32], x2 = p[lane + 64], x3 = p[lane + 96];
    float ss = warp_sum(x0 * x0 + x1 * x1 + x2 * x2 + x3 * x3);
    float mean = __fadd_rn(__fmul_rn(ss, 0.0078125f), 1e-6f);
    float rs = __fdiv_rn(1.0f, __fsqrt_rn(mean));
    x0 = __fmul_rn(__fmul_rn(x0, rs), w[lane]);
    x1 = __fmul_rn(__fmul_rn(x1, rs), w[lane + 32]);
    x2 = __fmul_rn(__fmul_rn(x2, rs), w[lane + 64]);
    x3 = __fmul_rn(__fmul_rn(x3, rs), w[lane + 96]);
    float pf = (float)pow(10000.0, (double)lane * (1.0 / 32.0));
    float invf = __fdiv_rn(1.0f, pf);
    float ang = __fmul_rn((float)(row * pmul + padd), invf);
    float c = (float)cos((double)ang);
    float s = (float)sin((double)ang);
    float n0 = __fsub_rn(__fmul_rn(x0, c), __fmul_rn(x1, s));
    float n1 = __fadd_rn(__fmul_rn(x0, s), __fmul_rn(x1, c));
    p[lane] = n0; p[lane + 32] = n1; p[lane + 64] = x2; p[lane + 96] = x3;
    if (s1) {
        float vals[4] = {n0, n1, x2, x3};
        int offs[4] = {lane, lane + 32, lane + 64, lane + 96};
#pragma unroll
        for (int i = 0; i < 4; i++) {
            size_t o = base + offs[i];
            split2(vals[i], s1[o], s2[o]);
        }
    }
}

__global__ void cmp_logits(const float* __restrict__ hidden, const float* __restrict__ Wc,
                           const float* __restrict__ bc)
{
    int gw = (blockIdx.x * blockDim.x + threadIdx.x) >> 5;
    int lane = threadIdx.x & 31;
    if (gw >= SQ) return;
    const float* hr = hidden + (size_t)gw * HIDN;
    float acc = 0.f, cmp = 0.f;
    for (int k = lane; k < HIDN; k += 32) {
        float y = __fmaf_rn(hr[k], Wc[k], -cmp);
        float t = __fadd_rn(acc, y);
        cmp = __fsub_rn(__fsub_rn(t, acc), y);
        acc = t;
    }
    acc = warp_sum(acc);
    if (lane == 0) g_wlog[gw] = __fadd_rn(acc, bc[0]);
}

__global__ void entries_kernel(const float* __restrict__ hidden)
{
    int c = blockIdx.x;
    float w0 = g_wlog[c * 4 + 0], w1 = g_wlog[c * 4 + 1];
    float w2 = g_wlog[c * 4 + 2], w3 = g_wlog[c * 4 + 3];
    float m = fmaxf(fmaxf(w0, w1), fmaxf(w2, w3));
    float e0 = (float)exp((double)__fsub_rn(w0, m));
    float e1 = (float)exp((double)__fsub_rn(w1, m));
    float e2 = (float)exp((double)__fsub_rn(w2, m));
    float e3 = (float)exp((double)__fsub_rn(w3, m));
    float sum = __fadd_rn(__fadd_rn(e0, e1), __fadd_rn(e2, e3));
    e0 = __fdiv_rn(e0, sum); e1 = __fdiv_rn(e1, sum);
    e2 = __fdiv_rn(e2, sum); e3 = __fdiv_rn(e3, sum);
    const float* h0 = hidden + (size_t)c * 4 * HIDN;
    float* dst = g_entries + (size_t)c * HIDN;
    for (int j = threadIdx.x; j < HIDN; j += blockDim.x)
        dst[j] = e0 * h0[j] + e1 * h0[HIDN + j] + e2 * h0[2 * HIDN + j] + e3 * h0[3 * HIDN + j];
}

// ------------------------------------------------------------------
// top-8 over causal prefix + softmax + gather cv; writes 1.0*ctx_sparse
// ------------------------------------------------------------------
__global__ void topk_sparse()
{
    int gw = (blockIdx.x * blockDim.x + threadIdx.x) >> 5;
    int lane = threadIdx.x & 31;
    if (gw >= NHEAD * SQ) return;
    int h = gw >> 12;
    int s = gw & (SQ - 1);
    int nc = (s + 1) >> 2;
    const float* row = g_sc + ((size_t)h * SQ + s) * CB;

    float bv[8]; int bi[8];
#pragma unroll
    for (int i = 0; i < 8; i++) { bv[i] = NEGV; bi[i] = -1; }
    for (int c = lane; c < nc; c += 32) {
        float v = row[c];
        if (v > bv[7]) {
            bv[7] = v; bi[7] = c;
#pragma unroll
            for (int j = 7; j > 0; j--) {
                if (bv[j] > bv[j - 1]) {
                    float tv = bv[j]; bv[j] = bv[j - 1]; bv[j - 1] = tv;
                    int txx = bi[j]; bi[j] = bi[j - 1]; bi[j - 1] = txx;
                }
            }
        }
    }
    int ptr = 0;
    float tvv[8]; int tii[8];
#pragma unroll
    for (int t = 0; t < 8; t++) {
        float m = (ptr < 8) ? bv[ptr] : NEGV;
        int mi = (ptr < 8) ? bi[ptr] : 0x7fffffff;
#pragma unroll
        for (int o = 16; o; o >>= 1) {
            float om = __shfl_xor_sync(0xffffffffu, m, o);
            int oi = __shfl_xor_sync(0xffffffffu, mi, o);
            if (om > m || (om == m && oi < mi)) { m = om; mi = oi; }
        }
        tvv[t] = m; tii[t] = mi;
        if (ptr < 8 && bv[ptr] == m && bi[ptr] == mi) ptr++;
    }
    float m0 = tvv[0];
    float e[8]; float sum = 0.f;
#pragma unroll
    for (int t = 0; t < 8; t++) {
        e[t] = (tvv[t] > NEGH) ? (float)exp((double)__fsub_rn(tvv[t], m0)) : 0.f;
        sum += e[t];
    }
    float den = fmaxf(sum, 1e-9f);
    float c0 = 0.f, c1 = 0.f, c2 = 0.f, c3 = 0.f;
#pragma unroll
    for (int t = 0; t < 8; t++) {
        float wgt = __fdiv_rn(e[t], den);
        if (wgt > 0.f) {
            const float* vr = g_cv + (size_t)tii[t] * DH;
            c0 += wgt * vr[lane];      c1 += wgt * vr[lane + 32];
            c2 += wgt * vr[lane + 64]; c3 += wgt * vr[lane + 96];
        }
    }
    float* dst = g_merged + (size_t)s * HIDN + h * DH;
    dst[lane] = c0;      dst[lane + 32] = c1;
    dst[lane + 64] = c2; dst[lane + 96] = c3;
}

// masked softmax over 256 local keys; writes fp16 split probs
__global__ void local_softmax()
{
    int gw = (blockIdx.x * blockDim.x + threadIdx.x) >> 5;
    int lane = threadIdx.x & 31;
    if (gw >= NHEAD * 32 * 128) return;
    int qi = gw & 127;
    int ch = (gw >> 7) & 31;
    const float* rowp = g_scl + (size_t)gw * 256;
    __half* oh = g_sph + (size_t)gw * 256;
    __half* ol = g_spl + (size_t)gw * 256;
    int lo = (ch == 0) ? 128 : qi;
    int hi = qi + 128;
    float v[8];
    float m = NEGV;
#pragma unroll
    for (int t = 0; t < 8; t++) {
        int j = lane + (t << 5);
        bool ok = (j >= lo) && (j <= hi);
        v[t] = ok ? rowp[j] : NEGV;
        m = fmaxf(m, v[t]);
    }
    m = warp_max(m);
    float e[8]; float sum = 0.f;
#pragma unroll
    for (int t = 0; t < 8; t++) {
        int j = lane + (t << 5);
        bool ok = (j >= lo) && (j <= hi);
        e[t] = ok ? (float)exp((double)__fsub_rn(v[t], m)) : 0.f;
        sum += e[t];
    }
    sum = warp_sum(sum);
#pragma unroll
    for (int t = 0; t < 8; t++) {
        float p = __fdiv_rn(e[t], sum);
        split2(p, oh[lane + (t << 5)], ol[lane + (t << 5)]);
    }
}

// ------------------------------------------------------------------
extern "C" void kernel_launch(void* const* d_in, const int* in_sizes, int n_in,
                              void* d_out, int out_size)
{
    const float* hidden = (const float*)d_in[0];
    const float* Wq   = (const float*)d_in[1];
    const float* bq   = (const float*)d_in[2];
    const float* Wcmp = (const float*)d_in[3];
    const float* bcmp = (const float*)d_in[4];
    const float* Wk   = (const float*)d_in[5];
    const float* bk   = (const float*)d_in[6];
    const float* Wv   = (const float*)d_in[7];
    const float* bvv  = (const float*)d_in[8];
    const float* Wlk  = (const float*)d_in[9];
    const float* blkb = (const float*)d_in[10];
    const float* Wlv  = (const float*)d_in[11];
    const float* blvb = (const float*)d_in[12];
    const float* qnw  = (const float*)d_in[13];
    const float* knw  = (const float*)d_in[14];
    const float* Wo   = (const float*)d_in[15];
    const float* bo   = (const float*)d_in[16];
    float* out = (float*)d_out;

    static __half *hid_h = nullptr, *hid_l, *mrg_h, *mrg_l,
                  *wlk_h, *wlk_l, *wlv_h, *wlv_l, *wo_h, *wo_l,
                  *qh, *ql, *lkh, *lkl, *lvh, *lvl,
                  *wq1, *wq2, *ck1, *ck2;
    static float *p_q = nullptr, *p_lk, *p_lv, *p_merged, *p_ck, *p_sc;
    static bool attr_done = false;
    if (!attr_done) {
        cudaFuncSetAttribute(gemm_tc, cudaFuncAttributeMaxDynamicSharedMemorySize, 98304);
        cudaFuncSetAttribute(gemm_tc4k, cudaFuncAttributeMaxDynamicSharedMemorySize, 73728);
        attr_done = true;
    }
    if (!hid_h) {
        cudaGetSymbolAddress((void**)&hid_h, g_hid_h);
        cudaGetSymbolAddress((void**)&hid_l, g_hid_l);
        cudaGetSymbolAddress((void**)&mrg_h, g_mrg_h);
        cudaGetSymbolAddress((void**)&mrg_l, g_mrg_l);
        cudaGetSymbolAddress((void**)&wlk_h, g_wlk_h);
        cudaGetSymbolAddress((void**)&wlk_l, g_wlk_l);
        cudaGetSymbolAddress((void**)&wlv_h, g_wlv_h);
        cudaGetSymbolAddress((void**)&wlv_l, g_wlv_l);
        cudaGetSymbolAddress((void**)&wo_h, g_wo_h);
        cudaGetSymbolAddress((void**)&wo_l, g_wo_l);
        cudaGetSymbolAddress((void**)&qh, g_qh);
        cudaGetSymbolAddress((void**)&ql, g_ql);
        cudaGetSymbolAddress((void**)&lkh, g_lkh);
        cudaGetSymbolAddress((void**)&lkl, g_lkl);
        cudaGetSymbolAddress((void**)&lvh, g_lvh);
        cudaGetSymbolAddress((void**)&lvl, g_lvl);
        cudaGetSymbolAddress((void**)&wq1, g_wq1);
        cudaGetSymbolAddress((void**)&wq2, g_wq2);
        cudaGetSymbolAddress((void**)&ck1, g_ck1);
        cudaGetSymbolAddress((void**)&ck2, g_ck2);
        cudaGetSymbolAddress((void**)&p_q, g_q);
        cudaGetSymbolAddress((void**)&p_lk, g_lk);
        cudaGetSymbolAddress((void**)&p_lv, g_lv);
        cudaGetSymbolAddress((void**)&p_merged, g_merged);
        cudaGetSymbolAddress((void**)&p_ck, g_ck);
        cudaGetSymbolAddress((void**)&p_sc, g_sc);
    }

    const int NELT = SQ * HIDN;

    // splits of inputs/weights (all fp16 2-split)
    split2_plain<<<(NELT + 255) / 256, 256>>>(hidden, hid_h, hid_l, NELT);
    tsplit<<<dim3(64, 64), 256>>>(Wq,  wq1,  wq2);
    tsplit<<<dim3(64, 64), 256>>>(Wlk, wlk_h, wlk_l);
    tsplit<<<dim3(64, 64), 256>>>(Wlv, wlv_h, wlv_l);
    tsplit<<<dim3(64, 64), 256>>>(Wo,  wo_h,  wo_l);

    // Wq: fp16 3-pass TC + Kahan fold (selection-grade), 3-stage cp.async
    gemm_tc4k<<<dim3(HIDN / 64, SQ / 128, 1), 256, 73728>>>(
        hid_h, hid_l, wq1, wq2, bq, p_q,
        HIDN, HIDN, HIDN, HIDN, 0, 0, 1.0f, 0);

    // smooth projections (fp16 3-pass, 3-stage cp.async); lv emits splits fused
    gemm_tc<<<dim3(HIDN / 128, SQ / 128), 256, 98304>>>(hid_h, hid_l, wlk_h, wlk_l,
                                                        blkb, p_lk, nullptr, nullptr);
    gemm_tc<<<dim3(HIDN / 128, SQ / 128), 256, 98304>>>(hid_h, hid_l, wlv_h, wlv_l,
                                                        blvb, p_lv, lvh, lvl);

    cmp_logits<<<SQ / 8, 256>>>(hidden, Wcmp, bcmp);
    entries_kernel<<<CB, 256>>>(hidden);

    // entries GEMMs: fused Wk+Wv, 64x64 tiles, 64 CTAs
    entries_gemm64<<<dim3(2, 16, 2), 256>>>(Wk, bk, Wv, bvv);

    // norm+rope with fused split emission
    norm_rope<<<(SQ * NHEAD) / 8, 256>>>(0, qnw, qh, ql);
    norm_rope<<<(SQ * NHEAD) / 8, 256>>>(1, knw, lkh, lkl);
    norm_rope<<<CB / 8, 256>>>(2, knw, ck1, ck2);

    // compressed scores: fp16 3-pass TC + Kahan fold, causal tile skip
    gemm_tc4k<<<dim3(CB / 64, SQ / 128, NHEAD), 256, 73728>>>(
        qh, ql, ck1, ck2, nullptr, p_sc,
        HIDN, DH, CB, DH, (size_t)DH, (size_t)SQ * CB, ATT_SCALE, 1);

    topk_sparse<<<(NHEAD * SQ) / 8, 256>>>();

    // local attention on tensor cores
    gemm_tc_qk<<<dim3(2, NHEAD * 32), 256>>>();
    local_softmax<<<(NHEAD * 32 * 128) / 8, 256>>>();
    gemm_tc_pv<<<NHEAD * 32, 256>>>();   // merges + emits mrg splits

    // output projection on tensor cores
    gemm_tc<<<dim3(HIDN / 128, SQ / 128), 256, 98304>>>(mrg_h, mrg_l, wo_h, wo_l,
                                                        bo, out, nullptr, nullptr);
}